// round 3
// baseline (speedup 1.0000x reference)
#include <cuda_runtime.h>
#include <math.h>
#include <stdint.h>

#define NN 24000
#define EE 96000
#define BB 1200
#define NPG 20

// ---------------- device scratch (no allocations allowed) ----------------
__device__ float g_q1[NN*512];
__device__ float g_k1[NN*512];
__device__ float g_v1[NN*512];
__device__ float g_s1[NN*512];
__device__ float g_h1[NN*512];
__device__ float g_q2[NN*1024];
__device__ float g_k2[NN*1024];
__device__ float g_v2[NN*1024];
__device__ float g_s2[NN*1024];
__device__ float g_h2[NN*1024];
__device__ float g_concat[BB*1280];
__device__ int   g_deg[NN];
__device__ int   g_offs[NN+1];
__device__ int   g_cursor[NN];
__device__ int   g_eidx[EE];
// tf32-rounded operand scratch
__device__ float g_wq2t[512*1024];
__device__ float g_wk2t[512*1024];
__device__ float g_wv2t[512*1024];
__device__ float g_ws2t[512*1024];
__device__ float g_wfpt[2048*256];
__device__ float g_wfint[1280*1024];
__device__ float g_fpbt[BB*2048];

// ---------------- CSR build ----------------
__global__ void zero_deg_kernel() {
    int i = blockIdx.x*blockDim.x + threadIdx.x;
    if (i < NN) g_deg[i] = 0;
}

__global__ void hist_kernel(const int* __restrict__ dst) {
    int e = blockIdx.x*blockDim.x + threadIdx.x;
    if (e < EE) atomicAdd(&g_deg[dst[e]], 1);
}

__global__ void scan_kernel() {
    __shared__ int wsum[32];
    __shared__ int carry;
    int tid = threadIdx.x;
    int lane = tid & 31, wid = tid >> 5;
    if (tid == 0) carry = 0;
    __syncthreads();
    for (int base = 0; base < NN; base += 1024) {
        int i = base + tid;
        int v = (i < NN) ? g_deg[i] : 0;
        int x = v;
        #pragma unroll
        for (int o = 1; o < 32; o <<= 1) {
            int y = __shfl_up_sync(0xffffffffu, x, o);
            if (lane >= o) x += y;
        }
        if (lane == 31) wsum[wid] = x;
        __syncthreads();
        if (wid == 0) {
            int s = wsum[lane];
            #pragma unroll
            for (int o = 1; o < 32; o <<= 1) {
                int y = __shfl_up_sync(0xffffffffu, s, o);
                if (lane >= o) s += y;
            }
            wsum[lane] = s;
        }
        __syncthreads();
        int pre = (wid > 0 ? wsum[wid-1] : 0) + carry;
        int incl = x + pre;
        if (i < NN) { g_offs[i] = incl - v; g_cursor[i] = incl - v; }
        __syncthreads();
        if (tid == 1023) carry = incl;
        __syncthreads();
    }
    if (tid == 0) g_offs[NN] = carry;
}

__global__ void scatter_kernel(const int* __restrict__ dst) {
    int e = blockIdx.x*blockDim.x + threadIdx.x;
    if (e < EE) {
        int p = atomicAdd(&g_cursor[dst[e]], 1);
        g_eidx[p] = e;
    }
}

__global__ void sort_kernel() {
    int n = blockIdx.x*blockDim.x + threadIdx.x;
    if (n >= NN) return;
    int a = g_offs[n], b = g_offs[n+1];
    for (int i = a+1; i < b; ++i) {
        int key = g_eidx[i];
        int j = i-1;
        while (j >= a && g_eidx[j] > key) { g_eidx[j+1] = g_eidx[j]; --j; }
        g_eidx[j+1] = key;
    }
}

// ---------------- tf32 rounding helpers ----------------
__device__ __forceinline__ float f2tf32(float x) {
    uint32_t r;
    asm("cvt.rna.tf32.f32 %0, %1;" : "=r"(r) : "f"(x));
    return __uint_as_float(r);
}

// in-place round-to-nearest tf32 (idempotent)
__global__ void round_ip_kernel(float* p, int n4) {
    int i = blockIdx.x*blockDim.x + threadIdx.x;
    if (i < n4) {
        float4 v = ((float4*)p)[i];
        v.x = f2tf32(v.x); v.y = f2tf32(v.y);
        v.z = f2tf32(v.z); v.w = f2tf32(v.w);
        ((float4*)p)[i] = v;
    }
}

__global__ void round_cp_kernel(const float* __restrict__ s, float* __restrict__ d, int n4) {
    int i = blockIdx.x*blockDim.x + threadIdx.x;
    if (i < n4) {
        float4 v = __ldg((const float4*)s + i);
        v.x = f2tf32(v.x); v.y = f2tf32(v.y);
        v.z = f2tf32(v.z); v.w = f2tf32(v.w);
        ((float4*)d)[i] = v;
    }
}

// ---------------- layer-1 projections ----------------
__global__ void proj1_kernel(const float* __restrict__ x,
    const float* __restrict__ Wq, const float* __restrict__ bq,
    const float* __restrict__ Wk, const float* __restrict__ bk,
    const float* __restrict__ Wv, const float* __restrict__ bv,
    const float* __restrict__ Ws, const float* __restrict__ bs)
{
    int warp = (blockIdx.x*blockDim.x + threadIdx.x) >> 5;
    int lane = threadIdx.x & 31;
    if (warp >= NN) return;
    float xr[9];
    #pragma unroll
    for (int t = 0; t < 9; ++t) xr[t] = __ldg(&x[warp*9 + t]);
    for (int j = lane; j < 512; j += 32) {
        float aq = __ldg(&bq[j]), ak = __ldg(&bk[j]);
        float av = __ldg(&bv[j]), as_ = __ldg(&bs[j]);
        #pragma unroll
        for (int t = 0; t < 9; ++t) {
            float xv = xr[t];
            aq  = fmaf(xv, __ldg(&Wq[t*512+j]), aq);
            ak  = fmaf(xv, __ldg(&Wk[t*512+j]), ak);
            av  = fmaf(xv, __ldg(&Wv[t*512+j]), av);
            as_ = fmaf(xv, __ldg(&Ws[t*512+j]), as_);
        }
        size_t o = (size_t)warp*512 + j;
        g_q1[o] = aq; g_k1[o] = ak; g_v1[o] = av; g_s1[o] = as_;
    }
}

// ---------------- attention: one warp per destination node, online softmax ----------------
template<int D, int H, bool RELU>
__global__ void __launch_bounds__(256) attn_kernel(
    const float* __restrict__ q, const float* __restrict__ k,
    const float* __restrict__ v, const float* __restrict__ s,
    const float* __restrict__ ea, const float* __restrict__ We,
    const int* __restrict__ srcArr, float* __restrict__ out)
{
    constexpr int VPT = D / 32;
    constexpr int NV4 = VPT / 4;
    constexpr int C = D / H;
    __shared__ float sWeT[4*D];
    for (int i = threadIdx.x; i < 4*D; i += blockDim.x) {
        int c = i >> 2, t = i & 3;
        sWeT[i] = __ldg(&We[t*D + c]);
    }
    __syncthreads();

    int warp = (blockIdx.x*blockDim.x + threadIdx.x) >> 5;
    int lane = threadIdx.x & 31;
    if (warp >= NN) return;
    int cbase = lane * VPT;

    float4 qr[NV4], acc[NV4];
    const float4* q4 = (const float4*)(q + (size_t)warp*D + cbase);
    #pragma unroll
    for (int i = 0; i < NV4; ++i) { qr[i] = __ldg(q4 + i); acc[i] = make_float4(0.f,0.f,0.f,0.f); }

    float m = -INFINITY, den = 0.f;
    const float invs = rsqrtf((float)C);
    const float4* sWe4 = (const float4*)sWeT;

    int e0 = g_offs[warp], e1 = g_offs[warp+1];
    for (int t = e0; t < e1; ++t) {
        int e  = __ldg(&g_eidx[t]);
        int sn = __ldg(&srcArr[e]);
        float4 a4 = __ldg((const float4*)ea + e);
        const float4* k4 = (const float4*)(k + (size_t)sn*D + cbase);
        float p = 0.f;
        #pragma unroll
        for (int i = 0; i < NV4; ++i) {
            float4 kk = __ldg(k4 + i);
            int c = cbase + 4*i;
            float4 w0 = sWe4[c+0], w1 = sWe4[c+1], w2 = sWe4[c+2], w3 = sWe4[c+3];
            float ex0 = a4.x*w0.x + a4.y*w0.y + a4.z*w0.z + a4.w*w0.w;
            float ex1 = a4.x*w1.x + a4.y*w1.y + a4.z*w1.z + a4.w*w1.w;
            float ex2 = a4.x*w2.x + a4.y*w2.y + a4.z*w2.z + a4.w*w2.w;
            float ex3 = a4.x*w3.x + a4.y*w3.y + a4.z*w3.z + a4.w*w3.w;
            p += qr[i].x*(kk.x+ex0) + qr[i].y*(kk.y+ex1)
               + qr[i].z*(kk.z+ex2) + qr[i].w*(kk.w+ex3);
        }
        p += __shfl_xor_sync(0xffffffffu, p, 1);
        p += __shfl_xor_sync(0xffffffffu, p, 2);
        p += __shfl_xor_sync(0xffffffffu, p, 4);
        float alpha = p * invs;
        float nm = fmaxf(m, alpha);
        float sc = __expf(m - nm);
        float w  = __expf(alpha - nm);
        den = den*sc + w;
        m = nm;
        const float4* v4 = (const float4*)(v + (size_t)sn*D + cbase);
        #pragma unroll
        for (int i = 0; i < NV4; ++i) {
            float4 vv = __ldg(v4 + i);
            int c = cbase + 4*i;
            float4 w0 = sWe4[c+0], w1 = sWe4[c+1], w2 = sWe4[c+2], w3 = sWe4[c+3];
            float ex0 = a4.x*w0.x + a4.y*w0.y + a4.z*w0.z + a4.w*w0.w;
            float ex1 = a4.x*w1.x + a4.y*w1.y + a4.z*w1.z + a4.w*w1.w;
            float ex2 = a4.x*w2.x + a4.y*w2.y + a4.z*w2.z + a4.w*w2.w;
            float ex3 = a4.x*w3.x + a4.y*w3.y + a4.z*w3.z + a4.w*w3.w;
            acc[i].x = acc[i].x*sc + w*(vv.x+ex0);
            acc[i].y = acc[i].y*sc + w*(vv.y+ex1);
            acc[i].z = acc[i].z*sc + w*(vv.z+ex2);
            acc[i].w = acc[i].w*sc + w*(vv.w+ex3);
        }
    }
    float r = 1.f / (den + 1e-16f);
    const float4* s4 = (const float4*)(s + (size_t)warp*D + cbase);
    float4* o4 = (float4*)(out + (size_t)warp*D + cbase);
    #pragma unroll
    for (int i = 0; i < NV4; ++i) {
        float4 sv = __ldg(s4 + i);
        float4 o;
        o.x = acc[i].x*r + sv.x;
        o.y = acc[i].y*r + sv.y;
        o.z = acc[i].z*r + sv.z;
        o.w = acc[i].w*r + sv.w;
        if (RELU) {
            o.x = fmaxf(o.x, 0.f); o.y = fmaxf(o.y, 0.f);
            o.z = fmaxf(o.z, 0.f); o.w = fmaxf(o.w, 0.f);
        }
        o4[i] = o;
    }
}

// ---------------- pipelined tf32 tensor-core GEMM ----------------
// Inputs must already be tf32-rounded (rna). Double-buffered cp.async, BM=BN=128, BK=32.
// z-dim selects one of up to 4 weight/bias/output sets sharing the same A.
__device__ __forceinline__ void cpa16(float* dst, const float* src, bool pred) {
    uint32_t d = (uint32_t)__cvta_generic_to_shared(dst);
    int sz = pred ? 16 : 0;
    asm volatile("cp.async.cg.shared.global [%0], [%1], 16, %2;\n"
                 :: "r"(d), "l"(src), "r"(sz));
}

#define AS(st,m,k) Asb[((st)*128 + (m))*36 + (k)]
#define BS(st,k,n) Bsb[((st)*32 + (k))*136 + (n)]

__global__ void __launch_bounds__(256) gemm_tf32_pipe(
    const float* __restrict__ A,
    const float* B0, const float* B1, const float* B2, const float* B3,
    const float* c0, const float* c1, const float* c2, const float* c3,
    float* C0, float* C1, float* C2, float* C3,
    int M, int N, int K, int ldc, int coff)
{
    extern __shared__ float smempool[];
    float* Asb = smempool;               // [2][128][36]
    float* Bsb = smempool + 2*128*36;    // [2][32][136]

    int z = blockIdx.z;
    const float* Bw   = (z==0) ? B0 : (z==1) ? B1 : (z==2) ? B2 : B3;
    const float* bias = (z==0) ? c0 : (z==1) ? c1 : (z==2) ? c2 : c3;
    float*       C    = (z==0) ? C0 : (z==1) ? C1 : (z==2) ? C2 : C3;

    int tid  = threadIdx.x;
    int lane = tid & 31, wid = tid >> 5;
    int wm = wid >> 2, wn = wid & 3;
    int m0 = blockIdx.x * 128, n0 = blockIdx.y * 128;
    int row = lane >> 2, col = lane & 3;

    // per-thread load coords (constant across tiles)
    int am[4], ak[4], bk_[4], bn[4];
    #pragma unroll
    for (int i = 0; i < 4; ++i) {
        int idx = tid + i*256;
        am[i] = idx >> 3;  ak[i] = (idx & 7) * 4;
        bk_[i] = idx >> 5; bn[i] = (idx & 31) * 4;
    }

    float acc[4][4][4];
    #pragma unroll
    for (int a = 0; a < 4; ++a)
        #pragma unroll
        for (int b = 0; b < 4; ++b)
            #pragma unroll
            for (int c = 0; c < 4; ++c) acc[a][b][c] = 0.f;

    int T = K >> 5;   // K/32 tiles

    // prologue: stage 0
    #pragma unroll
    for (int i = 0; i < 4; ++i)
        cpa16(&AS(0, am[i], ak[i]), &A[(size_t)(m0+am[i])*K + ak[i]], (m0+am[i]) < M);
    #pragma unroll
    for (int i = 0; i < 4; ++i)
        cpa16(&BS(0, bk_[i], bn[i]), &Bw[(size_t)bk_[i]*N + n0 + bn[i]], true);
    asm volatile("cp.async.commit_group;\n");

    for (int t = 0; t < T; ++t) {
        int st = t & 1;
        if (t + 1 < T) {
            int kt = (t+1) << 5;
            int ns = st ^ 1;
            #pragma unroll
            for (int i = 0; i < 4; ++i)
                cpa16(&AS(ns, am[i], ak[i]), &A[(size_t)(m0+am[i])*K + kt + ak[i]], (m0+am[i]) < M);
            #pragma unroll
            for (int i = 0; i < 4; ++i)
                cpa16(&BS(ns, bk_[i], bn[i]), &Bw[(size_t)(kt+bk_[i])*N + n0 + bn[i]], true);
            asm volatile("cp.async.commit_group;\n");
            asm volatile("cp.async.wait_group 1;\n");
        } else {
            asm volatile("cp.async.wait_group 0;\n");
        }
        __syncthreads();

        #pragma unroll
        for (int kc = 0; kc < 4; ++kc) {
            int kb = kc * 8;
            uint32_t af[4][4], bf[4][2];
            #pragma unroll
            for (int mt = 0; mt < 4; ++mt) {
                int mb = wm*64 + mt*16;
                af[mt][0] = __float_as_uint(AS(st, mb+row,   kb+col));
                af[mt][1] = __float_as_uint(AS(st, mb+row+8, kb+col));
                af[mt][2] = __float_as_uint(AS(st, mb+row,   kb+col+4));
                af[mt][3] = __float_as_uint(AS(st, mb+row+8, kb+col+4));
            }
            #pragma unroll
            for (int nt = 0; nt < 4; ++nt) {
                int nb = wn*32 + nt*8;
                bf[nt][0] = __float_as_uint(BS(st, kb+col,   nb+row));
                bf[nt][1] = __float_as_uint(BS(st, kb+col+4, nb+row));
            }
            #pragma unroll
            for (int mt = 0; mt < 4; ++mt)
                #pragma unroll
                for (int nt = 0; nt < 4; ++nt) {
                    asm volatile(
                        "mma.sync.aligned.m16n8k8.row.col.f32.tf32.tf32.f32 "
                        "{%0,%1,%2,%3}, {%4,%5,%6,%7}, {%8,%9}, {%0,%1,%2,%3};"
                        : "+f"(acc[mt][nt][0]), "+f"(acc[mt][nt][1]),
                          "+f"(acc[mt][nt][2]), "+f"(acc[mt][nt][3])
                        : "r"(af[mt][0]), "r"(af[mt][1]), "r"(af[mt][2]), "r"(af[mt][3]),
                          "r"(bf[nt][0]), "r"(bf[nt][1]));
                }
        }
        __syncthreads();
    }

    #pragma unroll
    for (int mt = 0; mt < 4; ++mt) {
        int r0 = m0 + wm*64 + mt*16 + row;
        #pragma unroll
        for (int nt = 0; nt < 4; ++nt) {
            int c = n0 + wn*32 + nt*8 + col*2;
            float bv0 = __ldg(&bias[c]), bv1 = __ldg(&bias[c+1]);
            if (r0 < M) {
                float2 o = make_float2(acc[mt][nt][0] + bv0, acc[mt][nt][1] + bv1);
                *(float2*)&C[(size_t)r0*ldc + coff + c] = o;
            }
            if (r0 + 8 < M) {
                float2 o = make_float2(acc[mt][nt][2] + bv0, acc[mt][nt][3] + bv1);
                *(float2*)&C[(size_t)(r0+8)*ldc + coff + c] = o;
            }
        }
    }
}

// ---------------- mean pool over 20 nodes per graph -> concat[:, :1024] ----------------
__global__ void pool_kernel() {
    int c = blockIdx.y*blockDim.x + threadIdx.x;
    int b = blockIdx.x;
    float sum = 0.f;
    #pragma unroll
    for (int i = 0; i < NPG; ++i)
        sum += g_h2[(size_t)(b*NPG + i)*1024 + c];
    g_concat[b*1280 + c] = sum * (1.f/NPG);
}

// ---------------- launch ----------------
extern "C" void kernel_launch(void* const* d_in, const int* in_sizes, int n_in,
                              void* d_out, int out_size)
{
    const float* x    = (const float*)d_in[0];
    const int*   ei   = (const int*)  d_in[1];
    const float* ea   = (const float*)d_in[2];
    const float* fpb  = (const float*)d_in[4];
    const float *Wq1=(const float*)d_in[5],  *bq1=(const float*)d_in[6];
    const float *Wk1=(const float*)d_in[7],  *bk1=(const float*)d_in[8];
    const float *Wv1=(const float*)d_in[9],  *bv1=(const float*)d_in[10];
    const float *We1=(const float*)d_in[11];
    const float *Ws1=(const float*)d_in[12], *bs1=(const float*)d_in[13];
    const float *Wq2=(const float*)d_in[14], *bq2=(const float*)d_in[15];
    const float *Wk2=(const float*)d_in[16], *bk2=(const float*)d_in[17];
    const float *Wv2=(const float*)d_in[18], *bv2=(const float*)d_in[19];
    const float *We2=(const float*)d_in[20];
    const float *Ws2=(const float*)d_in[21], *bs2=(const float*)d_in[22];
    const float *Wfp=(const float*)d_in[23], *bfp=(const float*)d_in[24];
    const float *Wfin=(const float*)d_in[25],*bfin=(const float*)d_in[26];

    const int* srcArr = ei;
    const int* dstArr = ei + EE;

    float *q1,*k1,*v1,*s1,*h1,*q2,*k2,*v2,*s2,*h2,*cc;
    float *wq2t,*wk2t,*wv2t,*ws2t,*wfpt,*wfint,*fpbt;
    cudaGetSymbolAddress((void**)&q1, g_q1);
    cudaGetSymbolAddress((void**)&k1, g_k1);
    cudaGetSymbolAddress((void**)&v1, g_v1);
    cudaGetSymbolAddress((void**)&s1, g_s1);
    cudaGetSymbolAddress((void**)&h1, g_h1);
    cudaGetSymbolAddress((void**)&q2, g_q2);
    cudaGetSymbolAddress((void**)&k2, g_k2);
    cudaGetSymbolAddress((void**)&v2, g_v2);
    cudaGetSymbolAddress((void**)&s2, g_s2);
    cudaGetSymbolAddress((void**)&h2, g_h2);
    cudaGetSymbolAddress((void**)&cc, g_concat);
    cudaGetSymbolAddress((void**)&wq2t, g_wq2t);
    cudaGetSymbolAddress((void**)&wk2t, g_wk2t);
    cudaGetSymbolAddress((void**)&wv2t, g_wv2t);
    cudaGetSymbolAddress((void**)&ws2t, g_ws2t);
    cudaGetSymbolAddress((void**)&wfpt, g_wfpt);
    cudaGetSymbolAddress((void**)&wfint, g_wfint);
    cudaGetSymbolAddress((void**)&fpbt, g_fpbt);

    const int SMEM = (2*128*36 + 2*32*136) * 4;  // 71680 B
    cudaFuncSetAttribute(gemm_tf32_pipe, cudaFuncAttributeMaxDynamicSharedMemorySize, SMEM);

    // CSR build
    zero_deg_kernel<<<(NN+255)/256, 256>>>();
    hist_kernel<<<(EE+255)/256, 256>>>(dstArr);
    scan_kernel<<<1, 1024>>>();
    scatter_kernel<<<(EE+255)/256, 256>>>(dstArr);
    sort_kernel<<<(NN+255)/256, 256>>>();

    // layer 1
    proj1_kernel<<<(NN*32+255)/256, 256>>>(x, Wq1,bq1, Wk1,bk1, Wv1,bv1, Ws1,bs1);
    attn_kernel<512,4,true><<<(NN*32+255)/256, 256>>>(q1,k1,v1,s1, ea, We1, srcArr, h1);

    // tf32-round operands for layer-2 projections
    round_ip_kernel<<<(NN*512/4+255)/256, 256>>>(h1, NN*512/4);
    round_cp_kernel<<<(512*1024/4+255)/256, 256>>>(Wq2, wq2t, 512*1024/4);
    round_cp_kernel<<<(512*1024/4+255)/256, 256>>>(Wk2, wk2t, 512*1024/4);
    round_cp_kernel<<<(512*1024/4+255)/256, 256>>>(Wv2, wv2t, 512*1024/4);
    round_cp_kernel<<<(512*1024/4+255)/256, 256>>>(Ws2, ws2t, 512*1024/4);

    // layer-2 projections: fused pipelined tf32 GEMM, z = {q,k,v,s}
    {
        dim3 grid((NN+127)/128, 1024/128, 4);
        gemm_tf32_pipe<<<grid, 256, SMEM>>>(h1,
            wq2t, wk2t, wv2t, ws2t,
            bq2, bk2, bv2, bs2,
            q2, k2, v2, s2,
            NN, 1024, 512, 1024, 0);
    }

    attn_kernel<1024,4,false><<<(NN*32+255)/256, 256>>>(q2,k2,v2,s2, ea, We2, srcArr, h2);

    // pooling
    pool_kernel<<<dim3(BB, 4), 256>>>();

    // fingerprint GEMM (tf32): concat[:, 1024:1280] = fpb @ Wfp + bfp
    round_cp_kernel<<<(BB*2048/4+255)/256, 256>>>(fpb, fpbt, BB*2048/4);
    round_cp_kernel<<<(2048*256/4+255)/256, 256>>>(Wfp, wfpt, 2048*256/4);
    gemm_tf32_pipe<<<dim3((BB+127)/128, 256/128, 1), 256, SMEM>>>(fpbt,
        wfpt, wfpt, wfpt, wfpt, bfp, bfp, bfp, bfp, cc, cc, cc, cc,
        BB, 256, 2048, 1280, 1024);

    // final GEMM (tf32): out = concat @ Wfin + bfin
    round_ip_kernel<<<(BB*1280/4+255)/256, 256>>>(cc, BB*1280/4);
    round_cp_kernel<<<(1280*1024/4+255)/256, 256>>>(Wfin, wfint, 1280*1024/4);
    gemm_tf32_pipe<<<dim3((BB+127)/128, 1024/128, 1), 256, SMEM>>>(cc,
        wfint, wfint, wfint, wfint, bfin, bfin, bfin, bfin,
        (float*)d_out, (float*)d_out, (float*)d_out, (float*)d_out,
        BB, 1024, 1280, 1024, 0);
}

// round 5
// speedup vs baseline: 1.5835x; 1.5835x over previous
#include <cuda_runtime.h>
#include <cuda_fp16.h>
#include <math.h>
#include <stdint.h>

#define NN 24000
#define EE 96000
#define BB 1200
#define NPG 20

// ---------------- device scratch (no allocations allowed) ----------------
__device__ float g_q1[NN*512];
__device__ float g_k1[NN*512];
__device__ float g_v1[NN*512];
__device__ float g_s1[NN*512];
__device__ float g_h1[NN*512];
__device__ float g_q2[NN*1024];
__device__ float g_k2[NN*1024];
__device__ float g_v2[NN*1024];
__device__ float g_s2[NN*1024];
__device__ float g_h2[NN*1024];
__device__ float g_concat[BB*1280];
__device__ int   g_deg[NN];
__device__ int   g_offs[NN+1];
__device__ int   g_cursor[NN];
__device__ int   g_eidx[EE];
// fp16 operands for the f16 tensor-core GEMM
__device__ __half g_h1h[NN*512];
__device__ __half g_w2h[4*1024*512];   // [z][n][k]  (transposed, k contiguous)

// ---------------- CSR build ----------------
__global__ void zero_deg_kernel() {
    int i = blockIdx.x*blockDim.x + threadIdx.x;
    if (i < NN) g_deg[i] = 0;
}

__global__ void hist_kernel(const int* __restrict__ dst) {
    int e = blockIdx.x*blockDim.x + threadIdx.x;
    if (e < EE) atomicAdd(&g_deg[dst[e]], 1);
}

__global__ void scan_kernel() {
    __shared__ int wsum[32];
    __shared__ int carry;
    int tid = threadIdx.x;
    int lane = tid & 31, wid = tid >> 5;
    if (tid == 0) carry = 0;
    __syncthreads();
    for (int base = 0; base < NN; base += 1024) {
        int i = base + tid;
        int v = (i < NN) ? g_deg[i] : 0;
        int x = v;
        #pragma unroll
        for (int o = 1; o < 32; o <<= 1) {
            int y = __shfl_up_sync(0xffffffffu, x, o);
            if (lane >= o) x += y;
        }
        if (lane == 31) wsum[wid] = x;
        __syncthreads();
        if (wid == 0) {
            int s = wsum[lane];
            #pragma unroll
            for (int o = 1; o < 32; o <<= 1) {
                int y = __shfl_up_sync(0xffffffffu, s, o);
                if (lane >= o) s += y;
            }
            wsum[lane] = s;
        }
        __syncthreads();
        int pre = (wid > 0 ? wsum[wid-1] : 0) + carry;
        int incl = x + pre;
        if (i < NN) { g_offs[i] = incl - v; g_cursor[i] = incl - v; }
        __syncthreads();
        if (tid == 1023) carry = incl;
        __syncthreads();
    }
    if (tid == 0) g_offs[NN] = carry;
}

__global__ void scatter_kernel(const int* __restrict__ dst) {
    int e = blockIdx.x*blockDim.x + threadIdx.x;
    if (e < EE) {
        int p = atomicAdd(&g_cursor[dst[e]], 1);
        g_eidx[p] = e;
    }
}

__global__ void sort_kernel() {
    int n = blockIdx.x*blockDim.x + threadIdx.x;
    if (n >= NN) return;
    int a = g_offs[n], b = g_offs[n+1];
    for (int i = a+1; i < b; ++i) {
        int key = g_eidx[i];
        int j = i-1;
        while (j >= a && g_eidx[j] > key) { g_eidx[j+1] = g_eidx[j]; --j; }
        g_eidx[j+1] = key;
    }
}

// ---------------- layer-1 projections ----------------
__global__ void proj1_kernel(const float* __restrict__ x,
    const float* __restrict__ Wq, const float* __restrict__ bq,
    const float* __restrict__ Wk, const float* __restrict__ bk,
    const float* __restrict__ Wv, const float* __restrict__ bv,
    const float* __restrict__ Ws, const float* __restrict__ bs)
{
    int warp = (blockIdx.x*blockDim.x + threadIdx.x) >> 5;
    int lane = threadIdx.x & 31;
    if (warp >= NN) return;
    float xr[9];
    #pragma unroll
    for (int t = 0; t < 9; ++t) xr[t] = __ldg(&x[warp*9 + t]);
    for (int j = lane; j < 512; j += 32) {
        float aq = __ldg(&bq[j]), ak = __ldg(&bk[j]);
        float av = __ldg(&bv[j]), as_ = __ldg(&bs[j]);
        #pragma unroll
        for (int t = 0; t < 9; ++t) {
            float xv = xr[t];
            aq  = fmaf(xv, __ldg(&Wq[t*512+j]), aq);
            ak  = fmaf(xv, __ldg(&Wk[t*512+j]), ak);
            av  = fmaf(xv, __ldg(&Wv[t*512+j]), av);
            as_ = fmaf(xv, __ldg(&Ws[t*512+j]), as_);
        }
        size_t o = (size_t)warp*512 + j;
        g_q1[o] = aq; g_k1[o] = ak; g_v1[o] = av; g_s1[o] = as_;
    }
}

// ---------------- attention: one warp per destination node, online softmax ----------------
template<int D, int H, bool RELU>
__global__ void __launch_bounds__(256) attn_kernel(
    const float* __restrict__ q, const float* __restrict__ k,
    const float* __restrict__ v, const float* __restrict__ s,
    const float* __restrict__ ea, const float* __restrict__ We,
    const int* __restrict__ srcArr, float* __restrict__ out)
{
    constexpr int VPT = D / 32;
    constexpr int NV4 = VPT / 4;
    constexpr int C = D / H;
    __shared__ float sWeT[4*D];
    for (int i = threadIdx.x; i < 4*D; i += blockDim.x) {
        int c = i >> 2, t = i & 3;
        sWeT[i] = __ldg(&We[t*D + c]);
    }
    __syncthreads();

    int warp = (blockIdx.x*blockDim.x + threadIdx.x) >> 5;
    int lane = threadIdx.x & 31;
    if (warp >= NN) return;
    int cbase = lane * VPT;

    float4 qr[NV4], acc[NV4];
    const float4* q4 = (const float4*)(q + (size_t)warp*D + cbase);
    #pragma unroll
    for (int i = 0; i < NV4; ++i) { qr[i] = __ldg(q4 + i); acc[i] = make_float4(0.f,0.f,0.f,0.f); }

    float m = -INFINITY, den = 0.f;
    const float invs = rsqrtf((float)C);
    const float4* sWe4 = (const float4*)sWeT;

    int e0 = g_offs[warp], e1 = g_offs[warp+1];
    for (int t = e0; t < e1; ++t) {
        int e  = __ldg(&g_eidx[t]);
        int sn = __ldg(&srcArr[e]);
        float4 a4 = __ldg((const float4*)ea + e);
        const float4* k4 = (const float4*)(k + (size_t)sn*D + cbase);
        float p = 0.f;
        #pragma unroll
        for (int i = 0; i < NV4; ++i) {
            float4 kk = __ldg(k4 + i);
            int c = cbase + 4*i;
            float4 w0 = sWe4[c+0], w1 = sWe4[c+1], w2 = sWe4[c+2], w3 = sWe4[c+3];
            float ex0 = a4.x*w0.x + a4.y*w0.y + a4.z*w0.z + a4.w*w0.w;
            float ex1 = a4.x*w1.x + a4.y*w1.y + a4.z*w1.z + a4.w*w1.w;
            float ex2 = a4.x*w2.x + a4.y*w2.y + a4.z*w2.z + a4.w*w2.w;
            float ex3 = a4.x*w3.x + a4.y*w3.y + a4.z*w3.z + a4.w*w3.w;
            p += qr[i].x*(kk.x+ex0) + qr[i].y*(kk.y+ex1)
               + qr[i].z*(kk.z+ex2) + qr[i].w*(kk.w+ex3);
        }
        p += __shfl_xor_sync(0xffffffffu, p, 1);
        p += __shfl_xor_sync(0xffffffffu, p, 2);
        p += __shfl_xor_sync(0xffffffffu, p, 4);
        float alpha = p * invs;
        float nm = fmaxf(m, alpha);
        float sc = __expf(m - nm);
        float w  = __expf(alpha - nm);
        den = den*sc + w;
        m = nm;
        const float4* v4 = (const float4*)(v + (size_t)sn*D + cbase);
        #pragma unroll
        for (int i = 0; i < NV4; ++i) {
            float4 vv = __ldg(v4 + i);
            int c = cbase + 4*i;
            float4 w0 = sWe4[c+0], w1 = sWe4[c+1], w2 = sWe4[c+2], w3 = sWe4[c+3];
            float ex0 = a4.x*w0.x + a4.y*w0.y + a4.z*w0.z + a4.w*w0.w;
            float ex1 = a4.x*w1.x + a4.y*w1.y + a4.z*w1.z + a4.w*w1.w;
            float ex2 = a4.x*w2.x + a4.y*w2.y + a4.z*w2.z + a4.w*w2.w;
            float ex3 = a4.x*w3.x + a4.y*w3.y + a4.z*w3.z + a4.w*w3.w;
            acc[i].x = acc[i].x*sc + w*(vv.x+ex0);
            acc[i].y = acc[i].y*sc + w*(vv.y+ex1);
            acc[i].z = acc[i].z*sc + w*(vv.z+ex2);
            acc[i].w = acc[i].w*sc + w*(vv.w+ex3);
        }
    }
    float r = 1.f / (den + 1e-16f);
    const float4* s4 = (const float4*)(s + (size_t)warp*D + cbase);
    float4* o4 = (float4*)(out + (size_t)warp*D + cbase);
    #pragma unroll
    for (int i = 0; i < NV4; ++i) {
        float4 sv = __ldg(s4 + i);
        float4 o;
        o.x = acc[i].x*r + sv.x;
        o.y = acc[i].y*r + sv.y;
        o.z = acc[i].z*r + sv.z;
        o.w = acc[i].w*r + sv.w;
        if (RELU) {
            o.x = fmaxf(o.x, 0.f); o.y = fmaxf(o.y, 0.f);
            o.z = fmaxf(o.z, 0.f); o.w = fmaxf(o.w, 0.f);
        }
        o4[i] = o;
    }
}

// ---------------- fp16 conversion pre-passes ----------------
__global__ void h2half_kernel(const float* __restrict__ src, int n2) {
    int i = blockIdx.x*blockDim.x + threadIdx.x;
    if (i < n2) {
        float2 v = ((const float2*)src)[i];
        ((__half2*)g_h1h)[i] = __floats2half2_rn(v.x, v.y);
    }
}

// transpose-convert: Wt[z][n][k] = (half)W_z[k][n]; W_z is [512][1024]
__global__ void wt2half_kernel(const float* __restrict__ W0, const float* __restrict__ W1,
                               const float* __restrict__ W2, const float* __restrict__ W3) {
    __shared__ float tile[32][33];
    int z = blockIdx.z;
    const float* W = (z==0) ? W0 : (z==1) ? W1 : (z==2) ? W2 : W3;
    int n0 = blockIdx.x * 32, k0 = blockIdx.y * 32;
    int tx = threadIdx.x, ty = threadIdx.y;
    tile[ty][tx] = __ldg(&W[(size_t)(k0+ty)*1024 + n0 + tx]);
    __syncthreads();
    g_w2h[(size_t)z*1024*512 + (size_t)(n0+ty)*512 + k0 + tx] = __float2half_rn(tile[tx][ty]);
}

// ---------------- f16 tensor-core GEMM (m16n8k16): C_z[M,1024] = A[M,512] @ W_z + bias_z ----
// BM=BN=128, BK=32, 256 threads (8 warps 2x4), register-prefetch double buffering.
// Smem rows stored as half2 (u32) with stride 20: bank set {g*20+t mod 32} is a permutation.
__global__ void __launch_bounds__(256) gemm4_f16_kernel(
    const __half* __restrict__ Ah,
    const float* __restrict__ b0, const float* __restrict__ b1,
    const float* __restrict__ b2, const float* __restrict__ b3,
    float* C0, float* C1, float* C2, float* C3, int M)
{
    __shared__ uint32_t As[2][128][20];   // [buf][m][k-pair]
    __shared__ uint32_t Bs[2][128][20];   // [buf][n][k-pair]

    int z = blockIdx.z;
    const __half* Bz  = g_w2h + (size_t)z*1024*512;
    const float* bias = (z==0) ? b0 : (z==1) ? b1 : (z==2) ? b2 : b3;
    float*       C    = (z==0) ? C0 : (z==1) ? C1 : (z==2) ? C2 : C3;

    int tid  = threadIdx.x;
    int lane = tid & 31, wid = tid >> 5;
    int wm = wid >> 2, wn = wid & 3;
    int m0 = blockIdx.x * 128, n0 = blockIdx.y * 128;
    int g = lane >> 2, t = lane & 3;

    // load coords: 2 float4 (= 8 halves) per thread per operand per tile
    int lm[2], lq[2];   // row, half-offset within 32-half row chunk
    #pragma unroll
    for (int i = 0; i < 2; ++i) {
        int idx = tid + i*256;
        lm[i] = idx >> 2;
        lq[i] = (idx & 3) * 8;
    }

    float acc[4][4][4];
    #pragma unroll
    for (int a = 0; a < 4; ++a)
        #pragma unroll
        for (int b = 0; b < 4; ++b)
            #pragma unroll
            for (int c = 0; c < 4; ++c) acc[a][b][c] = 0.f;

    float4 pa[2], pb[2];
    const int T = 512 / 32;   // 16 K-tiles

    // prologue: tile 0 -> regs -> buf 0
    #pragma unroll
    for (int i = 0; i < 2; ++i) {
        pa[i] = (m0 + lm[i] < M)
              ? *(const float4*)(Ah + (size_t)(m0+lm[i])*512 + lq[i])
              : make_float4(0.f,0.f,0.f,0.f);
        pb[i] = *(const float4*)(Bz + (size_t)(n0+lm[i])*512 + lq[i]);
    }
    #pragma unroll
    for (int i = 0; i < 2; ++i) {
        *(float4*)&As[0][lm[i]][lq[i]>>1] = pa[i];
        *(float4*)&Bs[0][lm[i]][lq[i]>>1] = pb[i];
    }
    __syncthreads();

    for (int kt = 0; kt < T; ++kt) {
        int b = kt & 1;
        if (kt + 1 < T) {
            int ko = (kt+1) * 32;
            #pragma unroll
            for (int i = 0; i < 2; ++i) {
                pa[i] = (m0 + lm[i] < M)
                      ? *(const float4*)(Ah + (size_t)(m0+lm[i])*512 + ko + lq[i])
                      : make_float4(0.f,0.f,0.f,0.f);
                pb[i] = *(const float4*)(Bz + (size_t)(n0+lm[i])*512 + ko + lq[i]);
            }
        }

        #pragma unroll
        for (int ks = 0; ks < 2; ++ks) {
            int kb = ks * 8;
            uint32_t af[4][4], bf[4][2];
            #pragma unroll
            for (int mt = 0; mt < 4; ++mt) {
                int mb = wm*64 + mt*16;
                af[mt][0] = As[b][mb+g  ][kb+t  ];
                af[mt][1] = As[b][mb+g+8][kb+t  ];
                af[mt][2] = As[b][mb+g  ][kb+t+4];
                af[mt][3] = As[b][mb+g+8][kb+t+4];
            }
            #pragma unroll
            for (int nt = 0; nt < 4; ++nt) {
                int nb = wn*32 + nt*8;
                bf[nt][0] = Bs[b][nb+g][kb+t  ];
                bf[nt][1] = Bs[b][nb+g][kb+t+4];
            }
            #pragma unroll
            for (int mt = 0; mt < 4; ++mt)
                #pragma unroll
                for (int nt = 0; nt < 4; ++nt) {
                    asm volatile(
                        "mma.sync.aligned.m16n8k16.row.col.f32.f16.f16.f32 "
                        "{%0,%1,%2,%3}, {%4,%5,%6,%7}, {%8,%9}, {%0,%1,%2,%3};"
                        : "+f"(acc[mt][nt][0]), "+f"(acc[mt][nt][1]),
                          "+f"(acc[mt][nt][2]), "+f"(acc[mt][nt][3])
                        : "r"(af[mt][0]), "r"(af[mt][1]), "r"(af[mt][2]), "r"(af[mt][3]),
                          "r"(bf[nt][0]), "r"(bf[nt][1]));
                }
        }

        if (kt + 1 < T) {
            int nb_ = b ^ 1;
            #pragma unroll
            for (int i = 0; i < 2; ++i) {
                *(float4*)&As[nb_][lm[i]][lq[i]>>1] = pa[i];
                *(float4*)&Bs[nb_][lm[i]][lq[i]>>1] = pb[i];
            }
            __syncthreads();
        }
    }

    // epilogue: c0,c1 -> (row=g, col=2t,2t+1); c2,c3 -> (row=g+8)
    #pragma unroll
    for (int mt = 0; mt < 4; ++mt) {
        int r0 = m0 + wm*64 + mt*16 + g;
        #pragma unroll
        for (int nt = 0; nt < 4; ++nt) {
            int c = n0 + wn*32 + nt*8 + t*2;
            float bv0 = __ldg(&bias[c]), bv1 = __ldg(&bias[c+1]);
            if (r0 < M) {
                float2 o = make_float2(acc[mt][nt][0] + bv0, acc[mt][nt][1] + bv1);
                *(float2*)&C[(size_t)r0*1024 + c] = o;
            }
            if (r0 + 8 < M) {
                float2 o = make_float2(acc[mt][nt][2] + bv0, acc[mt][nt][3] + bv1);
                *(float2*)&C[(size_t)(r0+8)*1024 + c] = o;
            }
        }
    }
}

// ---------------- fp32 tiled GEMM (tail GEMMs) ----------------
__global__ void __launch_bounds__(256) gemm_kernel(
    const float* __restrict__ A, const float* __restrict__ Bm,
    const float* __restrict__ bias, float* __restrict__ C,
    int M, int N, int K, int ldc, int coff)
{
    __shared__ float As[16][128+4];
    __shared__ float Bs[16][64+4];
    int tid = threadIdx.x;
    int tx = tid & 15, ty = tid >> 4;
    int m0 = blockIdx.x * 128;
    int n0 = blockIdx.y * 64;
    float acc[8][4] = {};

    for (int k0 = 0; k0 < K; k0 += 16) {
        #pragma unroll
        for (int it = 0; it < 2; ++it) {
            int f = tid + it*256;
            int row = f >> 2;
            int c4 = (f & 3) * 4;
            float4 val = make_float4(0.f,0.f,0.f,0.f);
            if (m0 + row < M)
                val = __ldg((const float4*)&A[(size_t)(m0+row)*K + k0 + c4]);
            As[c4+0][row] = val.x; As[c4+1][row] = val.y;
            As[c4+2][row] = val.z; As[c4+3][row] = val.w;
        }
        {
            int r  = tid >> 4;
            int c4 = (tid & 15) * 4;
            float4 val = __ldg((const float4*)&Bm[(size_t)(k0+r)*N + n0 + c4]);
            *(float4*)&Bs[r][c4] = val;
        }
        __syncthreads();
        #pragma unroll
        for (int kk = 0; kk < 16; ++kk) {
            float a[8], b[4];
            *(float4*)&a[0] = *(const float4*)&As[kk][ty*8];
            *(float4*)&a[4] = *(const float4*)&As[kk][ty*8+4];
            *(float4*)&b[0] = *(const float4*)&Bs[kk][tx*4];
            #pragma unroll
            for (int i = 0; i < 8; ++i)
                #pragma unroll
                for (int j = 0; j < 4; ++j)
                    acc[i][j] = fmaf(a[i], b[j], acc[i][j]);
        }
        __syncthreads();
    }
    #pragma unroll
    for (int i = 0; i < 8; ++i) {
        int row = m0 + ty*8 + i;
        if (row < M) {
            #pragma unroll
            for (int j = 0; j < 4; ++j) {
                int col = n0 + tx*4 + j;
                C[(size_t)row*ldc + coff + col] = acc[i][j] + __ldg(&bias[col]);
            }
        }
    }
}

// ---------------- mean pool ----------------
__global__ void pool_kernel() {
    int c = blockIdx.y*blockDim.x + threadIdx.x;
    int b = blockIdx.x;
    float sum = 0.f;
    #pragma unroll
    for (int i = 0; i < NPG; ++i)
        sum += g_h2[(size_t)(b*NPG + i)*1024 + c];
    g_concat[b*1280 + c] = sum * (1.f/NPG);
}

// ---------------- launch ----------------
extern "C" void kernel_launch(void* const* d_in, const int* in_sizes, int n_in,
                              void* d_out, int out_size)
{
    const float* x    = (const float*)d_in[0];
    const int*   ei   = (const int*)  d_in[1];
    const float* ea   = (const float*)d_in[2];
    const float* fpb  = (const float*)d_in[4];
    const float *Wq1=(const float*)d_in[5],  *bq1=(const float*)d_in[6];
    const float *Wk1=(const float*)d_in[7],  *bk1=(const float*)d_in[8];
    const float *Wv1=(const float*)d_in[9],  *bv1=(const float*)d_in[10];
    const float *We1=(const float*)d_in[11];
    const float *Ws1=(const float*)d_in[12], *bs1=(const float*)d_in[13];
    const float *Wq2=(const float*)d_in[14], *bq2=(const float*)d_in[15];
    const float *Wk2=(const float*)d_in[16], *bk2=(const float*)d_in[17];
    const float *Wv2=(const float*)d_in[18], *bv2=(const float*)d_in[19];
    const float *We2=(const float*)d_in[20];
    const float *Ws2=(const float*)d_in[21], *bs2=(const float*)d_in[22];
    const float *Wfp=(const float*)d_in[23], *bfp=(const float*)d_in[24];
    const float *Wfin=(const float*)d_in[25],*bfin=(const float*)d_in[26];

    const int* srcArr = ei;
    const int* dstArr = ei + EE;

    float *q1,*k1,*v1,*s1,*h1,*q2,*k2,*v2,*s2,*h2,*cc;
    __half *h1h;
    cudaGetSymbolAddress((void**)&q1, g_q1);
    cudaGetSymbolAddress((void**)&k1, g_k1);
    cudaGetSymbolAddress((void**)&v1, g_v1);
    cudaGetSymbolAddress((void**)&s1, g_s1);
    cudaGetSymbolAddress((void**)&h1, g_h1);
    cudaGetSymbolAddress((void**)&q2, g_q2);
    cudaGetSymbolAddress((void**)&k2, g_k2);
    cudaGetSymbolAddress((void**)&v2, g_v2);
    cudaGetSymbolAddress((void**)&s2, g_s2);
    cudaGetSymbolAddress((void**)&h2, g_h2);
    cudaGetSymbolAddress((void**)&cc, g_concat);
    cudaGetSymbolAddress((void**)&h1h, g_h1h);

    // CSR build
    zero_deg_kernel<<<(NN+255)/256, 256>>>();
    hist_kernel<<<(EE+255)/256, 256>>>(dstArr);
    scan_kernel<<<1, 1024>>>();
    scatter_kernel<<<(EE+255)/256, 256>>>(dstArr);
    sort_kernel<<<(NN+255)/256, 256>>>();

    // weight transpose + fp16 convert (independent of layer 1 -> issue early)
    wt2half_kernel<<<dim3(32, 16, 4), dim3(32, 32)>>>(Wq2, Wk2, Wv2, Ws2);

    // layer 1
    proj1_kernel<<<(NN*32+255)/256, 256>>>(x, Wq1,bq1, Wk1,bk1, Wv1,bv1, Ws1,bs1);
    attn_kernel<512,4,true><<<(NN*32+255)/256, 256>>>(q1,k1,v1,s1, ea, We1, srcArr, h1);

    // h1 -> fp16
    h2half_kernel<<<(NN*256+255)/256, 256>>>(h1, NN*256);

    // layer-2 projections: fused f16 tensor-core GEMM, z = {q,k,v,s}
    {
        dim3 grid((NN+127)/128, 1024/128, 4);
        gemm4_f16_kernel<<<grid, 256>>>(h1h, bq2, bk2, bv2, bs2, q2, k2, v2, s2, NN);
    }

    attn_kernel<1024,4,false><<<(NN*32+255)/256, 256>>>(q2,k2,v2,s2, ea, We2, srcArr, h2);

    // pooling + fingerprint + final (fp32, proven)
    pool_kernel<<<dim3(BB, 4), 256>>>();
    gemm_kernel<<<dim3((BB+127)/128, 256/64), 256>>>(fpb, Wfp, bfp, cc, BB, 256, 2048, 1280, 1024);
    gemm_kernel<<<dim3((BB+127)/128, 1024/64), 256>>>(cc, Wfin, bfin, (float*)d_out, BB, 1024, 1280, 1024, 0);
}

// round 6
// speedup vs baseline: 1.6962x; 1.0712x over previous
#include <cuda_runtime.h>
#include <cuda_fp16.h>
#include <math.h>
#include <stdint.h>

#define NN 24000
#define EE 96000
#define BB 1200
#define NPG 20

// ---------------- device scratch (no allocations allowed) ----------------
__device__ float g_q1[NN*512];
__device__ float g_k1[NN*512];
__device__ float g_v1[NN*512];
__device__ float g_s1[NN*512];
__device__ float g_h1[NN*512];
__device__ float g_ph1[BB*512];
__device__ float g_q2[NN*1024];
__device__ float g_k2[NN*1024];
__device__ float g_v2[NN*1024];
__device__ float g_h2[NN*1024];
__device__ float g_concat[BB*1280];
__device__ int   g_deg[NN];
__device__ int   g_offs[NN+1];
__device__ int   g_cursor[NN];
__device__ int   g_eidx[EE];
// fp16 operands for the f16 tensor-core GEMM
__device__ __half g_h1h[NN*512];
__device__ __half g_w2h[3*1024*512];   // [z][n][k]  (q,k,v transposed, k contiguous)

// ---------------- CSR build ----------------
__global__ void zero_deg_kernel() {
    int i = blockIdx.x*blockDim.x + threadIdx.x;
    if (i < NN) g_deg[i] = 0;
}

__global__ void hist_kernel(const int* __restrict__ dst) {
    int e = blockIdx.x*blockDim.x + threadIdx.x;
    if (e < EE) atomicAdd(&g_deg[dst[e]], 1);
}

__global__ void scan_kernel() {
    __shared__ int wsum[32];
    __shared__ int carry;
    int tid = threadIdx.x;
    int lane = tid & 31, wid = tid >> 5;
    if (tid == 0) carry = 0;
    __syncthreads();
    for (int base = 0; base < NN; base += 1024) {
        int i = base + tid;
        int v = (i < NN) ? g_deg[i] : 0;
        int x = v;
        #pragma unroll
        for (int o = 1; o < 32; o <<= 1) {
            int y = __shfl_up_sync(0xffffffffu, x, o);
            if (lane >= o) x += y;
        }
        if (lane == 31) wsum[wid] = x;
        __syncthreads();
        if (wid == 0) {
            int s = wsum[lane];
            #pragma unroll
            for (int o = 1; o < 32; o <<= 1) {
                int y = __shfl_up_sync(0xffffffffu, s, o);
                if (lane >= o) s += y;
            }
            wsum[lane] = s;
        }
        __syncthreads();
        int pre = (wid > 0 ? wsum[wid-1] : 0) + carry;
        int incl = x + pre;
        if (i < NN) { g_offs[i] = incl - v; g_cursor[i] = incl - v; }
        __syncthreads();
        if (tid == 1023) carry = incl;
        __syncthreads();
    }
    if (tid == 0) g_offs[NN] = carry;
}

__global__ void scatter_kernel(const int* __restrict__ dst) {
    int e = blockIdx.x*blockDim.x + threadIdx.x;
    if (e < EE) {
        int p = atomicAdd(&g_cursor[dst[e]], 1);
        g_eidx[p] = e;
    }
}

__global__ void sort_kernel() {
    int n = blockIdx.x*blockDim.x + threadIdx.x;
    if (n >= NN) return;
    int a = g_offs[n], b = g_offs[n+1];
    for (int i = a+1; i < b; ++i) {
        int key = g_eidx[i];
        int j = i-1;
        while (j >= a && g_eidx[j] > key) { g_eidx[j+1] = g_eidx[j]; --j; }
        g_eidx[j+1] = key;
    }
}

// ---------------- layer-1 projections ----------------
__global__ void proj1_kernel(const float* __restrict__ x,
    const float* __restrict__ Wq, const float* __restrict__ bq,
    const float* __restrict__ Wk, const float* __restrict__ bk,
    const float* __restrict__ Wv, const float* __restrict__ bv,
    const float* __restrict__ Ws, const float* __restrict__ bs)
{
    int warp = (blockIdx.x*blockDim.x + threadIdx.x) >> 5;
    int lane = threadIdx.x & 31;
    if (warp >= NN) return;
    float xr[9];
    #pragma unroll
    for (int t = 0; t < 9; ++t) xr[t] = __ldg(&x[warp*9 + t]);
    for (int j = lane; j < 512; j += 32) {
        float aq = __ldg(&bq[j]), ak = __ldg(&bk[j]);
        float av = __ldg(&bv[j]), as_ = __ldg(&bs[j]);
        #pragma unroll
        for (int t = 0; t < 9; ++t) {
            float xv = xr[t];
            aq  = fmaf(xv, __ldg(&Wq[t*512+j]), aq);
            ak  = fmaf(xv, __ldg(&Wk[t*512+j]), ak);
            av  = fmaf(xv, __ldg(&Wv[t*512+j]), av);
            as_ = fmaf(xv, __ldg(&Ws[t*512+j]), as_);
        }
        size_t o = (size_t)warp*512 + j;
        g_q1[o] = aq; g_k1[o] = ak; g_v1[o] = av; g_s1[o] = as_;
    }
}

// ---------------- attention: one warp per destination node, online softmax ----------------
// SKIP: add root/skip term (layer 1). WRITEH: also emit fp16 copy (feeds tensor GEMM).
template<int D, int H, bool RELU, bool SKIP, bool WRITEH>
__global__ void __launch_bounds__(256) attn_kernel(
    const float* __restrict__ q, const float* __restrict__ k,
    const float* __restrict__ v, const float* __restrict__ s,
    const float* __restrict__ ea, const float* __restrict__ We,
    const int* __restrict__ srcArr, float* __restrict__ out)
{
    constexpr int VPT = D / 32;
    constexpr int NV4 = VPT / 4;
    constexpr int C = D / H;
    __shared__ float sWeT[4*D];
    for (int i = threadIdx.x; i < 4*D; i += blockDim.x) {
        int c = i >> 2, t = i & 3;
        sWeT[i] = __ldg(&We[t*D + c]);
    }
    __syncthreads();

    int warp = (blockIdx.x*blockDim.x + threadIdx.x) >> 5;
    int lane = threadIdx.x & 31;
    if (warp >= NN) return;
    int cbase = lane * VPT;

    float4 qr[NV4], acc[NV4];
    const float4* q4 = (const float4*)(q + (size_t)warp*D + cbase);
    #pragma unroll
    for (int i = 0; i < NV4; ++i) { qr[i] = __ldg(q4 + i); acc[i] = make_float4(0.f,0.f,0.f,0.f); }

    float m = -INFINITY, den = 0.f;
    const float invs = rsqrtf((float)C);
    const float4* sWe4 = (const float4*)sWeT;

    int e0 = g_offs[warp], e1 = g_offs[warp+1];
    for (int t = e0; t < e1; ++t) {
        int e  = __ldg(&g_eidx[t]);
        int sn = __ldg(&srcArr[e]);
        float4 a4 = __ldg((const float4*)ea + e);
        const float4* k4 = (const float4*)(k + (size_t)sn*D + cbase);
        float p = 0.f;
        #pragma unroll
        for (int i = 0; i < NV4; ++i) {
            float4 kk = __ldg(k4 + i);
            int c = cbase + 4*i;
            float4 w0 = sWe4[c+0], w1 = sWe4[c+1], w2 = sWe4[c+2], w3 = sWe4[c+3];
            float ex0 = a4.x*w0.x + a4.y*w0.y + a4.z*w0.z + a4.w*w0.w;
            float ex1 = a4.x*w1.x + a4.y*w1.y + a4.z*w1.z + a4.w*w1.w;
            float ex2 = a4.x*w2.x + a4.y*w2.y + a4.z*w2.z + a4.w*w2.w;
            float ex3 = a4.x*w3.x + a4.y*w3.y + a4.z*w3.z + a4.w*w3.w;
            p += qr[i].x*(kk.x+ex0) + qr[i].y*(kk.y+ex1)
               + qr[i].z*(kk.z+ex2) + qr[i].w*(kk.w+ex3);
        }
        p += __shfl_xor_sync(0xffffffffu, p, 1);
        p += __shfl_xor_sync(0xffffffffu, p, 2);
        p += __shfl_xor_sync(0xffffffffu, p, 4);
        float alpha = p * invs;
        float nm = fmaxf(m, alpha);
        float sc = __expf(m - nm);
        float w  = __expf(alpha - nm);
        den = den*sc + w;
        m = nm;
        const float4* v4 = (const float4*)(v + (size_t)sn*D + cbase);
        #pragma unroll
        for (int i = 0; i < NV4; ++i) {
            float4 vv = __ldg(v4 + i);
            int c = cbase + 4*i;
            float4 w0 = sWe4[c+0], w1 = sWe4[c+1], w2 = sWe4[c+2], w3 = sWe4[c+3];
            float ex0 = a4.x*w0.x + a4.y*w0.y + a4.z*w0.z + a4.w*w0.w;
            float ex1 = a4.x*w1.x + a4.y*w1.y + a4.z*w1.z + a4.w*w1.w;
            float ex2 = a4.x*w2.x + a4.y*w2.y + a4.z*w2.z + a4.w*w2.w;
            float ex3 = a4.x*w3.x + a4.y*w3.y + a4.z*w3.z + a4.w*w3.w;
            acc[i].x = acc[i].x*sc + w*(vv.x+ex0);
            acc[i].y = acc[i].y*sc + w*(vv.y+ex1);
            acc[i].z = acc[i].z*sc + w*(vv.z+ex2);
            acc[i].w = acc[i].w*sc + w*(vv.w+ex3);
        }
    }
    float r = 1.f / (den + 1e-16f);
    const float4* s4 = (const float4*)(s + (size_t)warp*D + cbase);
    float4* o4 = (float4*)(out + (size_t)warp*D + cbase);
    __half2* h4 = (__half2*)(g_h1h + (size_t)warp*D + cbase);
    #pragma unroll
    for (int i = 0; i < NV4; ++i) {
        float4 o;
        o.x = acc[i].x*r; o.y = acc[i].y*r;
        o.z = acc[i].z*r; o.w = acc[i].w*r;
        if (SKIP) {
            float4 sv = __ldg(s4 + i);
            o.x += sv.x; o.y += sv.y; o.z += sv.z; o.w += sv.w;
        }
        if (RELU) {
            o.x = fmaxf(o.x, 0.f); o.y = fmaxf(o.y, 0.f);
            o.z = fmaxf(o.z, 0.f); o.w = fmaxf(o.w, 0.f);
        }
        o4[i] = o;
        if (WRITEH) {
            h4[2*i]   = __floats2half2_rn(o.x, o.y);
            h4[2*i+1] = __floats2half2_rn(o.z, o.w);
        }
    }
}

// ---------------- weight transpose+fp16 convert: Wt[z][n][k] = (half)W_z[k][n] --------------
__global__ void wt2half_kernel(const float* __restrict__ W0, const float* __restrict__ W1,
                               const float* __restrict__ W2) {
    __shared__ float tile[32][33];
    int z = blockIdx.z;
    const float* W = (z==0) ? W0 : (z==1) ? W1 : W2;
    int n0 = blockIdx.x * 32, k0 = blockIdx.y * 32;
    int tx = threadIdx.x, ty = threadIdx.y;
    tile[ty][tx] = __ldg(&W[(size_t)(k0+ty)*1024 + n0 + tx]);
    __syncthreads();
    g_w2h[(size_t)z*1024*512 + (size_t)(n0+ty)*512 + k0 + tx] = __float2half_rn(tile[tx][ty]);
}

// ---------------- f16 tensor-core GEMM (m16n8k16 + ldmatrix) ----------------
// C_z[M,1024] = A[M,512] @ W_z^T + bias_z for z in {q,k,v}.
// BM=BN=128, BK=32, 256 threads (8 warps 2x4), register-prefetch double buffering.
__global__ void __launch_bounds__(256) gemm3_f16_kernel(
    const __half* __restrict__ Ah,
    const float* __restrict__ b0, const float* __restrict__ b1,
    const float* __restrict__ b2,
    float* C0, float* C1, float* C2, int M)
{
    __shared__ uint32_t As[2][128][20];   // [buf][m][k-pair], stride 20 -> conflict-free
    __shared__ uint32_t Bs[2][128][20];   // [buf][n][k-pair]

    int z = blockIdx.z;
    const __half* Bz  = g_w2h + (size_t)z*1024*512;
    const float* bias = (z==0) ? b0 : (z==1) ? b1 : b2;
    float*       C    = (z==0) ? C0 : (z==1) ? C1 : C2;

    int tid  = threadIdx.x;
    int lane = tid & 31, wid = tid >> 5;
    int wm = wid >> 2, wn = wid & 3;
    int m0 = blockIdx.x * 128, n0 = blockIdx.y * 128;
    int g = lane >> 2, t = lane & 3;

    // ldmatrix per-lane source coords: 16-row block, row = l&7 + ((l>>3)&1)*8, kquad = (l>>4)*4
    int lrow  = (lane & 7) + ((lane >> 3) & 1) * 8;
    int lkq   = (lane >> 4) * 4;

    // gmem load coords: 2 float4 (8 halves) per thread per operand per tile
    int lm[2], lq[2];
    #pragma unroll
    for (int i = 0; i < 2; ++i) {
        int idx = tid + i*256;
        lm[i] = idx >> 2;
        lq[i] = (idx & 3) * 8;
    }

    float acc[4][4][4];
    #pragma unroll
    for (int a = 0; a < 4; ++a)
        #pragma unroll
        for (int b = 0; b < 4; ++b)
            #pragma unroll
            for (int c = 0; c < 4; ++c) acc[a][b][c] = 0.f;

    float4 pa[2], pb[2];
    const int T = 512 / 32;

    #pragma unroll
    for (int i = 0; i < 2; ++i) {
        pa[i] = (m0 + lm[i] < M)
              ? *(const float4*)(Ah + (size_t)(m0+lm[i])*512 + lq[i])
              : make_float4(0.f,0.f,0.f,0.f);
        pb[i] = *(const float4*)(Bz + (size_t)(n0+lm[i])*512 + lq[i]);
    }
    #pragma unroll
    for (int i = 0; i < 2; ++i) {
        *(float4*)&As[0][lm[i]][lq[i]>>1] = pa[i];
        *(float4*)&Bs[0][lm[i]][lq[i]>>1] = pb[i];
    }
    __syncthreads();

    for (int kt = 0; kt < T; ++kt) {
        int b = kt & 1;
        if (kt + 1 < T) {
            int ko = (kt+1) * 32;
            #pragma unroll
            for (int i = 0; i < 2; ++i) {
                pa[i] = (m0 + lm[i] < M)
                      ? *(const float4*)(Ah + (size_t)(m0+lm[i])*512 + ko + lq[i])
                      : make_float4(0.f,0.f,0.f,0.f);
                pb[i] = *(const float4*)(Bz + (size_t)(n0+lm[i])*512 + ko + lq[i]);
            }
        }

        #pragma unroll
        for (int ks = 0; ks < 2; ++ks) {
            int kb = ks * 8;
            uint32_t af[4][4], bf[4][2];
            #pragma unroll
            for (int mt = 0; mt < 4; ++mt) {
                int mb = wm*64 + mt*16;
                uint32_t addr = (uint32_t)__cvta_generic_to_shared(
                    &As[b][mb + lrow][kb + lkq]);
                asm volatile("ldmatrix.sync.aligned.m8n8.x4.shared.b16 {%0,%1,%2,%3}, [%4];"
                    : "=r"(af[mt][0]), "=r"(af[mt][1]), "=r"(af[mt][2]), "=r"(af[mt][3])
                    : "r"(addr));
            }
            #pragma unroll
            for (int p = 0; p < 2; ++p) {
                int nb = wn*32 + p*16;
                uint32_t addr = (uint32_t)__cvta_generic_to_shared(
                    &Bs[b][nb + lrow][kb + lkq]);
                uint32_t r0, r1, r2, r3;
                asm volatile("ldmatrix.sync.aligned.m8n8.x4.shared.b16 {%0,%1,%2,%3}, [%4];"
                    : "=r"(r0), "=r"(r1), "=r"(r2), "=r"(r3)
                    : "r"(addr));
                bf[2*p  ][0] = r0; bf[2*p+1][0] = r1;
                bf[2*p  ][1] = r2; bf[2*p+1][1] = r3;
            }
            #pragma unroll
            for (int mt = 0; mt < 4; ++mt)
                #pragma unroll
                for (int nt = 0; nt < 4; ++nt) {
                    asm volatile(
                        "mma.sync.aligned.m16n8k16.row.col.f32.f16.f16.f32 "
                        "{%0,%1,%2,%3}, {%4,%5,%6,%7}, {%8,%9}, {%0,%1,%2,%3};"
                        : "+f"(acc[mt][nt][0]), "+f"(acc[mt][nt][1]),
                          "+f"(acc[mt][nt][2]), "+f"(acc[mt][nt][3])
                        : "r"(af[mt][0]), "r"(af[mt][1]), "r"(af[mt][2]), "r"(af[mt][3]),
                          "r"(bf[nt][0]), "r"(bf[nt][1]));
                }
        }

        if (kt + 1 < T) {
            int nb_ = b ^ 1;
            #pragma unroll
            for (int i = 0; i < 2; ++i) {
                *(float4*)&As[nb_][lm[i]][lq[i]>>1] = pa[i];
                *(float4*)&Bs[nb_][lm[i]][lq[i]>>1] = pb[i];
            }
            __syncthreads();
        }
    }

    #pragma unroll
    for (int mt = 0; mt < 4; ++mt) {
        int r0 = m0 + wm*64 + mt*16 + g;
        #pragma unroll
        for (int nt = 0; nt < 4; ++nt) {
            int c = n0 + wn*32 + nt*8 + t*2;
            float bv0 = __ldg(&bias[c]), bv1 = __ldg(&bias[c+1]);
            if (r0 < M) {
                float2 o = make_float2(acc[mt][nt][0] + bv0, acc[mt][nt][1] + bv1);
                *(float2*)&C[(size_t)r0*1024 + c] = o;
            }
            if (r0 + 8 < M) {
                float2 o = make_float2(acc[mt][nt][2] + bv0, acc[mt][nt][3] + bv1);
                *(float2*)&C[(size_t)(r0+8)*1024 + c] = o;
            }
        }
    }
}

// ---------------- fp32 tiled GEMM (tail GEMMs; optional accumulate into C) ----------------
__global__ void __launch_bounds__(256) gemm_kernel(
    const float* __restrict__ A, const float* __restrict__ Bm,
    const float* __restrict__ bias, float* __restrict__ C,
    int M, int N, int K, int ldc, int coff, int accum)
{
    __shared__ float As[16][128+4];
    __shared__ float Bs[16][64+4];
    int tid = threadIdx.x;
    int tx = tid & 15, ty = tid >> 4;
    int m0 = blockIdx.x * 128;
    int n0 = blockIdx.y * 64;
    float acc[8][4] = {};

    for (int k0 = 0; k0 < K; k0 += 16) {
        #pragma unroll
        for (int it = 0; it < 2; ++it) {
            int f = tid + it*256;
            int row = f >> 2;
            int c4 = (f & 3) * 4;
            float4 val = make_float4(0.f,0.f,0.f,0.f);
            if (m0 + row < M)
                val = __ldg((const float4*)&A[(size_t)(m0+row)*K + k0 + c4]);
            As[c4+0][row] = val.x; As[c4+1][row] = val.y;
            As[c4+2][row] = val.z; As[c4+3][row] = val.w;
        }
        {
            int r  = tid >> 4;
            int c4 = (tid & 15) * 4;
            float4 val = __ldg((const float4*)&Bm[(size_t)(k0+r)*N + n0 + c4]);
            *(float4*)&Bs[r][c4] = val;
        }
        __syncthreads();
        #pragma unroll
        for (int kk = 0; kk < 16; ++kk) {
            float a[8], b[4];
            *(float4*)&a[0] = *(const float4*)&As[kk][ty*8];
            *(float4*)&a[4] = *(const float4*)&As[kk][ty*8+4];
            *(float4*)&b[0] = *(const float4*)&Bs[kk][tx*4];
            #pragma unroll
            for (int i = 0; i < 8; ++i)
                #pragma unroll
                for (int j = 0; j < 4; ++j)
                    acc[i][j] = fmaf(a[i], b[j], acc[i][j]);
        }
        __syncthreads();
    }
    #pragma unroll
    for (int i = 0; i < 8; ++i) {
        int row = m0 + ty*8 + i;
        if (row < M) {
            #pragma unroll
            for (int j = 0; j < 4; ++j) {
                int col = n0 + tx*4 + j;
                float prev = accum ? C[(size_t)row*ldc + coff + col] : 0.f;
                C[(size_t)row*ldc + coff + col] = acc[i][j] + __ldg(&bias[col]) + prev;
            }
        }
    }
}

// ---------------- mean pools ----------------
__global__ void pool_kernel() {   // g_h2 (attn-only) -> concat[:, :1024]
    int c = blockIdx.y*blockDim.x + threadIdx.x;
    int b = blockIdx.x;
    float sum = 0.f;
    #pragma unroll
    for (int i = 0; i < NPG; ++i)
        sum += g_h2[(size_t)(b*NPG + i)*1024 + c];
    g_concat[b*1280 + c] = sum * (1.f/NPG);
}

__global__ void poolh1_kernel() {  // g_h1 -> g_ph1 [BB,512]
    int c = blockIdx.y*blockDim.x + threadIdx.x;
    int b = blockIdx.x;
    float sum = 0.f;
    #pragma unroll
    for (int i = 0; i < NPG; ++i)
        sum += g_h1[(size_t)(b*NPG + i)*512 + c];
    g_ph1[b*512 + c] = sum * (1.f/NPG);
}

// ---------------- launch ----------------
extern "C" void kernel_launch(void* const* d_in, const int* in_sizes, int n_in,
                              void* d_out, int out_size)
{
    const float* x    = (const float*)d_in[0];
    const int*   ei   = (const int*)  d_in[1];
    const float* ea   = (const float*)d_in[2];
    const float* fpb  = (const float*)d_in[4];
    const float *Wq1=(const float*)d_in[5],  *bq1=(const float*)d_in[6];
    const float *Wk1=(const float*)d_in[7],  *bk1=(const float*)d_in[8];
    const float *Wv1=(const float*)d_in[9],  *bv1=(const float*)d_in[10];
    const float *We1=(const float*)d_in[11];
    const float *Ws1=(const float*)d_in[12], *bs1=(const float*)d_in[13];
    const float *Wq2=(const float*)d_in[14], *bq2=(const float*)d_in[15];
    const float *Wk2=(const float*)d_in[16], *bk2=(const float*)d_in[17];
    const float *Wv2=(const float*)d_in[18], *bv2=(const float*)d_in[19];
    const float *We2=(const float*)d_in[20];
    const float *Ws2=(const float*)d_in[21], *bs2=(const float*)d_in[22];
    const float *Wfp=(const float*)d_in[23], *bfp=(const float*)d_in[24];
    const float *Wfin=(const float*)d_in[25],*bfin=(const float*)d_in[26];

    const int* srcArr = ei;
    const int* dstArr = ei + EE;

    float *q1,*k1,*v1,*s1,*h1,*ph1,*q2,*k2,*v2,*h2,*cc;
    __half *h1h;
    cudaGetSymbolAddress((void**)&q1, g_q1);
    cudaGetSymbolAddress((void**)&k1, g_k1);
    cudaGetSymbolAddress((void**)&v1, g_v1);
    cudaGetSymbolAddress((void**)&s1, g_s1);
    cudaGetSymbolAddress((void**)&h1, g_h1);
    cudaGetSymbolAddress((void**)&ph1, g_ph1);
    cudaGetSymbolAddress((void**)&q2, g_q2);
    cudaGetSymbolAddress((void**)&k2, g_k2);
    cudaGetSymbolAddress((void**)&v2, g_v2);
    cudaGetSymbolAddress((void**)&h2, g_h2);
    cudaGetSymbolAddress((void**)&cc, g_concat);
    cudaGetSymbolAddress((void**)&h1h, g_h1h);

    // CSR build
    zero_deg_kernel<<<(NN+255)/256, 256>>>();
    hist_kernel<<<(EE+255)/256, 256>>>(dstArr);
    scan_kernel<<<1, 1024>>>();
    scatter_kernel<<<(EE+255)/256, 256>>>(dstArr);
    sort_kernel<<<(NN+255)/256, 256>>>();

    // weight transpose + fp16 convert for q2,k2,v2 (independent of layer 1)
    wt2half_kernel<<<dim3(32, 16, 3), dim3(32, 32)>>>(Wq2, Wk2, Wv2);

    // layer 1 (attn writes h1 in fp32 AND fp16)
    proj1_kernel<<<(NN*32+255)/256, 256>>>(x, Wq1,bq1, Wk1,bk1, Wv1,bv1, Ws1,bs1);
    attn_kernel<512,4,true,true,true><<<(NN*32+255)/256, 256>>>(
        q1,k1,v1,s1, ea, We1, srcArr, h1);

    // layer-2 q/k/v projections on tensor cores (skip projection moved post-pool)
    {
        dim3 grid((NN+127)/128, 1024/128, 3);
        gemm3_f16_kernel<<<grid, 256>>>(h1h, bq2, bk2, bv2, q2, k2, v2, NN);
    }

    // layer-2 attention WITHOUT skip (h2 = message part only)
    attn_kernel<1024,4,false,false,false><<<(NN*32+255)/256, 256>>>(
        q2,k2,v2,q2, ea, We2, srcArr, h2);

    // pooled outputs: concat[:, :1024] = pool(h2) + pool(h1) @ Ws2 + bs2
    pool_kernel<<<dim3(BB, 4), 256>>>();
    poolh1_kernel<<<dim3(BB, 2), 256>>>();
    gemm_kernel<<<dim3((BB+127)/128, 1024/64), 256>>>(ph1, Ws2, bs2, cc,
        BB, 1024, 512, 1280, 0, 1);

    // fingerprint + final (fp32)
    gemm_kernel<<<dim3((BB+127)/128, 256/64), 256>>>(fpb, Wfp, bfp, cc,
        BB, 256, 2048, 1280, 1024, 0);
    gemm_kernel<<<dim3((BB+127)/128, 1024/64), 256>>>(cc, Wfin, bfin, (float*)d_out,
        BB, 1024, 1280, 1024, 0, 0);
}

// round 7
// speedup vs baseline: 2.0919x; 1.2332x over previous
#include <cuda_runtime.h>
#include <cuda_fp16.h>
#include <math.h>
#include <stdint.h>

#define NN 24000
#define EE 96000
#define BB 1200
#define NPG 20

// ---------------- device scratch (no allocations allowed) ----------------
__device__ float  g_q1[NN*512];
__device__ float  g_s1[NN*512];
__device__ __half g_k1h[NN*512];
__device__ __half g_v1h[NN*512];
__device__ __half g_h1h[NN*512];
__device__ float  g_ph1[BB*512];
__device__ float  g_q2[NN*1024];
__device__ __half g_k2h[NN*1024];
__device__ __half g_v2h[NN*1024];
__device__ float  g_concat[BB*1280];
__device__ int    g_deg[NN];
__device__ int    g_offs[NN+1];
__device__ int    g_cursor[NN];
__device__ int    g_eidx[EE];
__device__ __half g_w2h[3*1024*512];   // [z][n][k]  (q,k,v transposed, k contiguous)

// ---------------- CSR build ----------------
__global__ void zero_deg_kernel() {
    int i = blockIdx.x*blockDim.x + threadIdx.x;
    if (i < NN) g_deg[i] = 0;
}

__global__ void hist_kernel(const int* __restrict__ dst) {
    int e = blockIdx.x*blockDim.x + threadIdx.x;
    if (e < EE) atomicAdd(&g_deg[dst[e]], 1);
}

__global__ void scan_kernel() {
    __shared__ int wsum[32];
    __shared__ int carry;
    int tid = threadIdx.x;
    int lane = tid & 31, wid = tid >> 5;
    if (tid == 0) carry = 0;
    __syncthreads();
    for (int base = 0; base < NN; base += 1024) {
        int i = base + tid;
        int v = (i < NN) ? g_deg[i] : 0;
        int x = v;
        #pragma unroll
        for (int o = 1; o < 32; o <<= 1) {
            int y = __shfl_up_sync(0xffffffffu, x, o);
            if (lane >= o) x += y;
        }
        if (lane == 31) wsum[wid] = x;
        __syncthreads();
        if (wid == 0) {
            int s = wsum[lane];
            #pragma unroll
            for (int o = 1; o < 32; o <<= 1) {
                int y = __shfl_up_sync(0xffffffffu, s, o);
                if (lane >= o) s += y;
            }
            wsum[lane] = s;
        }
        __syncthreads();
        int pre = (wid > 0 ? wsum[wid-1] : 0) + carry;
        int incl = x + pre;
        if (i < NN) { g_offs[i] = incl - v; g_cursor[i] = incl - v; }
        __syncthreads();
        if (tid == 1023) carry = incl;
        __syncthreads();
    }
    if (tid == 0) g_offs[NN] = carry;
}

__global__ void scatter_kernel(const int* __restrict__ dst) {
    int e = blockIdx.x*blockDim.x + threadIdx.x;
    if (e < EE) {
        int p = atomicAdd(&g_cursor[dst[e]], 1);
        g_eidx[p] = e;
    }
}

__global__ void sort_kernel() {
    int n = blockIdx.x*blockDim.x + threadIdx.x;
    if (n >= NN) return;
    int a = g_offs[n], b = g_offs[n+1];
    for (int i = a+1; i < b; ++i) {
        int key = g_eidx[i];
        int j = i-1;
        while (j >= a && g_eidx[j] > key) { g_eidx[j+1] = g_eidx[j]; --j; }
        g_eidx[j+1] = key;
    }
}

// ---------------- layer-1 projections: q,s fp32; k,v fp16 ----------------
__global__ void proj1_kernel(const float* __restrict__ x,
    const float* __restrict__ Wq, const float* __restrict__ bq,
    const float* __restrict__ Wk, const float* __restrict__ bk,
    const float* __restrict__ Wv, const float* __restrict__ bv,
    const float* __restrict__ Ws, const float* __restrict__ bs)
{
    int warp = (blockIdx.x*blockDim.x + threadIdx.x) >> 5;
    int lane = threadIdx.x & 31;
    if (warp >= NN) return;
    float xr[9];
    #pragma unroll
    for (int t = 0; t < 9; ++t) xr[t] = __ldg(&x[warp*9 + t]);
    for (int j = lane; j < 512; j += 32) {
        float aq = __ldg(&bq[j]), ak = __ldg(&bk[j]);
        float av = __ldg(&bv[j]), as_ = __ldg(&bs[j]);
        #pragma unroll
        for (int t = 0; t < 9; ++t) {
            float xv = xr[t];
            aq  = fmaf(xv, __ldg(&Wq[t*512+j]), aq);
            ak  = fmaf(xv, __ldg(&Wk[t*512+j]), ak);
            av  = fmaf(xv, __ldg(&Wv[t*512+j]), av);
            as_ = fmaf(xv, __ldg(&Ws[t*512+j]), as_);
        }
        size_t o = (size_t)warp*512 + j;
        g_q1[o] = aq; g_s1[o] = as_;
        g_k1h[o] = __float2half_rn(ak);
        g_v1h[o] = __float2half_rn(av);
    }
}

// ---------------- per-graph attention (one block per graph, 20 warps) ----------------
// Edge-feature algebra: dot_h(q,e) = qe_h . a4 ;  sum_e w(v+e) = acc + We^T wa.
// L1: out = relu(msg + skip) -> h1h fp16 per node, pooled -> outPooled.
// else: pooled(msg) -> outPooled (row stride ldOut).
template<int D, int H, bool L1>
__global__ void __launch_bounds__(640, 1) attn_graph_kernel(
    const float* __restrict__ q, const __half* __restrict__ khg,
    const __half* __restrict__ vhg, const float* __restrict__ s,
    const float* __restrict__ ea, const float* __restrict__ We,
    const int* __restrict__ srcArr, float* __restrict__ outPooled,
    __half* __restrict__ h1h, int ldOut)
{
    constexpr int VPT = D / 32;          // channels per lane
    constexpr int NU = VPT / 8;          // uint4 (8 halves) per lane row chunk
    constexpr int C = D / H;
    extern __shared__ char smraw[];
    float*  sWeT = (float*)smraw;                       // [D][4]
    __half* kh   = (__half*)(smraw + 16*D);             // [20][D]
    __half* vh   = (__half*)(smraw + 16*D + 40*D);      // [20][D]
    float*  poolbuf = (float*)kh;                       // overlay [20][D]

    int tid = threadIdx.x;
    int wid = tid >> 5, lane = tid & 31;
    int graph = blockIdx.x;
    int gbase = graph * NPG;

    for (int i = tid; i < 4*D; i += 640) {
        int c = i >> 2, t = i & 3;
        sWeT[i] = __ldg(&We[t*D + c]);
    }
    {   // stage k/v for the 20 nodes: contiguous block copy
        const uint4* ks = (const uint4*)(khg + (size_t)gbase*D);
        const uint4* vs = (const uint4*)(vhg + (size_t)gbase*D);
        uint4* kd = (uint4*)kh;
        uint4* vd = (uint4*)vh;
        for (int i = tid; i < NPG*D/8; i += 640) { kd[i] = __ldg(ks+i); vd[i] = __ldg(vs+i); }
    }
    __syncthreads();

    int node = gbase + wid;
    int cbase = lane * VPT;
    const float4* sWe4 = (const float4*)sWeT;

    float qrf[VPT], accf[VPT];
    {
        const float4* q4 = (const float4*)(q + (size_t)node*D + cbase);
        #pragma unroll
        for (int i = 0; i < VPT/4; ++i) *(float4*)&qrf[4*i] = __ldg(q4 + i);
    }
    #pragma unroll
    for (int i = 0; i < VPT; ++i) accf[i] = 0.f;

    // qe_h = sum_{c in lane} q_c * We[:,c], reduced over the 8 lanes of the head
    float4 qe = make_float4(0.f,0.f,0.f,0.f);
    #pragma unroll
    for (int i = 0; i < VPT; ++i) {
        float4 w = sWe4[cbase + i];
        qe.x = fmaf(qrf[i], w.x, qe.x);
        qe.y = fmaf(qrf[i], w.y, qe.y);
        qe.z = fmaf(qrf[i], w.z, qe.z);
        qe.w = fmaf(qrf[i], w.w, qe.w);
    }
    #pragma unroll
    for (int o = 1; o < 8; o <<= 1) {
        qe.x += __shfl_xor_sync(0xffffffffu, qe.x, o);
        qe.y += __shfl_xor_sync(0xffffffffu, qe.y, o);
        qe.z += __shfl_xor_sync(0xffffffffu, qe.z, o);
        qe.w += __shfl_xor_sync(0xffffffffu, qe.w, o);
    }

    float m = -INFINITY, den = 0.f;
    float4 wa = make_float4(0.f,0.f,0.f,0.f);
    const float invs = rsqrtf((float)C);

    int e0 = g_offs[node], e1 = g_offs[node+1];
    for (int t = e0; t < e1; ++t) {
        int e  = __ldg(&g_eidx[t]);
        int ln = __ldg(&srcArr[e]) - gbase;
        float4 a4 = __ldg((const float4*)ea + e);

        const uint4* krow = (const uint4*)(kh + ln*D + cbase);
        float p = 0.f;
        #pragma unroll
        for (int i = 0; i < NU; ++i) {
            uint4 u = krow[i];
            const __half2* h2 = (const __half2*)&u;
            #pragma unroll
            for (int j = 0; j < 4; ++j) {
                float2 f = __half22float2(h2[j]);
                p = fmaf(qrf[8*i+2*j], f.x, p);
                p = fmaf(qrf[8*i+2*j+1], f.y, p);
            }
        }
        p += __shfl_xor_sync(0xffffffffu, p, 1);
        p += __shfl_xor_sync(0xffffffffu, p, 2);
        p += __shfl_xor_sync(0xffffffffu, p, 4);
        float alpha = (p + qe.x*a4.x + qe.y*a4.y + qe.z*a4.z + qe.w*a4.w) * invs;

        float nm = fmaxf(m, alpha);
        float sc = __expf(m - nm);
        float w  = __expf(alpha - nm);
        den = den*sc + w;
        m = nm;

        const uint4* vrow = (const uint4*)(vh + ln*D + cbase);
        #pragma unroll
        for (int i = 0; i < NU; ++i) {
            uint4 u = vrow[i];
            const __half2* h2 = (const __half2*)&u;
            #pragma unroll
            for (int j = 0; j < 4; ++j) {
                float2 f = __half22float2(h2[j]);
                accf[8*i+2*j]   = fmaf(accf[8*i+2*j],   sc, 0.f) + w*f.x;
                accf[8*i+2*j+1] = fmaf(accf[8*i+2*j+1], sc, 0.f) + w*f.y;
            }
        }
        wa.x = wa.x*sc + w*a4.x; wa.y = wa.y*sc + w*a4.y;
        wa.z = wa.z*sc + w*a4.z; wa.w = wa.w*sc + w*a4.w;
    }

    // finish msg in registers
    float r = 1.f / (den + 1e-16f);
    float outv[VPT];
    #pragma unroll
    for (int i = 0; i < VPT; ++i) {
        float4 w = sWe4[cbase + i];
        float msg = (accf[i] + wa.x*w.x + wa.y*w.y + wa.z*w.z + wa.w*w.w) * r;
        if (L1) {
            msg += __ldg(&s[(size_t)node*D + cbase + i]);
            msg = fmaxf(msg, 0.f);
        }
        outv[i] = msg;
    }
    if (L1) {
        __half2* h4 = (__half2*)(h1h + (size_t)node*D + cbase);
        #pragma unroll
        for (int i = 0; i < VPT/2; ++i)
            h4[i] = __floats2half2_rn(outv[2*i], outv[2*i+1]);
    }

    // pooled output (deterministic): stash rows into smem overlay, tree-sum
    __syncthreads();   // all warps done reading kh/vh
    #pragma unroll
    for (int i = 0; i < VPT; ++i) poolbuf[wid*D + cbase + i] = outv[i];
    __syncthreads();
    for (int c = tid; c < D; c += 640) {
        float sum = 0.f;
        #pragma unroll
        for (int i = 0; i < NPG; ++i) sum += poolbuf[i*D + c];
        outPooled[(size_t)graph*ldOut + c] = sum * (1.f/NPG);
    }
}

// ---------------- weight transpose+fp16 convert: Wt[z][n][k] = (half)W_z[k][n] --------------
__global__ void wt2half_kernel(const float* __restrict__ W0, const float* __restrict__ W1,
                               const float* __restrict__ W2) {
    __shared__ float tile[32][33];
    int z = blockIdx.z;
    const float* W = (z==0) ? W0 : (z==1) ? W1 : W2;
    int n0 = blockIdx.x * 32, k0 = blockIdx.y * 32;
    int tx = threadIdx.x, ty = threadIdx.y;
    tile[ty][tx] = __ldg(&W[(size_t)(k0+ty)*1024 + n0 + tx]);
    __syncthreads();
    g_w2h[(size_t)z*1024*512 + (size_t)(n0+ty)*512 + k0 + tx] = __float2half_rn(tile[tx][ty]);
}

// ---------------- f16 tensor-core GEMM (m16n8k16, R5-proven LDS fragment loads) ----------
// z=0 -> q2 fp32; z=1 -> g_k2h fp16; z=2 -> g_v2h fp16.
__global__ void __launch_bounds__(256) gemm3_f16_kernel(
    const __half* __restrict__ Ah,
    const float* __restrict__ b0, const float* __restrict__ b1,
    const float* __restrict__ b2,
    float* C0, int M)
{
    __shared__ uint32_t As[2][128][20];
    __shared__ uint32_t Bs[2][128][20];

    int z = blockIdx.z;
    const __half* Bz  = g_w2h + (size_t)z*1024*512;
    const float* bias = (z==0) ? b0 : (z==1) ? b1 : b2;
    __half* Ch = (z==1) ? g_k2h : g_v2h;

    int tid  = threadIdx.x;
    int lane = tid & 31, wid = tid >> 5;
    int wm = wid >> 2, wn = wid & 3;
    int m0 = blockIdx.x * 128, n0 = blockIdx.y * 128;
    int g = lane >> 2, t = lane & 3;

    int lm[2], lq[2];
    #pragma unroll
    for (int i = 0; i < 2; ++i) {
        int idx = tid + i*256;
        lm[i] = idx >> 2;
        lq[i] = (idx & 3) * 8;
    }

    float acc[4][4][4];
    #pragma unroll
    for (int a = 0; a < 4; ++a)
        #pragma unroll
        for (int b = 0; b < 4; ++b)
            #pragma unroll
            for (int c = 0; c < 4; ++c) acc[a][b][c] = 0.f;

    float4 pa[2], pb[2];
    const int T = 512 / 32;

    #pragma unroll
    for (int i = 0; i < 2; ++i) {
        pa[i] = (m0 + lm[i] < M)
              ? *(const float4*)(Ah + (size_t)(m0+lm[i])*512 + lq[i])
              : make_float4(0.f,0.f,0.f,0.f);
        pb[i] = *(const float4*)(Bz + (size_t)(n0+lm[i])*512 + lq[i]);
    }
    #pragma unroll
    for (int i = 0; i < 2; ++i) {
        *(float4*)&As[0][lm[i]][lq[i]>>1] = pa[i];
        *(float4*)&Bs[0][lm[i]][lq[i]>>1] = pb[i];
    }
    __syncthreads();

    for (int kt = 0; kt < T; ++kt) {
        int b = kt & 1;
        if (kt + 1 < T) {
            int ko = (kt+1) * 32;
            #pragma unroll
            for (int i = 0; i < 2; ++i) {
                pa[i] = (m0 + lm[i] < M)
                      ? *(const float4*)(Ah + (size_t)(m0+lm[i])*512 + ko + lq[i])
                      : make_float4(0.f,0.f,0.f,0.f);
                pb[i] = *(const float4*)(Bz + (size_t)(n0+lm[i])*512 + ko + lq[i]);
            }
        }

        #pragma unroll
        for (int ks = 0; ks < 2; ++ks) {
            int kb = ks * 8;
            uint32_t af[4][4], bf[4][2];
            #pragma unroll
            for (int mt = 0; mt < 4; ++mt) {
                int mb = wm*64 + mt*16;
                af[mt][0] = As[b][mb+g  ][kb+t  ];
                af[mt][1] = As[b][mb+g+8][kb+t  ];
                af[mt][2] = As[b][mb+g  ][kb+t+4];
                af[mt][3] = As[b][mb+g+8][kb+t+4];
            }
            #pragma unroll
            for (int nt = 0; nt < 4; ++nt) {
                int nb = wn*32 + nt*8;
                bf[nt][0] = Bs[b][nb+g][kb+t  ];
                bf[nt][1] = Bs[b][nb+g][kb+t+4];
            }
            #pragma unroll
            for (int mt = 0; mt < 4; ++mt)
                #pragma unroll
                for (int nt = 0; nt < 4; ++nt) {
                    asm volatile(
                        "mma.sync.aligned.m16n8k16.row.col.f32.f16.f16.f32 "
                        "{%0,%1,%2,%3}, {%4,%5,%6,%7}, {%8,%9}, {%0,%1,%2,%3};"
                        : "+f"(acc[mt][nt][0]), "+f"(acc[mt][nt][1]),
                          "+f"(acc[mt][nt][2]), "+f"(acc[mt][nt][3])
                        : "r"(af[mt][0]), "r"(af[mt][1]), "r"(af[mt][2]), "r"(af[mt][3]),
                          "r"(bf[nt][0]), "r"(bf[nt][1]));
                }
        }

        if (kt + 1 < T) {
            int nb_ = b ^ 1;
            #pragma unroll
            for (int i = 0; i < 2; ++i) {
                *(float4*)&As[nb_][lm[i]][lq[i]>>1] = pa[i];
                *(float4*)&Bs[nb_][lm[i]][lq[i]>>1] = pb[i];
            }
            __syncthreads();
        }
    }

    #pragma unroll
    for (int mt = 0; mt < 4; ++mt) {
        int r0 = m0 + wm*64 + mt*16 + g;
        #pragma unroll
        for (int nt = 0; nt < 4; ++nt) {
            int c = n0 + wn*32 + nt*8 + t*2;
            float bv0 = __ldg(&bias[c]), bv1 = __ldg(&bias[c+1]);
            float o00 = acc[mt][nt][0] + bv0, o01 = acc[mt][nt][1] + bv1;
            float o10 = acc[mt][nt][2] + bv0, o11 = acc[mt][nt][3] + bv1;
            if (z == 0) {
                if (r0 < M)     *(float2*)&C0[(size_t)r0*1024 + c]     = make_float2(o00, o01);
                if (r0 + 8 < M) *(float2*)&C0[(size_t)(r0+8)*1024 + c] = make_float2(o10, o11);
            } else {
                if (r0 < M)     *(__half2*)&Ch[(size_t)r0*1024 + c]     = __floats2half2_rn(o00, o01);
                if (r0 + 8 < M) *(__half2*)&Ch[(size_t)(r0+8)*1024 + c] = __floats2half2_rn(o10, o11);
            }
        }
    }
}

// ---------------- fp32 tiled GEMM (tail GEMMs; optional accumulate) ----------------
__global__ void __launch_bounds__(256) gemm_kernel(
    const float* __restrict__ A, const float* __restrict__ Bm,
    const float* __restrict__ bias, float* __restrict__ C,
    int M, int N, int K, int ldc, int coff, int accum)
{
    __shared__ float As[16][128+4];
    __shared__ float Bs[16][64+4];
    int tid = threadIdx.x;
    int tx = tid & 15, ty = tid >> 4;
    int m0 = blockIdx.x * 128;
    int n0 = blockIdx.y * 64;
    float acc[8][4] = {};

    for (int k0 = 0; k0 < K; k0 += 16) {
        #pragma unroll
        for (int it = 0; it < 2; ++it) {
            int f = tid + it*256;
            int row = f >> 2;
            int c4 = (f & 3) * 4;
            float4 val = make_float4(0.f,0.f,0.f,0.f);
            if (m0 + row < M)
                val = __ldg((const float4*)&A[(size_t)(m0+row)*K + k0 + c4]);
            As[c4+0][row] = val.x; As[c4+1][row] = val.y;
            As[c4+2][row] = val.z; As[c4+3][row] = val.w;
        }
        {
            int r  = tid >> 4;
            int c4 = (tid & 15) * 4;
            float4 val = __ldg((const float4*)&Bm[(size_t)(k0+r)*N + n0 + c4]);
            *(float4*)&Bs[r][c4] = val;
        }
        __syncthreads();
        #pragma unroll
        for (int kk = 0; kk < 16; ++kk) {
            float a[8], b[4];
            *(float4*)&a[0] = *(const float4*)&As[kk][ty*8];
            *(float4*)&a[4] = *(const float4*)&As[kk][ty*8+4];
            *(float4*)&b[0] = *(const float4*)&Bs[kk][tx*4];
            #pragma unroll
            for (int i = 0; i < 8; ++i)
                #pragma unroll
                for (int j = 0; j < 4; ++j)
                    acc[i][j] = fmaf(a[i], b[j], acc[i][j]);
        }
        __syncthreads();
    }
    #pragma unroll
    for (int i = 0; i < 8; ++i) {
        int row = m0 + ty*8 + i;
        if (row < M) {
            #pragma unroll
            for (int j = 0; j < 4; ++j) {
                int col = n0 + tx*4 + j;
                float prev = accum ? C[(size_t)row*ldc + coff + col] : 0.f;
                C[(size_t)row*ldc + coff + col] = acc[i][j] + __ldg(&bias[col]) + prev;
            }
        }
    }
}

// ---------------- launch ----------------
extern "C" void kernel_launch(void* const* d_in, const int* in_sizes, int n_in,
                              void* d_out, int out_size)
{
    const float* x    = (const float*)d_in[0];
    const int*   ei   = (const int*)  d_in[1];
    const float* ea   = (const float*)d_in[2];
    const float* fpb  = (const float*)d_in[4];
    const float *Wq1=(const float*)d_in[5],  *bq1=(const float*)d_in[6];
    const float *Wk1=(const float*)d_in[7],  *bk1=(const float*)d_in[8];
    const float *Wv1=(const float*)d_in[9],  *bv1=(const float*)d_in[10];
    const float *We1=(const float*)d_in[11];
    const float *Ws1=(const float*)d_in[12], *bs1=(const float*)d_in[13];
    const float *Wq2=(const float*)d_in[14], *bq2=(const float*)d_in[15];
    const float *Wk2=(const float*)d_in[16], *bk2=(const float*)d_in[17];
    const float *Wv2=(const float*)d_in[18], *bv2=(const float*)d_in[19];
    const float *We2=(const float*)d_in[20];
    const float *Ws2=(const float*)d_in[21], *bs2=(const float*)d_in[22];
    const float *Wfp=(const float*)d_in[23], *bfp=(const float*)d_in[24];
    const float *Wfin=(const float*)d_in[25],*bfin=(const float*)d_in[26];

    const int* srcArr = ei;
    const int* dstArr = ei + EE;

    float *q1,*s1,*ph1,*q2,*cc;
    __half *k1h,*v1h,*h1h,*k2h,*v2h;
    cudaGetSymbolAddress((void**)&q1, g_q1);
    cudaGetSymbolAddress((void**)&s1, g_s1);
    cudaGetSymbolAddress((void**)&k1h, g_k1h);
    cudaGetSymbolAddress((void**)&v1h, g_v1h);
    cudaGetSymbolAddress((void**)&h1h, g_h1h);
    cudaGetSymbolAddress((void**)&ph1, g_ph1);
    cudaGetSymbolAddress((void**)&q2, g_q2);
    cudaGetSymbolAddress((void**)&k2h, g_k2h);
    cudaGetSymbolAddress((void**)&v2h, g_v2h);
    cudaGetSymbolAddress((void**)&cc, g_concat);

    const int SM1 = 96*512;    // 49152 B  (16D + 80D, D=512)
    const int SM2 = 96*1024;   // 98304 B  (D=1024)
    cudaFuncSetAttribute(attn_graph_kernel<512,4,true>,
        cudaFuncAttributeMaxDynamicSharedMemorySize, SM1);
    cudaFuncSetAttribute(attn_graph_kernel<1024,4,false>,
        cudaFuncAttributeMaxDynamicSharedMemorySize, SM2);

    // CSR build
    zero_deg_kernel<<<(NN+255)/256, 256>>>();
    hist_kernel<<<(EE+255)/256, 256>>>(dstArr);
    scan_kernel<<<1, 1024>>>();
    scatter_kernel<<<(EE+255)/256, 256>>>(dstArr);
    sort_kernel<<<(NN+255)/256, 256>>>();

    // weight transpose + fp16 convert for q2,k2,v2
    wt2half_kernel<<<dim3(32, 16, 3), dim3(32, 32)>>>(Wq2, Wk2, Wv2);

    // layer 1
    proj1_kernel<<<(NN*32+255)/256, 256>>>(x, Wq1,bq1, Wk1,bk1, Wv1,bv1, Ws1,bs1);
    attn_graph_kernel<512,4,true><<<BB, 640, SM1>>>(
        q1, k1h, v1h, s1, ea, We1, srcArr, ph1, h1h, 512);

    // layer-2 q/k/v projections on tensor cores
    {
        dim3 grid((NN+127)/128, 1024/128, 3);
        gemm3_f16_kernel<<<grid, 256>>>(h1h, bq2, bk2, bv2, q2, NN);
    }

    // layer-2 attention: pooled message written straight into concat[:, :1024]
    attn_graph_kernel<1024,4,false><<<BB, 640, SM2>>>(
        q2, k2h, v2h, nullptr, ea, We2, srcArr, cc, nullptr, 1280);

    // + pooled skip:  concat[:, :1024] += ph1 @ Ws2 + bs2
    gemm_kernel<<<dim3((BB+127)/128, 1024/64), 256>>>(ph1, Ws2, bs2, cc,
        BB, 1024, 512, 1280, 0, 1);

    // fingerprint + final (fp32)
    gemm_kernel<<<dim3((BB+127)/128, 256/64), 256>>>(fpb, Wfp, bfp, cc,
        BB, 256, 2048, 1280, 1024, 0);
    gemm_kernel<<<dim3((BB+127)/128, 1024/64), 256>>>(cc, Wfin, bfin, (float*)d_out,
        BB, 1024, 1280, 1024, 0, 0);
}

// round 9
// speedup vs baseline: 2.4551x; 1.1737x over previous
#include <cuda_runtime.h>
#include <cuda_fp16.h>
#include <math.h>
#include <stdint.h>

#define NN 24000
#define EE 96000
#define BB 1200
#define NPG 20

// ---------------- device scratch ----------------
__device__ float  g_q1[NN*512];
__device__ float  g_s1[NN*512];
__device__ __half g_k1h[NN*512];
__device__ __half g_v1h[NN*512];
__device__ __half g_h1h[NN*512];
__device__ float  g_ph1[BB*512];
__device__ float  g_q2[NN*1024];
__device__ __half g_k2h[NN*1024];
__device__ float  g_z[BB*2048];     // per-graph per-head weighted h1 sums [B][4][512] (scaled 1/NPG)
__device__ float  g_r[BB*16];       // per-graph per-head sum w*a4 [B][4][4] (scaled 1/NPG)
__device__ float  g_cnt[BB];        // per-graph count of fed nodes
__device__ float  g_concat[BB*1280];
__device__ int    g_deg[NN];
__device__ int    g_offs[NN+1];
__device__ int    g_cursor[NN];
__device__ int    g_eidx[EE];
__device__ __half g_w2h[2*1024*512];   // [z][n][k]  (q,k transposed, k contiguous)

// ---------------- CSR build ----------------
__global__ void zero_deg_kernel() {
    int i = blockIdx.x*blockDim.x + threadIdx.x;
    if (i < NN) g_deg[i] = 0;
}

__global__ void hist_kernel(const int* __restrict__ dst) {
    int e = blockIdx.x*blockDim.x + threadIdx.x;
    if (e < EE) atomicAdd(&g_deg[dst[e]], 1);
}

__global__ void scan_kernel() {
    __shared__ int wsum[32];
    __shared__ int carry;
    int tid = threadIdx.x;
    int lane = tid & 31, wid = tid >> 5;
    if (tid == 0) carry = 0;
    __syncthreads();
    for (int base = 0; base < NN; base += 1024) {
        int i = base + tid;
        int v = (i < NN) ? g_deg[i] : 0;
        int x = v;
        #pragma unroll
        for (int o = 1; o < 32; o <<= 1) {
            int y = __shfl_up_sync(0xffffffffu, x, o);
            if (lane >= o) x += y;
        }
        if (lane == 31) wsum[wid] = x;
        __syncthreads();
        if (wid == 0) {
            int s = wsum[lane];
            #pragma unroll
            for (int o = 1; o < 32; o <<= 1) {
                int y = __shfl_up_sync(0xffffffffu, s, o);
                if (lane >= o) s += y;
            }
            wsum[lane] = s;
        }
        __syncthreads();
        int pre = (wid > 0 ? wsum[wid-1] : 0) + carry;
        int incl = x + pre;
        if (i < NN) { g_offs[i] = incl - v; g_cursor[i] = incl - v; }
        __syncthreads();
        if (tid == 1023) carry = incl;
        __syncthreads();
    }
    if (tid == 0) g_offs[NN] = carry;
}

__global__ void scatter_kernel(const int* __restrict__ dst) {
    int e = blockIdx.x*blockDim.x + threadIdx.x;
    if (e < EE) {
        int p = atomicAdd(&g_cursor[dst[e]], 1);
        g_eidx[p] = e;
    }
}

__global__ void sort_kernel() {
    int n = blockIdx.x*blockDim.x + threadIdx.x;
    if (n >= NN) return;
    int a = g_offs[n], b = g_offs[n+1];
    for (int i = a+1; i < b; ++i) {
        int key = g_eidx[i];
        int j = i-1;
        while (j >= a && g_eidx[j] > key) { g_eidx[j+1] = g_eidx[j]; --j; }
        g_eidx[j+1] = key;
    }
}

// ---------------- layer-1 projections: q,s fp32; k,v fp16 ----------------
__global__ void proj1_kernel(const float* __restrict__ x,
    const float* __restrict__ Wq, const float* __restrict__ bq,
    const float* __restrict__ Wk, const float* __restrict__ bk,
    const float* __restrict__ Wv, const float* __restrict__ bv,
    const float* __restrict__ Ws, const float* __restrict__ bs)
{
    int warp = (blockIdx.x*blockDim.x + threadIdx.x) >> 5;
    int lane = threadIdx.x & 31;
    if (warp >= NN) return;
    float xr[9];
    #pragma unroll
    for (int t = 0; t < 9; ++t) xr[t] = __ldg(&x[warp*9 + t]);
    for (int j = lane; j < 512; j += 32) {
        float aq = __ldg(&bq[j]), ak = __ldg(&bk[j]);
        float av = __ldg(&bv[j]), as_ = __ldg(&bs[j]);
        #pragma unroll
        for (int t = 0; t < 9; ++t) {
            float xv = xr[t];
            aq  = fmaf(xv, __ldg(&Wq[t*512+j]), aq);
            ak  = fmaf(xv, __ldg(&Wk[t*512+j]), ak);
            av  = fmaf(xv, __ldg(&Wv[t*512+j]), av);
            as_ = fmaf(xv, __ldg(&Ws[t*512+j]), as_);
        }
        size_t o = (size_t)warp*512 + j;
        g_q1[o] = aq; g_s1[o] = as_;
        g_k1h[o] = __float2half_rn(ak);
        g_v1h[o] = __float2half_rn(av);
    }
}

// ---------------- layer-1 per-graph attention (full per-node output + pooled) ----------
__global__ void __launch_bounds__(640, 1) attn1_kernel(
    const float* __restrict__ q, const __half* __restrict__ khg,
    const __half* __restrict__ vhg, const float* __restrict__ s,
    const float* __restrict__ ea, const float* __restrict__ We,
    const int* __restrict__ srcArr, float* __restrict__ outPooled,
    __half* __restrict__ h1h)
{
    constexpr int D = 512, H = 4;
    constexpr int VPT = D / 32;          // 16
    constexpr int NU = VPT / 8;          // 2
    constexpr int C = D / H;
    extern __shared__ char smraw[];
    float*  sWeT = (float*)smraw;                       // [D][4]
    __half* kh   = (__half*)(smraw + 16*D);             // [20][D]
    __half* vh   = (__half*)(smraw + 16*D + 40*D);      // [20][D]
    float*  poolbuf = (float*)kh;                       // overlay [20][D]

    int tid = threadIdx.x;
    int wid = tid >> 5, lane = tid & 31;
    int graph = blockIdx.x;
    int gbase = graph * NPG;

    for (int i = tid; i < 4*D; i += 640) {
        int c = i >> 2, t = i & 3;
        sWeT[i] = __ldg(&We[t*D + c]);
    }
    {
        const uint4* ks = (const uint4*)(khg + (size_t)gbase*D);
        const uint4* vs = (const uint4*)(vhg + (size_t)gbase*D);
        uint4* kd = (uint4*)kh;
        uint4* vd = (uint4*)vh;
        for (int i = tid; i < NPG*D/8; i += 640) { kd[i] = __ldg(ks+i); vd[i] = __ldg(vs+i); }
    }
    __syncthreads();

    int node = gbase + wid;
    int cbase = lane * VPT;
    const float4* sWe4 = (const float4*)sWeT;

    float qrf[VPT], accf[VPT];
    {
        const float4* q4 = (const float4*)(q + (size_t)node*D + cbase);
        #pragma unroll
        for (int i = 0; i < VPT/4; ++i) *(float4*)&qrf[4*i] = __ldg(q4 + i);
    }
    #pragma unroll
    for (int i = 0; i < VPT; ++i) accf[i] = 0.f;

    float4 qe = make_float4(0.f,0.f,0.f,0.f);
    #pragma unroll
    for (int i = 0; i < VPT; ++i) {
        float4 w = sWe4[cbase + i];
        qe.x = fmaf(qrf[i], w.x, qe.x);
        qe.y = fmaf(qrf[i], w.y, qe.y);
        qe.z = fmaf(qrf[i], w.z, qe.z);
        qe.w = fmaf(qrf[i], w.w, qe.w);
    }
    #pragma unroll
    for (int o = 1; o < 8; o <<= 1) {
        qe.x += __shfl_xor_sync(0xffffffffu, qe.x, o);
        qe.y += __shfl_xor_sync(0xffffffffu, qe.y, o);
        qe.z += __shfl_xor_sync(0xffffffffu, qe.z, o);
        qe.w += __shfl_xor_sync(0xffffffffu, qe.w, o);
    }

    float m = -INFINITY, den = 0.f;
    float4 wa = make_float4(0.f,0.f,0.f,0.f);
    const float invs = rsqrtf((float)C);

    int e0 = g_offs[node], e1 = g_offs[node+1];
    for (int t = e0; t < e1; ++t) {
        int e  = __ldg(&g_eidx[t]);
        int ln = __ldg(&srcArr[e]) - gbase;
        float4 a4 = __ldg((const float4*)ea + e);

        const uint4* krow = (const uint4*)(kh + ln*D + cbase);
        float p = 0.f;
        #pragma unroll
        for (int i = 0; i < NU; ++i) {
            uint4 u = krow[i];
            const __half2* h2 = (const __half2*)&u;
            #pragma unroll
            for (int j = 0; j < 4; ++j) {
                float2 f = __half22float2(h2[j]);
                p = fmaf(qrf[8*i+2*j], f.x, p);
                p = fmaf(qrf[8*i+2*j+1], f.y, p);
            }
        }
        p += __shfl_xor_sync(0xffffffffu, p, 1);
        p += __shfl_xor_sync(0xffffffffu, p, 2);
        p += __shfl_xor_sync(0xffffffffu, p, 4);
        float alpha = (p + qe.x*a4.x + qe.y*a4.y + qe.z*a4.z + qe.w*a4.w) * invs;

        float nm = fmaxf(m, alpha);
        float sc = __expf(m - nm);
        float w  = __expf(alpha - nm);
        den = den*sc + w;
        m = nm;

        const uint4* vrow = (const uint4*)(vh + ln*D + cbase);
        #pragma unroll
        for (int i = 0; i < NU; ++i) {
            uint4 u = vrow[i];
            const __half2* h2 = (const __half2*)&u;
            #pragma unroll
            for (int j = 0; j < 4; ++j) {
                float2 f = __half22float2(h2[j]);
                accf[8*i+2*j]   = accf[8*i+2*j]*sc   + w*f.x;
                accf[8*i+2*j+1] = accf[8*i+2*j+1]*sc + w*f.y;
            }
        }
        wa.x = wa.x*sc + w*a4.x; wa.y = wa.y*sc + w*a4.y;
        wa.z = wa.z*sc + w*a4.z; wa.w = wa.w*sc + w*a4.w;
    }

    float r = 1.f / (den + 1e-16f);
    float outv[VPT];
    #pragma unroll
    for (int i = 0; i < VPT; ++i) {
        float4 w = sWe4[cbase + i];
        float msg = (accf[i] + wa.x*w.x + wa.y*w.y + wa.z*w.z + wa.w*w.w) * r;
        msg += __ldg(&s[(size_t)node*D + cbase + i]);
        msg = fmaxf(msg, 0.f);
        outv[i] = msg;
    }
    {
        __half2* h4 = (__half2*)(h1h + (size_t)node*D + cbase);
        #pragma unroll
        for (int i = 0; i < VPT/2; ++i)
            h4[i] = __floats2half2_rn(outv[2*i], outv[2*i+1]);
    }

    __syncthreads();
    #pragma unroll
    for (int i = 0; i < VPT; ++i) poolbuf[wid*D + cbase + i] = outv[i];
    __syncthreads();
    for (int c = tid; c < D; c += 640) {
        float sum = 0.f;
        #pragma unroll
        for (int i = 0; i < NPG; ++i) sum += poolbuf[i*D + c];
        outPooled[(size_t)graph*512 + c] = sum * (1.f/NPG);
    }
}

// ---------------- layer-2 attention: softmax weights only -> z, r, cnt ----------------
// z[g][h][512] = (1/NPG) sum_src c_{src,h} h1[src];  r[g][h][4] = (1/NPG) sum_e w_e a4.
__global__ void __launch_bounds__(640, 1) attn2_kernel(
    const float* __restrict__ q, const __half* __restrict__ khg,
    const __half* __restrict__ h1g,
    const float* __restrict__ ea, const float* __restrict__ We,
    const int* __restrict__ srcArr)
{
    constexpr int D = 1024, H = 4;
    constexpr int VPT = D / 32;          // 32
    constexpr int NU = VPT / 8;          // 4
    constexpr int C = D / H;             // 256
    constexpr int ECAP = 256;
    extern __shared__ char smraw[];
    float*  sWeT   = (float*)smraw;                              // 16KB
    __half* kh     = (__half*)(smraw + 16*D);                    // [20][1024] 40KB
    __half* h1s    = (__half*)(smraw + 16*D + 2*NPG*D);          // [20][512] 20KB
    float*  alphaS = (float*)(smraw + 16*D + 2*NPG*D + NPG*1024);// [ECAP][4] 4KB
    float*  wS     = alphaS + ECAP*H;                            // [ECAP][4] 4KB
    int*    lnS    = (int*)(wS + ECAP*H);                        // [ECAP]
    float*  cS     = (float*)(lnS + ECAP);                       // [20][4]
    int*    hasE   = (int*)(cS + NPG*H);                         // [20]

    int tid = threadIdx.x;
    int wid = tid >> 5, lane = tid & 31;
    int graph = blockIdx.x;
    int gbase = graph * NPG;
    int head = lane >> 3;

    for (int i = tid; i < 4*D; i += 640) {
        int c = i >> 2, t = i & 3;
        sWeT[i] = __ldg(&We[t*D + c]);
    }
    {
        const uint4* ks = (const uint4*)(khg + (size_t)gbase*D);
        uint4* kd = (uint4*)kh;
        for (int i = tid; i < NPG*D/8; i += 640) kd[i] = __ldg(ks+i);
        const uint4* hs = (const uint4*)(h1g + (size_t)gbase*512);
        uint4* hd = (uint4*)h1s;
        for (int i = tid; i < NPG*512/8; i += 640) hd[i] = __ldg(hs+i);
    }
    __syncthreads();

    int node = gbase + wid;
    int cbase = lane * VPT;
    const float4* sWe4 = (const float4*)sWeT;

    float qrf[VPT];
    {
        const float4* q4 = (const float4*)(q + (size_t)node*D + cbase);
        #pragma unroll
        for (int i = 0; i < VPT/4; ++i) *(float4*)&qrf[4*i] = __ldg(q4 + i);
    }

    float4 qe = make_float4(0.f,0.f,0.f,0.f);
    #pragma unroll
    for (int i = 0; i < VPT; ++i) {
        float4 w = sWe4[cbase + i];
        qe.x = fmaf(qrf[i], w.x, qe.x);
        qe.y = fmaf(qrf[i], w.y, qe.y);
        qe.z = fmaf(qrf[i], w.z, qe.z);
        qe.w = fmaf(qrf[i], w.w, qe.w);
    }
    #pragma unroll
    for (int o = 1; o < 8; o <<= 1) {
        qe.x += __shfl_xor_sync(0xffffffffu, qe.x, o);
        qe.y += __shfl_xor_sync(0xffffffffu, qe.y, o);
        qe.z += __shfl_xor_sync(0xffffffffu, qe.z, o);
        qe.w += __shfl_xor_sync(0xffffffffu, qe.w, o);
    }

    const float invs = rsqrtf((float)C);
    int eb = g_offs[gbase];
    int cntE = g_offs[gbase + NPG] - eb;
    int e0 = g_offs[node], e1 = g_offs[node+1];

    float m = -INFINITY, den = 0.f;
    for (int t = e0; t < e1; ++t) {
        int e  = __ldg(&g_eidx[t]);
        int ln = __ldg(&srcArr[e]) - gbase;
        float4 a4 = __ldg((const float4*)ea + e);

        const uint4* krow = (const uint4*)(kh + ln*D + cbase);
        float p = 0.f;
        #pragma unroll
        for (int i = 0; i < NU; ++i) {
            uint4 u = krow[i];
            const __half2* h2 = (const __half2*)&u;
            #pragma unroll
            for (int j = 0; j < 4; ++j) {
                float2 f = __half22float2(h2[j]);
                p = fmaf(qrf[8*i+2*j], f.x, p);
                p = fmaf(qrf[8*i+2*j+1], f.y, p);
            }
        }
        p += __shfl_xor_sync(0xffffffffu, p, 1);
        p += __shfl_xor_sync(0xffffffffu, p, 2);
        p += __shfl_xor_sync(0xffffffffu, p, 4);
        float alpha = (p + qe.x*a4.x + qe.y*a4.y + qe.z*a4.z + qe.w*a4.w) * invs;

        float nm = fmaxf(m, alpha);
        den = den*__expf(m - nm) + __expf(alpha - nm);
        m = nm;
        if ((lane & 7) == 0) alphaS[(t - eb)*H + head] = alpha;
        if (lane == 0) lnS[t - eb] = ln;
    }
    // normalized weights
    float rdn = (e1 > e0) ? 1.f/den : 0.f;
    if ((lane & 7) == 0) {
        for (int t = e0; t < e1; ++t) {
            float w = __expf(alphaS[(t - eb)*H + head] - m) * rdn;
            wS[(t - eb)*H + head] = w;
        }
    }
    if (lane == 0) hasE[wid] = (e1 > e0) ? 1 : 0;
    __syncthreads();

    // c[ln][h] = (1/NPG) * sum of w over this graph's edges with src==ln (fixed order)
    if (tid < NPG*H) {
        int ln = tid >> 2, h = tid & 3;
        float c = 0.f;
        for (int i = 0; i < cntE; ++i)
            if (lnS[i] == ln) c += wS[i*H + h];
        cS[tid] = c * (1.f/NPG);
    } else if (tid < NPG*H + 16) {
        int idx = tid - NPG*H;
        int h = idx >> 2, t4 = idx & 3;
        float r = 0.f;
        for (int i = 0; i < cntE; ++i) {
            int e = __ldg(&g_eidx[eb + i]);
            r += wS[i*H + h] * __ldg(&ea[e*4 + t4]);
        }
        g_r[graph*16 + h*4 + t4] = r * (1.f/NPG);
    } else if (tid == NPG*H + 16) {
        int c = 0;
        #pragma unroll
        for (int i = 0; i < NPG; ++i) c += hasE[i];
        g_cnt[graph] = (float)c;
    }
    __syncthreads();

    // z[h][c] = sum_ln cS[ln][h] * h1s[ln][c]   (cS already scaled by 1/NPG)
    for (int o = tid; o < H*512; o += 640) {
        int h = o >> 9, c = o & 511;
        float z = 0.f;
        #pragma unroll
        for (int ln = 0; ln < NPG; ++ln)
            z = fmaf(cS[ln*H + h], __half2float(h1s[ln*512 + c]), z);
        g_z[(size_t)graph*2048 + o] = z;
    }
}

// ---------------- weight transpose+fp16 convert: Wt[z][n][k] = (half)W_z[k][n] -----------
__global__ void wt2half_kernel(const float* __restrict__ W0, const float* __restrict__ W1) {
    __shared__ float tile[32][33];
    int z = blockIdx.z;
    const float* W = (z==0) ? W0 : W1;
    int n0 = blockIdx.x * 32, k0 = blockIdx.y * 32;
    int tx = threadIdx.x, ty = threadIdx.y;
    tile[ty][tx] = __ldg(&W[(size_t)(k0+ty)*1024 + n0 + tx]);
    __syncthreads();
    g_w2h[(size_t)z*1024*512 + (size_t)(n0+ty)*512 + k0 + tx] = __float2half_rn(tile[tx][ty]);
}

// ---------------- f16 tensor-core GEMM (m16n8k16): q2 fp32 / k2h fp16 ----------------
__global__ void __launch_bounds__(256) gemm2_f16_kernel(
    const __half* __restrict__ Ah,
    const float* __restrict__ b0, const float* __restrict__ b1,
    float* C0, int M)
{
    __shared__ uint32_t As[2][128][20];
    __shared__ uint32_t Bs[2][128][20];

    int z = blockIdx.z;
    const __half* Bz  = g_w2h + (size_t)z*1024*512;
    const float* bias = (z==0) ? b0 : b1;

    int tid  = threadIdx.x;
    int lane = tid & 31, wid = tid >> 5;
    int wm = wid >> 2, wn = wid & 3;
    int m0 = blockIdx.x * 128, n0 = blockIdx.y * 128;
    int g = lane >> 2, t = lane & 3;

    int lm[2], lq[2];
    #pragma unroll
    for (int i = 0; i < 2; ++i) {
        int idx = tid + i*256;
        lm[i] = idx >> 2;
        lq[i] = (idx & 3) * 8;
    }

    float acc[4][4][4];
    #pragma unroll
    for (int a = 0; a < 4; ++a)
        #pragma unroll
        for (int b = 0; b < 4; ++b)
            #pragma unroll
            for (int c = 0; c < 4; ++c) acc[a][b][c] = 0.f;

    float4 pa[2], pb[2];
    const int T = 512 / 32;

    #pragma unroll
    for (int i = 0; i < 2; ++i) {
        pa[i] = (m0 + lm[i] < M)
              ? *(const float4*)(Ah + (size_t)(m0+lm[i])*512 + lq[i])
              : make_float4(0.f,0.f,0.f,0.f);
        pb[i] = *(const float4*)(Bz + (size_t)(n0+lm[i])*512 + lq[i]);
    }
    #pragma unroll
    for (int i = 0; i < 2; ++i) {
        *(float4*)&As[0][lm[i]][lq[i]>>1] = pa[i];
        *(float4*)&Bs[0][lm[i]][lq[i]>>1] = pb[i];
    }
    __syncthreads();

    for (int kt = 0; kt < T; ++kt) {
        int b = kt & 1;
        if (kt + 1 < T) {
            int ko = (kt+1) * 32;
            #pragma unroll
            for (int i = 0; i < 2; ++i) {
                pa[i] = (m0 + lm[i] < M)
                      ? *(const float4*)(Ah + (size_t)(m0+lm[i])*512 + ko + lq[i])
                      : make_float4(0.f,0.f,0.f,0.f);
                pb[i] = *(const float4*)(Bz + (size_t)(n0+lm[i])*512 + ko + lq[i]);
            }
        }

        #pragma unroll
        for (int ks = 0; ks < 2; ++ks) {
            int kb = ks * 8;
            uint32_t af[4][4], bf[4][2];
            #pragma unroll
            for (int mt = 0; mt < 4; ++mt) {
                int mb = wm*64 + mt*16;
                af[mt][0] = As[b][mb+g  ][kb+t  ];
                af[mt][1] = As[b][mb+g+8][kb+t  ];
                af[mt][2] = As[b][mb+g  ][kb+t+4];
                af[mt][3] = As[b][mb+g+8][kb+t+4];
            }
            #pragma unroll
            for (int nt = 0; nt < 4; ++nt) {
                int nb = wn*32 + nt*8;
                bf[nt][0] = Bs[b][nb+g][kb+t  ];
                bf[nt][1] = Bs[b][nb+g][kb+t+4];
            }
            #pragma unroll
            for (int mt = 0; mt < 4; ++mt)
                #pragma unroll
                for (int nt = 0; nt < 4; ++nt) {
                    asm volatile(
                        "mma.sync.aligned.m16n8k16.row.col.f32.f16.f16.f32 "
                        "{%0,%1,%2,%3}, {%4,%5,%6,%7}, {%8,%9}, {%0,%1,%2,%3};"
                        : "+f"(acc[mt][nt][0]), "+f"(acc[mt][nt][1]),
                          "+f"(acc[mt][nt][2]), "+f"(acc[mt][nt][3])
                        : "r"(af[mt][0]), "r"(af[mt][1]), "r"(af[mt][2]), "r"(af[mt][3]),
                          "r"(bf[nt][0]), "r"(bf[nt][1]));
                }
        }

        if (kt + 1 < T) {
            int nb_ = b ^ 1;
            #pragma unroll
            for (int i = 0; i < 2; ++i) {
                *(float4*)&As[nb_][lm[i]][lq[i]>>1] = pa[i];
                *(float4*)&Bs[nb_][lm[i]][lq[i]>>1] = pb[i];
            }
            __syncthreads();
        }
    }

    #pragma unroll
    for (int mt = 0; mt < 4; ++mt) {
        int r0 = m0 + wm*64 + mt*16 + g;
        #pragma unroll
        for (int nt = 0; nt < 4; ++nt) {
            int c = n0 + wn*32 + nt*8 + t*2;
            float bv0 = __ldg(&bias[c]), bv1 = __ldg(&bias[c+1]);
            float o00 = acc[mt][nt][0] + bv0, o01 = acc[mt][nt][1] + bv1;
            float o10 = acc[mt][nt][2] + bv0, o11 = acc[mt][nt][3] + bv1;
            if (z == 0) {
                if (r0 < M)     *(float2*)&C0[(size_t)r0*1024 + c]     = make_float2(o00, o01);
                if (r0 + 8 < M) *(float2*)&C0[(size_t)(r0+8)*1024 + c] = make_float2(o10, o11);
            } else {
                if (r0 < M)     *(__half2*)&g_k2h[(size_t)r0*1024 + c]     = __floats2half2_rn(o00, o01);
                if (r0 + 8 < M) *(__half2*)&g_k2h[(size_t)(r0+8)*1024 + c] = __floats2half2_rn(o10, o11);
            }
        }
    }
}

// ---------------- fp32 tiled GEMM (tails; optional accumulate) ----------------
__global__ void __launch_bounds__(256) gemm_kernel(
    const float* __restrict__ A, const float* __restrict__ Bm,
    const float* __restrict__ bias, float* __restrict__ C,
    int M, int N, int K, int ldc, int coff, int accum)
{
    __shared__ float As[16][128+4];
    __shared__ float Bs[16][64+4];
    int tid = threadIdx.x;
    int tx = tid & 15, ty = tid >> 4;
    int m0 = blockIdx.x * 128;
    int n0 = blockIdx.y * 64;
    float acc[8][4] = {};

    for (int k0 = 0; k0 < K; k0 += 16) {
        #pragma unroll
        for (int it = 0; it < 2; ++it) {
            int f = tid + it*256;
            int row = f >> 2;
            int c4 = (f & 3) * 4;
            float4 val = make_float4(0.f,0.f,0.f,0.f);
            if (m0 + row < M)
                val = __ldg((const float4*)&A[(size_t)(m0+row)*K + k0 + c4]);
            As[c4+0][row] = val.x; As[c4+1][row] = val.y;
            As[c4+2][row] = val.z; As[c4+3][row] = val.w;
        }
        {
            int r  = tid >> 4;
            int c4 = (tid & 15) * 4;
            float4 val = __ldg((const float4*)&Bm[(size_t)(k0+r)*N + n0 + c4]);
            *(float4*)&Bs[r][c4] = val;
        }
        __syncthreads();
        #pragma unroll
        for (int kk = 0; kk < 16; ++kk) {
            float a[8], b[4];
            *(float4*)&a[0] = *(const float4*)&As[kk][ty*8];
            *(float4*)&a[4] = *(const float4*)&As[kk][ty*8+4];
            *(float4*)&b[0] = *(const float4*)&Bs[kk][tx*4];
            #pragma unroll
            for (int i = 0; i < 8; ++i)
                #pragma unroll
                for (int j = 0; j < 4; ++j)
                    acc[i][j] = fmaf(a[i], b[j], acc[i][j]);
        }
        __syncthreads();
    }
    #pragma unroll
    for (int i = 0; i < 8; ++i) {
        int row = m0 + ty*8 + i;
        if (row < M) {
            #pragma unroll
            for (int j = 0; j < 4; ++j) {
                int col = n0 + tx*4 + j;
                float prev = accum ? C[(size_t)row*ldc + coff + col] : 0.f;
                C[(size_t)row*ldc + coff + col] = acc[i][j] + __ldg(&bias[col]) + prev;
            }
        }
    }
}

// ---------------- z @ Wv2 (per-head block-diagonal), accumulate into concat ----------
__global__ void __launch_bounds__(256) gemmz_kernel(const float* __restrict__ Wv2)
{
    __shared__ float As[16][128+4];
    __shared__ float Bs[16][64+4];
    int tid = threadIdx.x;
    int tx = tid & 15, ty = tid >> 4;
    int m0 = blockIdx.x * 128;
    int n0 = blockIdx.y * 64;
    int hOff = (n0 >> 8) * 512;      // head = n0/256, A slice offset
    float acc[8][4] = {};

    for (int k0 = 0; k0 < 512; k0 += 16) {
        #pragma unroll
        for (int it = 0; it < 2; ++it) {
            int f = tid + it*256;
            int row = f >> 2;
            int c4 = (f & 3) * 4;
            float4 val = make_float4(0.f,0.f,0.f,0.f);
            if (m0 + row < BB)
                val = __ldg((const float4*)&g_z[(size_t)(m0+row)*2048 + hOff + k0 + c4]);
            As[c4+0][row] = val.x; As[c4+1][row] = val.y;
            As[c4+2][row] = val.z; As[c4+3][row] = val.w;
        }
        {
            int r  = tid >> 4;
            int c4 = (tid & 15) * 4;
            float4 val = __ldg((const float4*)&Wv2[(size_t)(k0+r)*1024 + n0 + c4]);
            *(float4*)&Bs[r][c4] = val;
        }
        __syncthreads();
        #pragma unroll
        for (int kk = 0; kk < 16; ++kk) {
            float a[8], b[4];
            *(float4*)&a[0] = *(const float4*)&As[kk][ty*8];
            *(float4*)&a[4] = *(const float4*)&As[kk][ty*8+4];
            *(float4*)&b[0] = *(const float4*)&Bs[kk][tx*4];
            #pragma unroll
            for (int i = 0; i < 8; ++i)
                #pragma unroll
                for (int j = 0; j < 4; ++j)
                    acc[i][j] = fmaf(a[i], b[j], acc[i][j]);
        }
        __syncthreads();
    }
    #pragma unroll
    for (int i = 0; i < 8; ++i) {
        int row = m0 + ty*8 + i;
        if (row < BB) {
            #pragma unroll
            for (int j = 0; j < 4; ++j) {
                int col = n0 + tx*4 + j;
                g_concat[(size_t)row*1280 + col] += acc[i][j];
            }
        }
    }
}

// ---------------- epilogue: edge term + bv2 term into concat ----------------
__global__ void eps_kernel(const float* __restrict__ We2, const float* __restrict__ bv2)
{
    int g = blockIdx.x;
    int c = blockIdx.y*256 + threadIdx.x;
    int h = c >> 8;
    float acc = g_cnt[g] * (1.f/NPG) * __ldg(&bv2[c]);
    #pragma unroll
    for (int t = 0; t < 4; ++t)
        acc = fmaf(g_r[g*16 + h*4 + t], __ldg(&We2[t*1024 + c]), acc);
    g_concat[(size_t)g*1280 + c] += acc;
}

// ---------------- launch ----------------
extern "C" void kernel_launch(void* const* d_in, const int* in_sizes, int n_in,
                              void* d_out, int out_size)
{
    const float* x    = (const float*)d_in[0];
    const int*   ei   = (const int*)  d_in[1];
    const float* ea   = (const float*)d_in[2];
    const float* fpb  = (const float*)d_in[4];
    const float *Wq1=(const float*)d_in[5],  *bq1=(const float*)d_in[6];
    const float *Wk1=(const float*)d_in[7],  *bk1=(const float*)d_in[8];
    const float *Wv1=(const float*)d_in[9],  *bv1=(const float*)d_in[10];
    const float *We1=(const float*)d_in[11];
    const float *Ws1=(const float*)d_in[12], *bs1=(const float*)d_in[13];
    const float *Wq2=(const float*)d_in[14], *bq2=(const float*)d_in[15];
    const float *Wk2=(const float*)d_in[16], *bk2=(const float*)d_in[17];
    const float *Wv2=(const float*)d_in[18], *bv2=(const float*)d_in[19];
    const float *We2=(const float*)d_in[20];
    const float *Ws2=(const float*)d_in[21], *bs2=(const float*)d_in[22];
    const float *Wfp=(const float*)d_in[23], *bfp=(const float*)d_in[24];
    const float *Wfin=(const float*)d_in[25],*bfin=(const float*)d_in[26];

    const int* srcArr = ei;
    const int* dstArr = ei + EE;

    float *q1,*s1,*ph1,*q2,*cc;
    __half *k1h,*v1h,*h1h,*k2h;
    cudaGetSymbolAddress((void**)&q1, g_q1);
    cudaGetSymbolAddress((void**)&s1, g_s1);
    cudaGetSymbolAddress((void**)&k1h, g_k1h);
    cudaGetSymbolAddress((void**)&v1h, g_v1h);
    cudaGetSymbolAddress((void**)&h1h, g_h1h);
    cudaGetSymbolAddress((void**)&ph1, g_ph1);
    cudaGetSymbolAddress((void**)&q2, g_q2);
    cudaGetSymbolAddress((void**)&k2h, g_k2h);
    cudaGetSymbolAddress((void**)&cc, g_concat);

    const int SM1 = 96*512;                               // 49152 B
    const int SM2 = 16*1024 + 2*NPG*1024 + NPG*1024
                  + 256*4*4*2 + 256*4 + NPG*4*4 + NPG*4 + 64;
    cudaFuncSetAttribute(attn1_kernel, cudaFuncAttributeMaxDynamicSharedMemorySize, SM1);
    cudaFuncSetAttribute(attn2_kernel, cudaFuncAttributeMaxDynamicSharedMemorySize, SM2);

    // CSR build
    zero_deg_kernel<<<(NN+255)/256, 256>>>();
    hist_kernel<<<(EE+255)/256, 256>>>(dstArr);
    scan_kernel<<<1, 1024>>>();
    scatter_kernel<<<(EE+255)/256, 256>>>(dstArr);
    sort_kernel<<<(NN+255)/256, 256>>>();

    // weight transpose + fp16 convert for q2,k2
    wt2half_kernel<<<dim3(32, 16, 2), dim3(32, 32)>>>(Wq2, Wk2);

    // layer 1
    proj1_kernel<<<(NN*32+255)/256, 256>>>(x, Wq1,bq1, Wk1,bk1, Wv1,bv1, Ws1,bs1);
    attn1_kernel<<<BB, 640, SM1>>>(q1, k1h, v1h, s1, ea, We1, srcArr, ph1, h1h);

    // layer-2 q,k projections on tensor cores (v projection eliminated by algebra)
    {
        dim3 grid((NN+127)/128, 1024/128, 2);
        gemm2_f16_kernel<<<grid, 256>>>(h1h, bq2, bk2, q2, NN);
    }

    // layer-2 attention weights -> z, r, cnt
    attn2_kernel<<<BB, 640, SM2>>>(q2, k2h, h1h, ea, We2, srcArr);

    // concat[:, :1024] = ph1 @ Ws2 + bs2  (pooled skip)
    gemm_kernel<<<dim3((BB+127)/128, 1024/64), 256>>>(ph1, Ws2, bs2, cc,
        BB, 1024, 512, 1280, 0, 0);
    // += z @ Wv2 (per-head)
    gemmz_kernel<<<dim3((BB+127)/128, 1024/64), 256>>>(Wv2);
    // += edge/bias terms
    eps_kernel<<<dim3(BB, 4), 256>>>(We2, bv2);

    // fingerprint + final
    gemm_kernel<<<dim3((BB+127)/128, 256/64), 256>>>(fpb, Wfp, bfp, cc,
        BB, 256, 2048, 1280, 1024, 0);
    gemm_kernel<<<dim3((BB+127)/128, 1024/64), 256>>>(cc, Wfin, bfin, (float*)d_out,
        BB, 1024, 1280, 1024, 0, 0);
}

// round 10
// speedup vs baseline: 3.2157x; 1.3098x over previous
#include <cuda_runtime.h>
#include <cuda_fp16.h>
#include <math.h>
#include <stdint.h>

#define NN 24000
#define EE 96000
#define BB 1200
#define NPG 20

// ---------------- device scratch ----------------
__device__ float  g_q1[NN*512];
__device__ float  g_s1[NN*512];
__device__ __half g_k1h[NN*512];
__device__ __half g_v1h[NN*512];
__device__ __half g_h1h[NN*512];
__device__ float  g_ph1[BB*512];
__device__ float  g_q2[NN*1024];
__device__ __half g_k2h[NN*1024];
__device__ float  g_z[BB*2048];     // per-graph per-head weighted h1 sums (scaled 1/NPG)
__device__ float  g_r[BB*16];       // per-graph per-head sum w*a4 (scaled 1/NPG)
__device__ float  g_cnt[BB];
__device__ float  g_concat[BB*1280];
__device__ int    g_deg[NN];
__device__ int    g_offs[NN+1];
__device__ int    g_cursor[NN];
__device__ int    g_eidx[EE];
__device__ __half g_w2h[2*1024*512];    // q,k weights transposed [z][n][k]
__device__ __half g_wfinh[1024*1280];   // Wfin transposed [n][k] fp16
__device__ __half g_cch[BB*1280];       // concat fp16
__device__ float  g_fppart[4*BB*256];   // fingerprint GEMM split-K partials
__device__ float  g_fpart[4*BB*1024];   // final GEMM split-K partials

// ---------------- CSR build ----------------
__global__ void zero_deg_kernel() {
    int i = blockIdx.x*blockDim.x + threadIdx.x;
    if (i < NN) g_deg[i] = 0;
}

__global__ void hist_kernel(const int* __restrict__ dst) {
    int e = blockIdx.x*blockDim.x + threadIdx.x;
    if (e < EE) atomicAdd(&g_deg[dst[e]], 1);
}

__global__ void scan_kernel() {
    __shared__ int wsum[32];
    __shared__ int carry;
    int tid = threadIdx.x;
    int lane = tid & 31, wid = tid >> 5;
    if (tid == 0) carry = 0;
    __syncthreads();
    for (int base = 0; base < NN; base += 1024) {
        int i = base + tid;
        int v = (i < NN) ? g_deg[i] : 0;
        int x = v;
        #pragma unroll
        for (int o = 1; o < 32; o <<= 1) {
            int y = __shfl_up_sync(0xffffffffu, x, o);
            if (lane >= o) x += y;
        }
        if (lane == 31) wsum[wid] = x;
        __syncthreads();
        if (wid == 0) {
            int s = wsum[lane];
            #pragma unroll
            for (int o = 1; o < 32; o <<= 1) {
                int y = __shfl_up_sync(0xffffffffu, s, o);
                if (lane >= o) s += y;
            }
            wsum[lane] = s;
        }
        __syncthreads();
        int pre = (wid > 0 ? wsum[wid-1] : 0) + carry;
        int incl = x + pre;
        if (i < NN) { g_offs[i] = incl - v; g_cursor[i] = incl - v; }
        __syncthreads();
        if (tid == 1023) carry = incl;
        __syncthreads();
    }
    if (tid == 0) g_offs[NN] = carry;
}

__global__ void scatter_kernel(const int* __restrict__ dst) {
    int e = blockIdx.x*blockDim.x + threadIdx.x;
    if (e < EE) {
        int p = atomicAdd(&g_cursor[dst[e]], 1);
        g_eidx[p] = e;
    }
}

__global__ void sort_kernel() {
    int n = blockIdx.x*blockDim.x + threadIdx.x;
    if (n >= NN) return;
    int a = g_offs[n], b = g_offs[n+1];
    for (int i = a+1; i < b; ++i) {
        int key = g_eidx[i];
        int j = i-1;
        while (j >= a && g_eidx[j] > key) { g_eidx[j+1] = g_eidx[j]; --j; }
        g_eidx[j+1] = key;
    }
}

// ---------------- layer-1 projections: q,s fp32; k,v fp16 ----------------
__global__ void proj1_kernel(const float* __restrict__ x,
    const float* __restrict__ Wq, const float* __restrict__ bq,
    const float* __restrict__ Wk, const float* __restrict__ bk,
    const float* __restrict__ Wv, const float* __restrict__ bv,
    const float* __restrict__ Ws, const float* __restrict__ bs)
{
    int warp = (blockIdx.x*blockDim.x + threadIdx.x) >> 5;
    int lane = threadIdx.x & 31;
    if (warp >= NN) return;
    float xr[9];
    #pragma unroll
    for (int t = 0; t < 9; ++t) xr[t] = __ldg(&x[warp*9 + t]);
    for (int j = lane; j < 512; j += 32) {
        float aq = __ldg(&bq[j]), ak = __ldg(&bk[j]);
        float av = __ldg(&bv[j]), as_ = __ldg(&bs[j]);
        #pragma unroll
        for (int t = 0; t < 9; ++t) {
            float xv = xr[t];
            aq  = fmaf(xv, __ldg(&Wq[t*512+j]), aq);
            ak  = fmaf(xv, __ldg(&Wk[t*512+j]), ak);
            av  = fmaf(xv, __ldg(&Wv[t*512+j]), av);
            as_ = fmaf(xv, __ldg(&Ws[t*512+j]), as_);
        }
        size_t o = (size_t)warp*512 + j;
        g_q1[o] = aq; g_s1[o] = as_;
        g_k1h[o] = __float2half_rn(ak);
        g_v1h[o] = __float2half_rn(av);
    }
}

// ---------------- layer-1 per-graph attention ----------------
__global__ void __launch_bounds__(640, 1) attn1_kernel(
    const float* __restrict__ q, const __half* __restrict__ khg,
    const __half* __restrict__ vhg, const float* __restrict__ s,
    const float* __restrict__ ea, const float* __restrict__ We,
    const int* __restrict__ srcArr, float* __restrict__ outPooled,
    __half* __restrict__ h1h)
{
    constexpr int D = 512, H = 4;
    constexpr int VPT = D / 32;
    constexpr int NU = VPT / 8;
    constexpr int C = D / H;
    extern __shared__ char smraw[];
    float*  sWeT = (float*)smraw;
    __half* kh   = (__half*)(smraw + 16*D);
    __half* vh   = (__half*)(smraw + 16*D + 40*D);
    float*  poolbuf = (float*)kh;

    int tid = threadIdx.x;
    int wid = tid >> 5, lane = tid & 31;
    int graph = blockIdx.x;
    int gbase = graph * NPG;

    for (int i = tid; i < 4*D; i += 640) {
        int c = i >> 2, t = i & 3;
        sWeT[i] = __ldg(&We[t*D + c]);
    }
    {
        const uint4* ks = (const uint4*)(khg + (size_t)gbase*D);
        const uint4* vs = (const uint4*)(vhg + (size_t)gbase*D);
        uint4* kd = (uint4*)kh;
        uint4* vd = (uint4*)vh;
        for (int i = tid; i < NPG*D/8; i += 640) { kd[i] = __ldg(ks+i); vd[i] = __ldg(vs+i); }
    }
    __syncthreads();

    int node = gbase + wid;
    int cbase = lane * VPT;
    const float4* sWe4 = (const float4*)sWeT;

    float qrf[VPT], accf[VPT];
    {
        const float4* q4 = (const float4*)(q + (size_t)node*D + cbase);
        #pragma unroll
        for (int i = 0; i < VPT/4; ++i) *(float4*)&qrf[4*i] = __ldg(q4 + i);
    }
    #pragma unroll
    for (int i = 0; i < VPT; ++i) accf[i] = 0.f;

    float4 qe = make_float4(0.f,0.f,0.f,0.f);
    #pragma unroll
    for (int i = 0; i < VPT; ++i) {
        float4 w = sWe4[cbase + i];
        qe.x = fmaf(qrf[i], w.x, qe.x);
        qe.y = fmaf(qrf[i], w.y, qe.y);
        qe.z = fmaf(qrf[i], w.z, qe.z);
        qe.w = fmaf(qrf[i], w.w, qe.w);
    }
    #pragma unroll
    for (int o = 1; o < 8; o <<= 1) {
        qe.x += __shfl_xor_sync(0xffffffffu, qe.x, o);
        qe.y += __shfl_xor_sync(0xffffffffu, qe.y, o);
        qe.z += __shfl_xor_sync(0xffffffffu, qe.z, o);
        qe.w += __shfl_xor_sync(0xffffffffu, qe.w, o);
    }

    float m = -INFINITY, den = 0.f;
    float4 wa = make_float4(0.f,0.f,0.f,0.f);
    const float invs = rsqrtf((float)C);

    int e0 = g_offs[node], e1 = g_offs[node+1];
    for (int t = e0; t < e1; ++t) {
        int e  = __ldg(&g_eidx[t]);
        int ln = __ldg(&srcArr[e]) - gbase;
        float4 a4 = __ldg((const float4*)ea + e);

        const uint4* krow = (const uint4*)(kh + ln*D + cbase);
        float p = 0.f;
        #pragma unroll
        for (int i = 0; i < NU; ++i) {
            uint4 u = krow[i];
            const __half2* h2 = (const __half2*)&u;
            #pragma unroll
            for (int j = 0; j < 4; ++j) {
                float2 f = __half22float2(h2[j]);
                p = fmaf(qrf[8*i+2*j], f.x, p);
                p = fmaf(qrf[8*i+2*j+1], f.y, p);
            }
        }
        p += __shfl_xor_sync(0xffffffffu, p, 1);
        p += __shfl_xor_sync(0xffffffffu, p, 2);
        p += __shfl_xor_sync(0xffffffffu, p, 4);
        float alpha = (p + qe.x*a4.x + qe.y*a4.y + qe.z*a4.z + qe.w*a4.w) * invs;

        float nm = fmaxf(m, alpha);
        float sc = __expf(m - nm);
        float w  = __expf(alpha - nm);
        den = den*sc + w;
        m = nm;

        const uint4* vrow = (const uint4*)(vh + ln*D + cbase);
        #pragma unroll
        for (int i = 0; i < NU; ++i) {
            uint4 u = vrow[i];
            const __half2* h2 = (const __half2*)&u;
            #pragma unroll
            for (int j = 0; j < 4; ++j) {
                float2 f = __half22float2(h2[j]);
                accf[8*i+2*j]   = accf[8*i+2*j]*sc   + w*f.x;
                accf[8*i+2*j+1] = accf[8*i+2*j+1]*sc + w*f.y;
            }
        }
        wa.x = wa.x*sc + w*a4.x; wa.y = wa.y*sc + w*a4.y;
        wa.z = wa.z*sc + w*a4.z; wa.w = wa.w*sc + w*a4.w;
    }

    float r = 1.f / (den + 1e-16f);
    float outv[VPT];
    #pragma unroll
    for (int i = 0; i < VPT; ++i) {
        float4 w = sWe4[cbase + i];
        float msg = (accf[i] + wa.x*w.x + wa.y*w.y + wa.z*w.z + wa.w*w.w) * r;
        msg += __ldg(&s[(size_t)node*D + cbase + i]);
        msg = fmaxf(msg, 0.f);
        outv[i] = msg;
    }
    {
        __half2* h4 = (__half2*)(h1h + (size_t)node*D + cbase);
        #pragma unroll
        for (int i = 0; i < VPT/2; ++i)
            h4[i] = __floats2half2_rn(outv[2*i], outv[2*i+1]);
    }

    __syncthreads();
    #pragma unroll
    for (int i = 0; i < VPT; ++i) poolbuf[wid*D + cbase + i] = outv[i];
    __syncthreads();
    for (int c = tid; c < D; c += 640) {
        float sum = 0.f;
        #pragma unroll
        for (int i = 0; i < NPG; ++i) sum += poolbuf[i*D + c];
        outPooled[(size_t)graph*512 + c] = sum * (1.f/NPG);
    }
}

// ---------------- layer-2 attention: softmax weights only -> z, r, cnt ----------------
__global__ void __launch_bounds__(640, 1) attn2_kernel(
    const float* __restrict__ q, const __half* __restrict__ khg,
    const __half* __restrict__ h1g,
    const float* __restrict__ ea, const float* __restrict__ We,
    const int* __restrict__ srcArr)
{
    constexpr int D = 1024, H = 4;
    constexpr int VPT = D / 32;
    constexpr int NU = VPT / 8;
    constexpr int C = D / H;
    constexpr int ECAP = 256;
    extern __shared__ char smraw[];
    float*  sWeT   = (float*)smraw;
    __half* kh     = (__half*)(smraw + 16*D);
    __half* h1s    = (__half*)(smraw + 16*D + 2*NPG*D);
    float*  alphaS = (float*)(smraw + 16*D + 2*NPG*D + NPG*1024);
    float*  wS     = alphaS + ECAP*H;
    int*    lnS    = (int*)(wS + ECAP*H);
    float*  cS     = (float*)(lnS + ECAP);
    int*    hasE   = (int*)(cS + NPG*H);

    int tid = threadIdx.x;
    int wid = tid >> 5, lane = tid & 31;
    int graph = blockIdx.x;
    int gbase = graph * NPG;
    int head = lane >> 3;

    for (int i = tid; i < 4*D; i += 640) {
        int c = i >> 2, t = i & 3;
        sWeT[i] = __ldg(&We[t*D + c]);
    }
    {
        const uint4* ks = (const uint4*)(khg + (size_t)gbase*D);
        uint4* kd = (uint4*)kh;
        for (int i = tid; i < NPG*D/8; i += 640) kd[i] = __ldg(ks+i);
        const uint4* hs = (const uint4*)(h1g + (size_t)gbase*512);
        uint4* hd = (uint4*)h1s;
        for (int i = tid; i < NPG*512/8; i += 640) hd[i] = __ldg(hs+i);
    }
    __syncthreads();

    int node = gbase + wid;
    int cbase = lane * VPT;
    const float4* sWe4 = (const float4*)sWeT;

    float qrf[VPT];
    {
        const float4* q4 = (const float4*)(q + (size_t)node*D + cbase);
        #pragma unroll
        for (int i = 0; i < VPT/4; ++i) *(float4*)&qrf[4*i] = __ldg(q4 + i);
    }

    float4 qe = make_float4(0.f,0.f,0.f,0.f);
    #pragma unroll
    for (int i = 0; i < VPT; ++i) {
        float4 w = sWe4[cbase + i];
        qe.x = fmaf(qrf[i], w.x, qe.x);
        qe.y = fmaf(qrf[i], w.y, qe.y);
        qe.z = fmaf(qrf[i], w.z, qe.z);
        qe.w = fmaf(qrf[i], w.w, qe.w);
    }
    #pragma unroll
    for (int o = 1; o < 8; o <<= 1) {
        qe.x += __shfl_xor_sync(0xffffffffu, qe.x, o);
        qe.y += __shfl_xor_sync(0xffffffffu, qe.y, o);
        qe.z += __shfl_xor_sync(0xffffffffu, qe.z, o);
        qe.w += __shfl_xor_sync(0xffffffffu, qe.w, o);
    }

    const float invs = rsqrtf((float)C);
    int eb = g_offs[gbase];
    int cntE = g_offs[gbase + NPG] - eb;
    int e0 = g_offs[node], e1 = g_offs[node+1];

    float m = -INFINITY, den = 0.f;
    for (int t = e0; t < e1; ++t) {
        int e  = __ldg(&g_eidx[t]);
        int ln = __ldg(&srcArr[e]) - gbase;
        float4 a4 = __ldg((const float4*)ea + e);

        const uint4* krow = (const uint4*)(kh + ln*D + cbase);
        float p = 0.f;
        #pragma unroll
        for (int i = 0; i < NU; ++i) {
            uint4 u = krow[i];
            const __half2* h2 = (const __half2*)&u;
            #pragma unroll
            for (int j = 0; j < 4; ++j) {
                float2 f = __half22float2(h2[j]);
                p = fmaf(qrf[8*i+2*j], f.x, p);
                p = fmaf(qrf[8*i+2*j+1], f.y, p);
            }
        }
        p += __shfl_xor_sync(0xffffffffu, p, 1);
        p += __shfl_xor_sync(0xffffffffu, p, 2);
        p += __shfl_xor_sync(0xffffffffu, p, 4);
        float alpha = (p + qe.x*a4.x + qe.y*a4.y + qe.z*a4.z + qe.w*a4.w) * invs;

        float nm = fmaxf(m, alpha);
        den = den*__expf(m - nm) + __expf(alpha - nm);
        m = nm;
        if ((lane & 7) == 0) alphaS[(t - eb)*H + head] = alpha;
        if (lane == 0) lnS[t - eb] = ln;
    }
    float rdn = (e1 > e0) ? 1.f/den : 0.f;
    if ((lane & 7) == 0) {
        for (int t = e0; t < e1; ++t) {
            float w = __expf(alphaS[(t - eb)*H + head] - m) * rdn;
            wS[(t - eb)*H + head] = w;
        }
    }
    if (lane == 0) hasE[wid] = (e1 > e0) ? 1 : 0;
    __syncthreads();

    if (tid < NPG*H) {
        int ln = tid >> 2, h = tid & 3;
        float c = 0.f;
        for (int i = 0; i < cntE; ++i)
            if (lnS[i] == ln) c += wS[i*H + h];
        cS[tid] = c * (1.f/NPG);
    } else if (tid < NPG*H + 16) {
        int idx = tid - NPG*H;
        int h = idx >> 2, t4 = idx & 3;
        float r = 0.f;
        for (int i = 0; i < cntE; ++i) {
            int e = __ldg(&g_eidx[eb + i]);
            r += wS[i*H + h] * __ldg(&ea[e*4 + t4]);
        }
        g_r[graph*16 + h*4 + t4] = r * (1.f/NPG);
    } else if (tid == NPG*H + 16) {
        int c = 0;
        #pragma unroll
        for (int i = 0; i < NPG; ++i) c += hasE[i];
        g_cnt[graph] = (float)c;
    }
    __syncthreads();

    for (int o = tid; o < H*512; o += 640) {
        int h = o >> 9, c = o & 511;
        float z = 0.f;
        #pragma unroll
        for (int ln = 0; ln < NPG; ++ln)
            z = fmaf(cS[ln*H + h], __half2float(h1s[ln*512 + c]), z);
        g_z[(size_t)graph*2048 + o] = z;
    }
}

// ---------------- weight transpose+fp16 converts ----------------
__global__ void wt2half_kernel(const float* __restrict__ W0, const float* __restrict__ W1) {
    __shared__ float tile[32][33];
    int z = blockIdx.z;
    const float* W = (z==0) ? W0 : W1;
    int n0 = blockIdx.x * 32, k0 = blockIdx.y * 32;
    int tx = threadIdx.x, ty = threadIdx.y;
    tile[ty][tx] = __ldg(&W[(size_t)(k0+ty)*1024 + n0 + tx]);
    __syncthreads();
    g_w2h[(size_t)z*1024*512 + (size_t)(n0+ty)*512 + k0 + tx] = __float2half_rn(tile[tx][ty]);
}

// Wfin [1280][1024] -> g_wfinh [1024][1280]
__global__ void wfin2half_kernel(const float* __restrict__ W) {
    __shared__ float tile[32][33];
    int n0 = blockIdx.x * 32, k0 = blockIdx.y * 32;
    int tx = threadIdx.x, ty = threadIdx.y;
    tile[ty][tx] = __ldg(&W[(size_t)(k0+ty)*1024 + n0 + tx]);
    __syncthreads();
    g_wfinh[(size_t)(n0+ty)*1280 + k0 + tx] = __float2half_rn(tile[tx][ty]);
}

// ---------------- f16 tensor-core GEMM (m16n8k16): q2 fp32 / k2h fp16 ----------------
__global__ void __launch_bounds__(256) gemm2_f16_kernel(
    const __half* __restrict__ Ah,
    const float* __restrict__ b0, const float* __restrict__ b1,
    float* C0, int M)
{
    __shared__ uint32_t As[2][128][20];
    __shared__ uint32_t Bs[2][128][20];

    int z = blockIdx.z;
    const __half* Bz  = g_w2h + (size_t)z*1024*512;
    const float* bias = (z==0) ? b0 : b1;

    int tid  = threadIdx.x;
    int lane = tid & 31, wid = tid >> 5;
    int wm = wid >> 2, wn = wid & 3;
    int m0 = blockIdx.x * 128, n0 = blockIdx.y * 128;
    int g = lane >> 2, t = lane & 3;

    int lm[2], lq[2];
    #pragma unroll
    for (int i = 0; i < 2; ++i) {
        int idx = tid + i*256;
        lm[i] = idx >> 2;
        lq[i] = (idx & 3) * 8;
    }

    float acc[4][4][4];
    #pragma unroll
    for (int a = 0; a < 4; ++a)
        #pragma unroll
        for (int b = 0; b < 4; ++b)
            #pragma unroll
            for (int c = 0; c < 4; ++c) acc[a][b][c] = 0.f;

    float4 pa[2], pb[2];
    const int T = 512 / 32;

    #pragma unroll
    for (int i = 0; i < 2; ++i) {
        pa[i] = (m0 + lm[i] < M)
              ? *(const float4*)(Ah + (size_t)(m0+lm[i])*512 + lq[i])
              : make_float4(0.f,0.f,0.f,0.f);
        pb[i] = *(const float4*)(Bz + (size_t)(n0+lm[i])*512 + lq[i]);
    }
    #pragma unroll
    for (int i = 0; i < 2; ++i) {
        *(float4*)&As[0][lm[i]][lq[i]>>1] = pa[i];
        *(float4*)&Bs[0][lm[i]][lq[i]>>1] = pb[i];
    }
    __syncthreads();

    for (int kt = 0; kt < T; ++kt) {
        int b = kt & 1;
        if (kt + 1 < T) {
            int ko = (kt+1) * 32;
            #pragma unroll
            for (int i = 0; i < 2; ++i) {
                pa[i] = (m0 + lm[i] < M)
                      ? *(const float4*)(Ah + (size_t)(m0+lm[i])*512 + ko + lq[i])
                      : make_float4(0.f,0.f,0.f,0.f);
                pb[i] = *(const float4*)(Bz + (size_t)(n0+lm[i])*512 + ko + lq[i]);
            }
        }

        #pragma unroll
        for (int ks = 0; ks < 2; ++ks) {
            int kb = ks * 8;
            uint32_t af[4][4], bf[4][2];
            #pragma unroll
            for (int mt = 0; mt < 4; ++mt) {
                int mb = wm*64 + mt*16;
                af[mt][0] = As[b][mb+g  ][kb+t  ];
                af[mt][1] = As[b][mb+g+8][kb+t  ];
                af[mt][2] = As[b][mb+g  ][kb+t+4];
                af[mt][3] = As[b][mb+g+8][kb+t+4];
            }
            #pragma unroll
            for (int nt = 0; nt < 4; ++nt) {
                int nb = wn*32 + nt*8;
                bf[nt][0] = Bs[b][nb+g][kb+t  ];
                bf[nt][1] = Bs[b][nb+g][kb+t+4];
            }
            #pragma unroll
            for (int mt = 0; mt < 4; ++mt)
                #pragma unroll
                for (int nt = 0; nt < 4; ++nt) {
                    asm volatile(
                        "mma.sync.aligned.m16n8k16.row.col.f32.f16.f16.f32 "
                        "{%0,%1,%2,%3}, {%4,%5,%6,%7}, {%8,%9}, {%0,%1,%2,%3};"
                        : "+f"(acc[mt][nt][0]), "+f"(acc[mt][nt][1]),
                          "+f"(acc[mt][nt][2]), "+f"(acc[mt][nt][3])
                        : "r"(af[mt][0]), "r"(af[mt][1]), "r"(af[mt][2]), "r"(af[mt][3]),
                          "r"(bf[nt][0]), "r"(bf[nt][1]));
                }
        }

        if (kt + 1 < T) {
            int nb_ = b ^ 1;
            #pragma unroll
            for (int i = 0; i < 2; ++i) {
                *(float4*)&As[nb_][lm[i]][lq[i]>>1] = pa[i];
                *(float4*)&Bs[nb_][lm[i]][lq[i]>>1] = pb[i];
            }
            __syncthreads();
        }
    }

    #pragma unroll
    for (int mt = 0; mt < 4; ++mt) {
        int r0 = m0 + wm*64 + mt*16 + g;
        #pragma unroll
        for (int nt = 0; nt < 4; ++nt) {
            int c = n0 + wn*32 + nt*8 + t*2;
            float bv0 = __ldg(&bias[c]), bv1 = __ldg(&bias[c+1]);
            float o00 = acc[mt][nt][0] + bv0, o01 = acc[mt][nt][1] + bv1;
            float o10 = acc[mt][nt][2] + bv0, o11 = acc[mt][nt][3] + bv1;
            if (z == 0) {
                if (r0 < M)     *(float2*)&C0[(size_t)r0*1024 + c]     = make_float2(o00, o01);
                if (r0 + 8 < M) *(float2*)&C0[(size_t)(r0+8)*1024 + c] = make_float2(o10, o11);
            } else {
                if (r0 < M)     *(__half2*)&g_k2h[(size_t)r0*1024 + c]     = __floats2half2_rn(o00, o01);
                if (r0 + 8 < M) *(__half2*)&g_k2h[(size_t)(r0+8)*1024 + c] = __floats2half2_rn(o10, o11);
            }
        }
    }
}

// ---------------- final-GEMM f16 tensor kernel, split-K partials ----------------
// P[z][M][1024] = g_cch[:, z*320:(z+1)*320] @ g_wfinh[:, z*320:(z+1)*320]^T
__global__ void __launch_bounds__(256) gemmfin_f16_kernel(int M)
{
    __shared__ uint32_t As[2][128][20];
    __shared__ uint32_t Bs[2][128][20];

    int zs = blockIdx.z;
    int kbase = zs * 320;
    float* P = g_fpart + (size_t)zs*BB*1024;

    int tid  = threadIdx.x;
    int lane = tid & 31, wid = tid >> 5;
    int wm = wid >> 2, wn = wid & 3;
    int m0 = blockIdx.x * 128, n0 = blockIdx.y * 128;
    int g = lane >> 2, t = lane & 3;

    int lm[2], lq[2];
    #pragma unroll
    for (int i = 0; i < 2; ++i) {
        int idx = tid + i*256;
        lm[i] = idx >> 2;
        lq[i] = (idx & 3) * 8;
    }

    float acc[4][4][4];
    #pragma unroll
    for (int a = 0; a < 4; ++a)
        #pragma unroll
        for (int b = 0; b < 4; ++b)
            #pragma unroll
            for (int c = 0; c < 4; ++c) acc[a][b][c] = 0.f;

    float4 pa[2], pb[2];
    const int T = 10;   // 320 / 32

    #pragma unroll
    for (int i = 0; i < 2; ++i) {
        pa[i] = (m0 + lm[i] < M)
              ? *(const float4*)(g_cch + (size_t)(m0+lm[i])*1280 + kbase + lq[i])
              : make_float4(0.f,0.f,0.f,0.f);
        pb[i] = *(const float4*)(g_wfinh + (size_t)(n0+lm[i])*1280 + kbase + lq[i]);
    }
    #pragma unroll
    for (int i = 0; i < 2; ++i) {
        *(float4*)&As[0][lm[i]][lq[i]>>1] = pa[i];
        *(float4*)&Bs[0][lm[i]][lq[i]>>1] = pb[i];
    }
    __syncthreads();

    for (int kt = 0; kt < T; ++kt) {
        int b = kt & 1;
        if (kt + 1 < T) {
            int ko = kbase + (kt+1) * 32;
            #pragma unroll
            for (int i = 0; i < 2; ++i) {
                pa[i] = (m0 + lm[i] < M)
                      ? *(const float4*)(g_cch + (size_t)(m0+lm[i])*1280 + ko + lq[i])
                      : make_float4(0.f,0.f,0.f,0.f);
                pb[i] = *(const float4*)(g_wfinh + (size_t)(n0+lm[i])*1280 + ko + lq[i]);
            }
        }

        #pragma unroll
        for (int ks = 0; ks < 2; ++ks) {
            int kb = ks * 8;
            uint32_t af[4][4], bf[4][2];
            #pragma unroll
            for (int mt = 0; mt < 4; ++mt) {
                int mb = wm*64 + mt*16;
                af[mt][0] = As[b][mb+g  ][kb+t  ];
                af[mt][1] = As[b][mb+g+8][kb+t  ];
                af[mt][2] = As[b][mb+g  ][kb+t+4];
                af[mt][3] = As[b][mb+g+8][kb+t+4];
            }
            #pragma unroll
            for (int nt = 0; nt < 4; ++nt) {
                int nb = wn*32 + nt*8;
                bf[nt][0] = Bs[b][nb+g][kb+t  ];
                bf[nt][1] = Bs[b][nb+g][kb+t+4];
            }
            #pragma unroll
            for (int mt = 0; mt < 4; ++mt)
                #pragma unroll
                for (int nt = 0; nt < 4; ++nt) {
                    asm volatile(
                        "mma.sync.aligned.m16n8k16.row.col.f32.f16.f16.f32 "
                        "{%0,%1,%2,%3}, {%4,%5,%6,%7}, {%8,%9}, {%0,%1,%2,%3};"
                        : "+f"(acc[mt][nt][0]), "+f"(acc[mt][nt][1]),
                          "+f"(acc[mt][nt][2]), "+f"(acc[mt][nt][3])
                        : "r"(af[mt][0]), "r"(af[mt][1]), "r"(af[mt][2]), "r"(af[mt][3]),
                          "r"(bf[nt][0]), "r"(bf[nt][1]));
                }
        }

        if (kt + 1 < T) {
            int nb_ = b ^ 1;
            #pragma unroll
            for (int i = 0; i < 2; ++i) {
                *(float4*)&As[nb_][lm[i]][lq[i]>>1] = pa[i];
                *(float4*)&Bs[nb_][lm[i]][lq[i]>>1] = pb[i];
            }
            __syncthreads();
        }
    }

    #pragma unroll
    for (int mt = 0; mt < 4; ++mt) {
        int r0 = m0 + wm*64 + mt*16 + g;
        #pragma unroll
        for (int nt = 0; nt < 4; ++nt) {
            int c = n0 + wn*32 + nt*8 + t*2;
            if (r0 < M)
                *(float2*)&P[(size_t)r0*1024 + c] = make_float2(acc[mt][nt][0], acc[mt][nt][1]);
            if (r0 + 8 < M)
                *(float2*)&P[(size_t)(r0+8)*1024 + c] = make_float2(acc[mt][nt][2], acc[mt][nt][3]);
        }
    }
}

// ---------------- fp32 64x64 GEMM: pooled skip + z@Wv2 fused (virtual K=1024) ----------
// concat[g][n] = sum_k ph1[g][k] Ws2[k][n] + sum_k z[g][hOff+k] Wv2[k][n] + bs2[n]
__global__ void __launch_bounds__(256) gemm_pool64(
    const float* __restrict__ Ws2, const float* __restrict__ Wv2,
    const float* __restrict__ bs2)
{
    __shared__ float As[16][68];
    __shared__ float Bs[16][68];
    int tid = threadIdx.x;
    int tx = tid & 15, ty = tid >> 4;
    int m0 = blockIdx.x * 64;
    int n0 = blockIdx.y * 64;
    int hOff = (n0 >> 8) * 512;
    float acc[4][4] = {};

    int arow = tid >> 2, ac4 = (tid & 3)*4;
    int brow = tid >> 4, bc4 = (tid & 15)*4;

    #pragma unroll 1
    for (int half_ = 0; half_ < 2; ++half_) {
        const float* Bm = half_ ? Wv2 : Ws2;
        for (int k0 = 0; k0 < 512; k0 += 16) {
            float4 av = make_float4(0.f,0.f,0.f,0.f);
            if (m0 + arow < BB) {
                av = half_
                   ? __ldg((const float4*)&g_z[(size_t)(m0+arow)*2048 + hOff + k0 + ac4])
                   : __ldg((const float4*)&g_ph1[(size_t)(m0+arow)*512 + k0 + ac4]);
            }
            As[ac4+0][arow] = av.x; As[ac4+1][arow] = av.y;
            As[ac4+2][arow] = av.z; As[ac4+3][arow] = av.w;
            float4 bv = __ldg((const float4*)&Bm[(size_t)(k0+brow)*1024 + n0 + bc4]);
            *(float4*)&Bs[brow][bc4] = bv;
            __syncthreads();
            #pragma unroll
            for (int kk = 0; kk < 16; ++kk) {
                float a[4], b[4];
                *(float4*)a = *(const float4*)&As[kk][ty*4];
                *(float4*)b = *(const float4*)&Bs[kk][tx*4];
                #pragma unroll
                for (int i = 0; i < 4; ++i)
                    #pragma unroll
                    for (int j = 0; j < 4; ++j)
                        acc[i][j] = fmaf(a[i], b[j], acc[i][j]);
            }
            __syncthreads();
        }
    }
    #pragma unroll
    for (int i = 0; i < 4; ++i) {
        int row = m0 + ty*4 + i;
        if (row < BB) {
            #pragma unroll
            for (int j = 0; j < 4; ++j) {
                int col = n0 + tx*4 + j;
                g_concat[(size_t)row*1280 + col] = acc[i][j] + __ldg(&bs2[col]);
            }
        }
    }
}

// ---------------- fingerprint GEMM partials: fpb @ Wfp, split-K=4 ----------------
__global__ void __launch_bounds__(256) gemm_fp64(
    const float* __restrict__ A, const float* __restrict__ Bm)
{
    __shared__ float As[16][68];
    __shared__ float Bs[16][68];
    int tid = threadIdx.x;
    int tx = tid & 15, ty = tid >> 4;
    int m0 = blockIdx.x * 64;
    int n0 = blockIdx.y * 64;
    int zs = blockIdx.z;
    int kb = zs * 512;
    float acc[4][4] = {};

    int arow = tid >> 2, ac4 = (tid & 3)*4;
    int brow = tid >> 4, bc4 = (tid & 15)*4;

    for (int k0 = kb; k0 < kb + 512; k0 += 16) {
        float4 av = make_float4(0.f,0.f,0.f,0.f);
        if (m0 + arow < BB)
            av = __ldg((const float4*)&A[(size_t)(m0+arow)*2048 + k0 + ac4]);
        As[ac4+0][arow] = av.x; As[ac4+1][arow] = av.y;
        As[ac4+2][arow] = av.z; As[ac4+3][arow] = av.w;
        float4 bv = __ldg((const float4*)&Bm[(size_t)(k0+brow)*256 + n0 + bc4]);
        *(float4*)&Bs[brow][bc4] = bv;
        __syncthreads();
        #pragma unroll
        for (int kk = 0; kk < 16; ++kk) {
            float a[4], b[4];
            *(float4*)a = *(const float4*)&As[kk][ty*4];
            *(float4*)b = *(const float4*)&Bs[kk][tx*4];
            #pragma unroll
            for (int i = 0; i < 4; ++i)
                #pragma unroll
                for (int j = 0; j < 4; ++j)
                    acc[i][j] = fmaf(a[i], b[j], acc[i][j]);
        }
        __syncthreads();
    }
    #pragma unroll
    for (int i = 0; i < 4; ++i) {
        int row = m0 + ty*4 + i;
        if (row < BB) {
            #pragma unroll
            for (int j = 0; j < 4; ++j) {
                int col = n0 + tx*4 + j;
                g_fppart[(size_t)zs*BB*256 + (size_t)row*256 + col] = acc[i][j];
            }
        }
    }
}

// ---------------- epilogue: edge term + bv2 term into concat ----------------
__global__ void eps_kernel(const float* __restrict__ We2, const float* __restrict__ bv2)
{
    int g = blockIdx.x;
    int c = blockIdx.y*256 + threadIdx.x;
    int h = c >> 8;
    float acc = g_cnt[g] * (1.f/NPG) * __ldg(&bv2[c]);
    #pragma unroll
    for (int t = 0; t < 4; ++t)
        acc = fmaf(g_r[g*16 + h*4 + t], __ldg(&We2[t*1024 + c]), acc);
    g_concat[(size_t)g*1280 + c] += acc;
}

// ---------------- concat -> fp16 (folds fp-partial reduce + bfp) ----------------
__global__ void convert_cc_kernel(const float* __restrict__ bfp)
{
    int i = blockIdx.x*blockDim.x + threadIdx.x;   // over BB*640 half2s
    if (i >= BB*640) return;
    int row = i / 640;
    int c = (i % 640) * 2;
    float v0, v1;
    if (c < 1024) {
        v0 = g_concat[(size_t)row*1280 + c];
        v1 = g_concat[(size_t)row*1280 + c + 1];
    } else {
        int cc = c - 1024;
        v0 = __ldg(&bfp[cc]);   v1 = __ldg(&bfp[cc+1]);
        #pragma unroll
        for (int zp = 0; zp < 4; ++zp) {
            v0 += g_fppart[(size_t)zp*BB*256 + (size_t)row*256 + cc];
            v1 += g_fppart[(size_t)zp*BB*256 + (size_t)row*256 + cc + 1];
        }
        g_concat[(size_t)row*1280 + c]   = v0;   // keep fp32 copy coherent (unused later)
        g_concat[(size_t)row*1280 + c+1] = v1;
    }
    ((__half2*)g_cch)[i] = __floats2half2_rn(v0, v1);
}

// ---------------- final reduce: d_out = bfin + sum of 4 partials ----------------
__global__ void reduce_fin_kernel(const float* __restrict__ bfin, float* __restrict__ out)
{
    int i = blockIdx.x*blockDim.x + threadIdx.x;   // over BB*256 float4s
    if (i >= BB*256) return;
    int c4 = (i & 255) * 4;
    float4 acc = __ldg((const float4*)&bfin[c4]);
    #pragma unroll
    for (int zp = 0; zp < 4; ++zp) {
        float4 p = *(const float4*)&g_fpart[(size_t)zp*BB*1024 + (size_t)i*4];
        acc.x += p.x; acc.y += p.y; acc.z += p.z; acc.w += p.w;
    }
    ((float4*)out)[i] = acc;
}

// ---------------- launch ----------------
extern "C" void kernel_launch(void* const* d_in, const int* in_sizes, int n_in,
                              void* d_out, int out_size)
{
    const float* x    = (const float*)d_in[0];
    const int*   ei   = (const int*)  d_in[1];
    const float* ea   = (const float*)d_in[2];
    const float* fpb  = (const float*)d_in[4];
    const float *Wq1=(const float*)d_in[5],  *bq1=(const float*)d_in[6];
    const float *Wk1=(const float*)d_in[7],  *bk1=(const float*)d_in[8];
    const float *Wv1=(const float*)d_in[9],  *bv1=(const float*)d_in[10];
    const float *We1=(const float*)d_in[11];
    const float *Ws1=(const float*)d_in[12], *bs1=(const float*)d_in[13];
    const float *Wq2=(const float*)d_in[14], *bq2=(const float*)d_in[15];
    const float *Wk2=(const float*)d_in[16], *bk2=(const float*)d_in[17];
    const float *Wv2=(const float*)d_in[18], *bv2=(const float*)d_in[19];
    const float *We2=(const float*)d_in[20];
    const float *Ws2=(const float*)d_in[21], *bs2=(const float*)d_in[22];
    const float *Wfp=(const float*)d_in[23], *bfp=(const float*)d_in[24];
    const float *Wfin=(const float*)d_in[25],*bfin=(const float*)d_in[26];

    const int* srcArr = ei;
    const int* dstArr = ei + EE;

    float *q1,*s1,*ph1,*q2;
    __half *k1h,*v1h,*h1h,*k2h;
    cudaGetSymbolAddress((void**)&q1, g_q1);
    cudaGetSymbolAddress((void**)&s1, g_s1);
    cudaGetSymbolAddress((void**)&k1h, g_k1h);
    cudaGetSymbolAddress((void**)&v1h, g_v1h);
    cudaGetSymbolAddress((void**)&h1h, g_h1h);
    cudaGetSymbolAddress((void**)&ph1, g_ph1);
    cudaGetSymbolAddress((void**)&q2, g_q2);
    cudaGetSymbolAddress((void**)&k2h, g_k2h);

    const int SM1 = 96*512;
    const int SM2 = 16*1024 + 2*NPG*1024 + NPG*1024
                  + 256*4*4*2 + 256*4 + NPG*4*4 + NPG*4 + 64;
    cudaFuncSetAttribute(attn1_kernel, cudaFuncAttributeMaxDynamicSharedMemorySize, SM1);
    cudaFuncSetAttribute(attn2_kernel, cudaFuncAttributeMaxDynamicSharedMemorySize, SM2);

    // CSR build
    zero_deg_kernel<<<(NN+255)/256, 256>>>();
    hist_kernel<<<(EE+255)/256, 256>>>(dstArr);
    scan_kernel<<<1, 1024>>>();
    scatter_kernel<<<(EE+255)/256, 256>>>(dstArr);
    sort_kernel<<<(NN+255)/256, 256>>>();

    // weight converts (independent; issue early)
    wt2half_kernel<<<dim3(32, 16, 2), dim3(32, 32)>>>(Wq2, Wk2);
    wfin2half_kernel<<<dim3(32, 40), dim3(32, 32)>>>(Wfin);

    // fingerprint GEMM partials (independent of the graph path)
    gemm_fp64<<<dim3((BB+63)/64, 4, 4), 256>>>(fpb, Wfp);

    // layer 1
    proj1_kernel<<<(NN*32+255)/256, 256>>>(x, Wq1,bq1, Wk1,bk1, Wv1,bv1, Ws1,bs1);
    attn1_kernel<<<BB, 640, SM1>>>(q1, k1h, v1h, s1, ea, We1, srcArr, ph1, h1h);

    // layer-2 q,k projections on tensor cores
    {
        dim3 grid((NN+127)/128, 1024/128, 2);
        gemm2_f16_kernel<<<grid, 256>>>(h1h, bq2, bk2, q2, NN);
    }

    // layer-2 attention weights -> z, r, cnt
    attn2_kernel<<<BB, 640, SM2>>>(q2, k2h, h1h, ea, We2, srcArr);

    // concat[:, :1024] = ph1@Ws2 + z@Wv2(per-head) + bs2, then edge/bias epilogue
    gemm_pool64<<<dim3((BB+63)/64, 1024/64), 256>>>(Ws2, Wv2, bs2);
    eps_kernel<<<dim3(BB, 4), 256>>>(We2, bv2);

    // fp16 convert (also reduces fingerprint partials into cols 1024:1280)
    convert_cc_kernel<<<(BB*640+255)/256, 256>>>(bfp);

    // final GEMM on tensor cores, split-K=4, then reduce
    gemmfin_f16_kernel<<<dim3((BB+127)/128, 1024/128, 4), 256>>>(BB);
    reduce_fin_kernel<<<(BB*256+255)/256, 256>>>(bfin, (float*)d_out);
}

// round 11
// speedup vs baseline: 3.3272x; 1.0347x over previous
#include <cuda_runtime.h>
#include <cuda_fp16.h>
#include <math.h>
#include <stdint.h>

#define NN 24000
#define EE 96000
#define BB 1200
#define NPG 20

// ---------------- device scratch ----------------
__device__ float  g_q1[NN*512];
__device__ float  g_s1[NN*512];
__device__ __half g_k1h[NN*512];
__device__ __half g_v1h[NN*512];
__device__ __half g_h1h[NN*512];
__device__ float  g_ph1[BB*512];
__device__ float  g_q2[NN*1024];
__device__ __half g_k2h[NN*1024];
__device__ float  g_z[BB*2048];
__device__ float  g_r[BB*16];
__device__ float  g_cnt[BB];
__device__ float  g_concat[BB*1280];
__device__ int    g_deg[NN];
__device__ int    g_offs[NN+1];
__device__ int    g_cursor[NN];
__device__ int    g_eidx[EE];
__device__ __half g_w2h[2*1024*512];
__device__ __half g_wfinh[1024*1280];
__device__ __half g_cch[BB*1280];
__device__ float  g_fppart[4*BB*256];
__device__ float  g_fpart[4*BB*1024];

__device__ __forceinline__ void cpa16(void* dst, const void* src, bool pred) {
    uint32_t d = (uint32_t)__cvta_generic_to_shared(dst);
    int sz = pred ? 16 : 0;
    asm volatile("cp.async.cg.shared.global [%0], [%1], 16, %2;\n"
                 :: "r"(d), "l"(src), "r"(sz));
}

// ---------------- CSR build ----------------
__global__ void zero_deg_kernel() {
    int i = blockIdx.x*blockDim.x + threadIdx.x;
    if (i < NN) g_deg[i] = 0;
}

__global__ void hist_kernel(const int* __restrict__ dst) {
    int e = blockIdx.x*blockDim.x + threadIdx.x;
    if (e < EE) atomicAdd(&g_deg[dst[e]], 1);
}

__global__ void scan_kernel() {
    __shared__ int wsum[32];
    __shared__ int carry;
    int tid = threadIdx.x;
    int lane = tid & 31, wid = tid >> 5;
    if (tid == 0) carry = 0;
    __syncthreads();
    for (int base = 0; base < NN; base += 1024) {
        int i = base + tid;
        int v = (i < NN) ? g_deg[i] : 0;
        int x = v;
        #pragma unroll
        for (int o = 1; o < 32; o <<= 1) {
            int y = __shfl_up_sync(0xffffffffu, x, o);
            if (lane >= o) x += y;
        }
        if (lane == 31) wsum[wid] = x;
        __syncthreads();
        if (wid == 0) {
            int s = wsum[lane];
            #pragma unroll
            for (int o = 1; o < 32; o <<= 1) {
                int y = __shfl_up_sync(0xffffffffu, s, o);
                if (lane >= o) s += y;
            }
            wsum[lane] = s;
        }
        __syncthreads();
        int pre = (wid > 0 ? wsum[wid-1] : 0) + carry;
        int incl = x + pre;
        if (i < NN) { g_offs[i] = incl - v; g_cursor[i] = incl - v; }
        __syncthreads();
        if (tid == 1023) carry = incl;
        __syncthreads();
    }
    if (tid == 0) g_offs[NN] = carry;
}

__global__ void scatter_kernel(const int* __restrict__ dst) {
    int e = blockIdx.x*blockDim.x + threadIdx.x;
    if (e < EE) {
        int p = atomicAdd(&g_cursor[dst[e]], 1);
        g_eidx[p] = e;
    }
}

__global__ void sort_kernel() {
    int n = blockIdx.x*blockDim.x + threadIdx.x;
    if (n >= NN) return;
    int a = g_offs[n], b = g_offs[n+1];
    for (int i = a+1; i < b; ++i) {
        int key = g_eidx[i];
        int j = i-1;
        while (j >= a && g_eidx[j] > key) { g_eidx[j+1] = g_eidx[j]; --j; }
        g_eidx[j+1] = key;
    }
}

// ---------------- layer-1 projections ----------------
__global__ void proj1_kernel(const float* __restrict__ x,
    const float* __restrict__ Wq, const float* __restrict__ bq,
    const float* __restrict__ Wk, const float* __restrict__ bk,
    const float* __restrict__ Wv, const float* __restrict__ bv,
    const float* __restrict__ Ws, const float* __restrict__ bs)
{
    int warp = (blockIdx.x*blockDim.x + threadIdx.x) >> 5;
    int lane = threadIdx.x & 31;
    if (warp >= NN) return;
    float xr[9];
    #pragma unroll
    for (int t = 0; t < 9; ++t) xr[t] = __ldg(&x[warp*9 + t]);
    for (int j = lane; j < 512; j += 32) {
        float aq = __ldg(&bq[j]), ak = __ldg(&bk[j]);
        float av = __ldg(&bv[j]), as_ = __ldg(&bs[j]);
        #pragma unroll
        for (int t = 0; t < 9; ++t) {
            float xv = xr[t];
            aq  = fmaf(xv, __ldg(&Wq[t*512+j]), aq);
            ak  = fmaf(xv, __ldg(&Wk[t*512+j]), ak);
            av  = fmaf(xv, __ldg(&Wv[t*512+j]), av);
            as_ = fmaf(xv, __ldg(&Ws[t*512+j]), as_);
        }
        size_t o = (size_t)warp*512 + j;
        g_q1[o] = aq; g_s1[o] = as_;
        g_k1h[o] = __float2half_rn(ak);
        g_v1h[o] = __float2half_rn(av);
    }
}

// ---------------- layer-1 per-graph attention ----------------
__global__ void __launch_bounds__(640, 1) attn1_kernel(
    const float* __restrict__ q, const __half* __restrict__ khg,
    const __half* __restrict__ vhg, const float* __restrict__ s,
    const float* __restrict__ ea, const float* __restrict__ We,
    const int* __restrict__ srcArr, float* __restrict__ outPooled,
    __half* __restrict__ h1h)
{
    constexpr int D = 512, H = 4;
    constexpr int VPT = D / 32;
    constexpr int NU = VPT / 8;
    constexpr int C = D / H;
    extern __shared__ char smraw[];
    float*  sWeT = (float*)smraw;
    __half* kh   = (__half*)(smraw + 16*D);
    __half* vh   = (__half*)(smraw + 16*D + 40*D);
    float*  poolbuf = (float*)kh;

    int tid = threadIdx.x;
    int wid = tid >> 5, lane = tid & 31;
    int graph = blockIdx.x;
    int gbase = graph * NPG;

    for (int i = tid; i < 4*D; i += 640) {
        int c = i >> 2, t = i & 3;
        sWeT[i] = __ldg(&We[t*D + c]);
    }
    {
        const uint4* ks = (const uint4*)(khg + (size_t)gbase*D);
        const uint4* vs = (const uint4*)(vhg + (size_t)gbase*D);
        uint4* kd = (uint4*)kh;
        uint4* vd = (uint4*)vh;
        for (int i = tid; i < NPG*D/8; i += 640) { kd[i] = __ldg(ks+i); vd[i] = __ldg(vs+i); }
    }
    __syncthreads();

    int node = gbase + wid;
    int cbase = lane * VPT;
    const float4* sWe4 = (const float4*)sWeT;

    float qrf[VPT], accf[VPT];
    {
        const float4* q4 = (const float4*)(q + (size_t)node*D + cbase);
        #pragma unroll
        for (int i = 0; i < VPT/4; ++i) *(float4*)&qrf[4*i] = __ldg(q4 + i);
    }
    #pragma unroll
    for (int i = 0; i < VPT; ++i) accf[i] = 0.f;

    float4 qe = make_float4(0.f,0.f,0.f,0.f);
    #pragma unroll
    for (int i = 0; i < VPT; ++i) {
        float4 w = sWe4[cbase + i];
        qe.x = fmaf(qrf[i], w.x, qe.x);
        qe.y = fmaf(qrf[i], w.y, qe.y);
        qe.z = fmaf(qrf[i], w.z, qe.z);
        qe.w = fmaf(qrf[i], w.w, qe.w);
    }
    #pragma unroll
    for (int o = 1; o < 8; o <<= 1) {
        qe.x += __shfl_xor_sync(0xffffffffu, qe.x, o);
        qe.y += __shfl_xor_sync(0xffffffffu, qe.y, o);
        qe.z += __shfl_xor_sync(0xffffffffu, qe.z, o);
        qe.w += __shfl_xor_sync(0xffffffffu, qe.w, o);
    }

    float m = -INFINITY, den = 0.f;
    float4 wa = make_float4(0.f,0.f,0.f,0.f);
    const float invs = rsqrtf((float)C);

    int e0 = g_offs[node], e1 = g_offs[node+1];
    for (int t = e0; t < e1; ++t) {
        int e  = __ldg(&g_eidx[t]);
        int ln = __ldg(&srcArr[e]) - gbase;
        float4 a4 = __ldg((const float4*)ea + e);

        const uint4* krow = (const uint4*)(kh + ln*D + cbase);
        float p = 0.f;
        #pragma unroll
        for (int i = 0; i < NU; ++i) {
            uint4 u = krow[i];
            const __half2* h2 = (const __half2*)&u;
            #pragma unroll
            for (int j = 0; j < 4; ++j) {
                float2 f = __half22float2(h2[j]);
                p = fmaf(qrf[8*i+2*j], f.x, p);
                p = fmaf(qrf[8*i+2*j+1], f.y, p);
            }
        }
        p += __shfl_xor_sync(0xffffffffu, p, 1);
        p += __shfl_xor_sync(0xffffffffu, p, 2);
        p += __shfl_xor_sync(0xffffffffu, p, 4);
        float alpha = (p + qe.x*a4.x + qe.y*a4.y + qe.z*a4.z + qe.w*a4.w) * invs;

        float nm = fmaxf(m, alpha);
        float sc = __expf(m - nm);
        float w  = __expf(alpha - nm);
        den = den*sc + w;
        m = nm;

        const uint4* vrow = (const uint4*)(vh + ln*D + cbase);
        #pragma unroll
        for (int i = 0; i < NU; ++i) {
            uint4 u = vrow[i];
            const __half2* h2 = (const __half2*)&u;
            #pragma unroll
            for (int j = 0; j < 4; ++j) {
                float2 f = __half22float2(h2[j]);
                accf[8*i+2*j]   = accf[8*i+2*j]*sc   + w*f.x;
                accf[8*i+2*j+1] = accf[8*i+2*j+1]*sc + w*f.y;
            }
        }
        wa.x = wa.x*sc + w*a4.x; wa.y = wa.y*sc + w*a4.y;
        wa.z = wa.z*sc + w*a4.z; wa.w = wa.w*sc + w*a4.w;
    }

    float r = 1.f / (den + 1e-16f);
    float outv[VPT];
    #pragma unroll
    for (int i = 0; i < VPT; ++i) {
        float4 w = sWe4[cbase + i];
        float msg = (accf[i] + wa.x*w.x + wa.y*w.y + wa.z*w.z + wa.w*w.w) * r;
        msg += __ldg(&s[(size_t)node*D + cbase + i]);
        msg = fmaxf(msg, 0.f);
        outv[i] = msg;
    }
    {
        __half2* h4 = (__half2*)(h1h + (size_t)node*D + cbase);
        #pragma unroll
        for (int i = 0; i < VPT/2; ++i)
            h4[i] = __floats2half2_rn(outv[2*i], outv[2*i+1]);
    }

    __syncthreads();
    #pragma unroll
    for (int i = 0; i < VPT; ++i) poolbuf[wid*D + cbase + i] = outv[i];
    __syncthreads();
    for (int c = tid; c < D; c += 640) {
        float sum = 0.f;
        #pragma unroll
        for (int i = 0; i < NPG; ++i) sum += poolbuf[i*D + c];
        outPooled[(size_t)graph*512 + c] = sum * (1.f/NPG);
    }
}

// ---------------- layer-2 attention: softmax weights only -> z, r, cnt ----------------
__global__ void __launch_bounds__(640, 1) attn2_kernel(
    const float* __restrict__ q, const __half* __restrict__ khg,
    const __half* __restrict__ h1g,
    const float* __restrict__ ea, const float* __restrict__ We,
    const int* __restrict__ srcArr)
{
    constexpr int D = 1024, H = 4;
    constexpr int VPT = D / 32;
    constexpr int NU = VPT / 8;
    constexpr int C = D / H;
    constexpr int ECAP = 256;
    extern __shared__ char smraw[];
    float*  sWeT   = (float*)smraw;
    __half* kh     = (__half*)(smraw + 16*D);
    __half* h1s    = (__half*)(smraw + 16*D + 2*NPG*D);
    float*  alphaS = (float*)(smraw + 16*D + 2*NPG*D + NPG*1024);
    float*  wS     = alphaS + ECAP*H;
    int*    lnS    = (int*)(wS + ECAP*H);
    float*  cS     = (float*)(lnS + ECAP);
    int*    hasE   = (int*)(cS + NPG*H);

    int tid = threadIdx.x;
    int wid = tid >> 5, lane = tid & 31;
    int graph = blockIdx.x;
    int gbase = graph * NPG;
    int head = lane >> 3;

    for (int i = tid; i < 4*D; i += 640) {
        int c = i >> 2, t = i & 3;
        sWeT[i] = __ldg(&We[t*D + c]);
    }
    {
        const uint4* ks = (const uint4*)(khg + (size_t)gbase*D);
        uint4* kd = (uint4*)kh;
        for (int i = tid; i < NPG*D/8; i += 640) kd[i] = __ldg(ks+i);
        const uint4* hs = (const uint4*)(h1g + (size_t)gbase*512);
        uint4* hd = (uint4*)h1s;
        for (int i = tid; i < NPG*512/8; i += 640) hd[i] = __ldg(hs+i);
    }
    __syncthreads();

    int node = gbase + wid;
    int cbase = lane * VPT;
    const float4* sWe4 = (const float4*)sWeT;

    float qrf[VPT];
    {
        const float4* q4 = (const float4*)(q + (size_t)node*D + cbase);
        #pragma unroll
        for (int i = 0; i < VPT/4; ++i) *(float4*)&qrf[4*i] = __ldg(q4 + i);
    }

    float4 qe = make_float4(0.f,0.f,0.f,0.f);
    #pragma unroll
    for (int i = 0; i < VPT; ++i) {
        float4 w = sWe4[cbase + i];
        qe.x = fmaf(qrf[i], w.x, qe.x);
        qe.y = fmaf(qrf[i], w.y, qe.y);
        qe.z = fmaf(qrf[i], w.z, qe.z);
        qe.w = fmaf(qrf[i], w.w, qe.w);
    }
    #pragma unroll
    for (int o = 1; o < 8; o <<= 1) {
        qe.x += __shfl_xor_sync(0xffffffffu, qe.x, o);
        qe.y += __shfl_xor_sync(0xffffffffu, qe.y, o);
        qe.z += __shfl_xor_sync(0xffffffffu, qe.z, o);
        qe.w += __shfl_xor_sync(0xffffffffu, qe.w, o);
    }

    const float invs = rsqrtf((float)C);
    int eb = g_offs[gbase];
    int cntE = g_offs[gbase + NPG] - eb;
    int e0 = g_offs[node], e1 = g_offs[node+1];

    float m = -INFINITY, den = 0.f;
    for (int t = e0; t < e1; ++t) {
        int e  = __ldg(&g_eidx[t]);
        int ln = __ldg(&srcArr[e]) - gbase;
        float4 a4 = __ldg((const float4*)ea + e);

        const uint4* krow = (const uint4*)(kh + ln*D + cbase);
        float p = 0.f;
        #pragma unroll
        for (int i = 0; i < NU; ++i) {
            uint4 u = krow[i];
            const __half2* h2 = (const __half2*)&u;
            #pragma unroll
            for (int j = 0; j < 4; ++j) {
                float2 f = __half22float2(h2[j]);
                p = fmaf(qrf[8*i+2*j], f.x, p);
                p = fmaf(qrf[8*i+2*j+1], f.y, p);
            }
        }
        p += __shfl_xor_sync(0xffffffffu, p, 1);
        p += __shfl_xor_sync(0xffffffffu, p, 2);
        p += __shfl_xor_sync(0xffffffffu, p, 4);
        float alpha = (p + qe.x*a4.x + qe.y*a4.y + qe.z*a4.z + qe.w*a4.w) * invs;

        float nm = fmaxf(m, alpha);
        den = den*__expf(m - nm) + __expf(alpha - nm);
        m = nm;
        if ((lane & 7) == 0) alphaS[(t - eb)*H + head] = alpha;
        if (lane == 0) lnS[t - eb] = ln;
    }
    float rdn = (e1 > e0) ? 1.f/den : 0.f;
    if ((lane & 7) == 0) {
        for (int t = e0; t < e1; ++t) {
            float w = __expf(alphaS[(t - eb)*H + head] - m) * rdn;
            wS[(t - eb)*H + head] = w;
        }
    }
    if (lane == 0) hasE[wid] = (e1 > e0) ? 1 : 0;
    __syncthreads();

    if (tid < NPG*H) {
        int ln = tid >> 2, h = tid & 3;
        float c = 0.f;
        for (int i = 0; i < cntE; ++i)
            if (lnS[i] == ln) c += wS[i*H + h];
        cS[tid] = c * (1.f/NPG);
    } else if (tid < NPG*H + 16) {
        int idx = tid - NPG*H;
        int h = idx >> 2, t4 = idx & 3;
        float r = 0.f;
        for (int i = 0; i < cntE; ++i) {
            int e = __ldg(&g_eidx[eb + i]);
            r += wS[i*H + h] * __ldg(&ea[e*4 + t4]);
        }
        g_r[graph*16 + h*4 + t4] = r * (1.f/NPG);
    } else if (tid == NPG*H + 16) {
        int c = 0;
        #pragma unroll
        for (int i = 0; i < NPG; ++i) c += hasE[i];
        g_cnt[graph] = (float)c;
    }
    __syncthreads();

    for (int o = tid; o < H*512; o += 640) {
        int h = o >> 9, c = o & 511;
        float z = 0.f;
        #pragma unroll
        for (int ln = 0; ln < NPG; ++ln)
            z = fmaf(cS[ln*H + h], __half2float(h1s[ln*512 + c]), z);
        g_z[(size_t)graph*2048 + o] = z;
    }
}

// ---------------- weight transpose+fp16 converts ----------------
__global__ void wt2half_kernel(const float* __restrict__ W0, const float* __restrict__ W1) {
    __shared__ float tile[32][33];
    int z = blockIdx.z;
    const float* W = (z==0) ? W0 : W1;
    int n0 = blockIdx.x * 32, k0 = blockIdx.y * 32;
    int tx = threadIdx.x, ty = threadIdx.y;
    tile[ty][tx] = __ldg(&W[(size_t)(k0+ty)*1024 + n0 + tx]);
    __syncthreads();
    g_w2h[(size_t)z*1024*512 + (size_t)(n0+ty)*512 + k0 + tx] = __float2half_rn(tile[tx][ty]);
}

__global__ void wfin2half_kernel(const float* __restrict__ W) {
    __shared__ float tile[32][33];
    int n0 = blockIdx.x * 32, k0 = blockIdx.y * 32;
    int tx = threadIdx.x, ty = threadIdx.y;
    tile[ty][tx] = __ldg(&W[(size_t)(k0+ty)*1024 + n0 + tx]);
    __syncthreads();
    g_wfinh[(size_t)(n0+ty)*1280 + k0 + tx] = __float2half_rn(tile[tx][ty]);
}

// ---------------- f16 tensor-core GEMM (m16n8k16): q2 fp32 / k2h fp16 ----------------
// 3-stage cp.async pipeline, occupancy forced to 2 CTAs/SM.
__global__ void __launch_bounds__(256, 2) gemm2_f16_kernel(
    const __half* __restrict__ Ah,
    const float* __restrict__ b0, const float* __restrict__ b1,
    float* C0, int M)
{
    __shared__ __align__(16) uint32_t As[3][128][20];
    __shared__ __align__(16) uint32_t Bs[3][128][20];

    int z = blockIdx.z;
    const __half* Bz  = g_w2h + (size_t)z*1024*512;
    const float* bias = (z==0) ? b0 : b1;

    int tid  = threadIdx.x;
    int lane = tid & 31, wid = tid >> 5;
    int wm = wid >> 2, wn = wid & 3;
    int m0 = blockIdx.x * 128, n0 = blockIdx.y * 128;
    int g = lane >> 2, t = lane & 3;

    int lm[2], lq[2];
    #pragma unroll
    for (int i = 0; i < 2; ++i) {
        int idx = tid + i*256;
        lm[i] = idx >> 2;
        lq[i] = (idx & 3) * 8;
    }

    float acc[4][4][4];
    #pragma unroll
    for (int a = 0; a < 4; ++a)
        #pragma unroll
        for (int b = 0; b < 4; ++b)
            #pragma unroll
            for (int c = 0; c < 4; ++c) acc[a][b][c] = 0.f;

    const int T = 512 / 32;

    // prologue: tiles 0 and 1
    #pragma unroll
    for (int pt = 0; pt < 2; ++pt) {
        int ko = pt * 32;
        #pragma unroll
        for (int i = 0; i < 2; ++i) {
            cpa16(&As[pt][lm[i]][lq[i]>>1],
                  Ah + (size_t)(m0+lm[i])*512 + ko + lq[i], (m0+lm[i]) < M);
            cpa16(&Bs[pt][lm[i]][lq[i]>>1],
                  Bz + (size_t)(n0+lm[i])*512 + ko + lq[i], true);
        }
        asm volatile("cp.async.commit_group;\n");
    }

    for (int kt = 0; kt < T; ++kt) {
        int sl = kt % 3;
        asm volatile("cp.async.wait_group 1;\n");
        __syncthreads();

        // issue tile kt+2 into slot (kt+2)%3 (nobody reads it this iteration)
        if (kt + 2 < T) {
            int ns = (kt + 2) % 3;
            int ko = (kt + 2) * 32;
            #pragma unroll
            for (int i = 0; i < 2; ++i) {
                cpa16(&As[ns][lm[i]][lq[i]>>1],
                      Ah + (size_t)(m0+lm[i])*512 + ko + lq[i], (m0+lm[i]) < M);
                cpa16(&Bs[ns][lm[i]][lq[i]>>1],
                      Bz + (size_t)(n0+lm[i])*512 + ko + lq[i], true);
            }
        }
        asm volatile("cp.async.commit_group;\n");   // empty group in the tail keeps invariant

        #pragma unroll
        for (int ks = 0; ks < 2; ++ks) {
            int kb = ks * 8;
            uint32_t af[4][4], bf[4][2];
            #pragma unroll
            for (int mt = 0; mt < 4; ++mt) {
                int mb = wm*64 + mt*16;
                af[mt][0] = As[sl][mb+g  ][kb+t  ];
                af[mt][1] = As[sl][mb+g+8][kb+t  ];
                af[mt][2] = As[sl][mb+g  ][kb+t+4];
                af[mt][3] = As[sl][mb+g+8][kb+t+4];
            }
            #pragma unroll
            for (int nt = 0; nt < 4; ++nt) {
                int nb = wn*32 + nt*8;
                bf[nt][0] = Bs[sl][nb+g][kb+t  ];
                bf[nt][1] = Bs[sl][nb+g][kb+t+4];
            }
            #pragma unroll
            for (int mt = 0; mt < 4; ++mt)
                #pragma unroll
                for (int nt = 0; nt < 4; ++nt) {
                    asm volatile(
                        "mma.sync.aligned.m16n8k16.row.col.f32.f16.f16.f32 "
                        "{%0,%1,%2,%3}, {%4,%5,%6,%7}, {%8,%9}, {%0,%1,%2,%3};"
                        : "+f"(acc[mt][nt][0]), "+f"(acc[mt][nt][1]),
                          "+f"(acc[mt][nt][2]), "+f"(acc[mt][nt][3])
                        : "r"(af[mt][0]), "r"(af[mt][1]), "r"(af[mt][2]), "r"(af[mt][3]),
                          "r"(bf[nt][0]), "r"(bf[nt][1]));
                }
        }
    }

    #pragma unroll
    for (int mt = 0; mt < 4; ++mt) {
        int r0 = m0 + wm*64 + mt*16 + g;
        #pragma unroll
        for (int nt = 0; nt < 4; ++nt) {
            int c = n0 + wn*32 + nt*8 + t*2;
            float bv0 = __ldg(&bias[c]), bv1 = __ldg(&bias[c+1]);
            float o00 = acc[mt][nt][0] + bv0, o01 = acc[mt][nt][1] + bv1;
            float o10 = acc[mt][nt][2] + bv0, o11 = acc[mt][nt][3] + bv1;
            if (z == 0) {
                if (r0 < M)     *(float2*)&C0[(size_t)r0*1024 + c]     = make_float2(o00, o01);
                if (r0 + 8 < M) *(float2*)&C0[(size_t)(r0+8)*1024 + c] = make_float2(o10, o11);
            } else {
                if (r0 < M)     *(__half2*)&g_k2h[(size_t)r0*1024 + c]     = __floats2half2_rn(o00, o01);
                if (r0 + 8 < M) *(__half2*)&g_k2h[(size_t)(r0+8)*1024 + c] = __floats2half2_rn(o10, o11);
            }
        }
    }
}

// ---------------- final-GEMM f16 tensor kernel, split-K partials ----------------
__global__ void __launch_bounds__(256) gemmfin_f16_kernel(int M)
{
    __shared__ uint32_t As[2][128][20];
    __shared__ uint32_t Bs[2][128][20];

    int zs = blockIdx.z;
    int kbase = zs * 320;
    float* P = g_fpart + (size_t)zs*BB*1024;

    int tid  = threadIdx.x;
    int lane = tid & 31, wid = tid >> 5;
    int wm = wid >> 2, wn = wid & 3;
    int m0 = blockIdx.x * 128, n0 = blockIdx.y * 128;
    int g = lane >> 2, t = lane & 3;

    int lm[2], lq[2];
    #pragma unroll
    for (int i = 0; i < 2; ++i) {
        int idx = tid + i*256;
        lm[i] = idx >> 2;
        lq[i] = (idx & 3) * 8;
    }

    float acc[4][4][4];
    #pragma unroll
    for (int a = 0; a < 4; ++a)
        #pragma unroll
        for (int b = 0; b < 4; ++b)
            #pragma unroll
            for (int c = 0; c < 4; ++c) acc[a][b][c] = 0.f;

    float4 pa[2], pb[2];
    const int T = 10;

    #pragma unroll
    for (int i = 0; i < 2; ++i) {
        pa[i] = (m0 + lm[i] < M)
              ? *(const float4*)(g_cch + (size_t)(m0+lm[i])*1280 + kbase + lq[i])
              : make_float4(0.f,0.f,0.f,0.f);
        pb[i] = *(const float4*)(g_wfinh + (size_t)(n0+lm[i])*1280 + kbase + lq[i]);
    }
    #pragma unroll
    for (int i = 0; i < 2; ++i) {
        *(float4*)&As[0][lm[i]][lq[i]>>1] = pa[i];
        *(float4*)&Bs[0][lm[i]][lq[i]>>1] = pb[i];
    }
    __syncthreads();

    for (int kt = 0; kt < T; ++kt) {
        int b = kt & 1;
        if (kt + 1 < T) {
            int ko = kbase + (kt+1) * 32;
            #pragma unroll
            for (int i = 0; i < 2; ++i) {
                pa[i] = (m0 + lm[i] < M)
                      ? *(const float4*)(g_cch + (size_t)(m0+lm[i])*1280 + ko + lq[i])
                      : make_float4(0.f,0.f,0.f,0.f);
                pb[i] = *(const float4*)(g_wfinh + (size_t)(n0+lm[i])*1280 + ko + lq[i]);
            }
        }

        #pragma unroll
        for (int ks = 0; ks < 2; ++ks) {
            int kb = ks * 8;
            uint32_t af[4][4], bf[4][2];
            #pragma unroll
            for (int mt = 0; mt < 4; ++mt) {
                int mb = wm*64 + mt*16;
                af[mt][0] = As[b][mb+g  ][kb+t  ];
                af[mt][1] = As[b][mb+g+8][kb+t  ];
                af[mt][2] = As[b][mb+g  ][kb+t+4];
                af[mt][3] = As[b][mb+g+8][kb+t+4];
            }
            #pragma unroll
            for (int nt = 0; nt < 4; ++nt) {
                int nb = wn*32 + nt*8;
                bf[nt][0] = Bs[b][nb+g][kb+t  ];
                bf[nt][1] = Bs[b][nb+g][kb+t+4];
            }
            #pragma unroll
            for (int mt = 0; mt < 4; ++mt)
                #pragma unroll
                for (int nt = 0; nt < 4; ++nt) {
                    asm volatile(
                        "mma.sync.aligned.m16n8k16.row.col.f32.f16.f16.f32 "
                        "{%0,%1,%2,%3}, {%4,%5,%6,%7}, {%8,%9}, {%0,%1,%2,%3};"
                        : "+f"(acc[mt][nt][0]), "+f"(acc[mt][nt][1]),
                          "+f"(acc[mt][nt][2]), "+f"(acc[mt][nt][3])
                        : "r"(af[mt][0]), "r"(af[mt][1]), "r"(af[mt][2]), "r"(af[mt][3]),
                          "r"(bf[nt][0]), "r"(bf[nt][1]));
                }
        }

        if (kt + 1 < T) {
            int nb_ = b ^ 1;
            #pragma unroll
            for (int i = 0; i < 2; ++i) {
                *(float4*)&As[nb_][lm[i]][lq[i]>>1] = pa[i];
                *(float4*)&Bs[nb_][lm[i]][lq[i]>>1] = pb[i];
            }
            __syncthreads();
        }
    }

    #pragma unroll
    for (int mt = 0; mt < 4; ++mt) {
        int r0 = m0 + wm*64 + mt*16 + g;
        #pragma unroll
        for (int nt = 0; nt < 4; ++nt) {
            int c = n0 + wn*32 + nt*8 + t*2;
            if (r0 < M)
                *(float2*)&P[(size_t)r0*1024 + c] = make_float2(acc[mt][nt][0], acc[mt][nt][1]);
            if (r0 + 8 < M)
                *(float2*)&P[(size_t)(r0+8)*1024 + c] = make_float2(acc[mt][nt][2], acc[mt][nt][3]);
        }
    }
}

// ---------------- fp32 64x64 GEMM: pooled skip + z@Wv2 fused ----------------
__global__ void __launch_bounds__(256) gemm_pool64(
    const float* __restrict__ Ws2, const float* __restrict__ Wv2,
    const float* __restrict__ bs2)
{
    __shared__ float As[16][68];
    __shared__ float Bs[16][68];
    int tid = threadIdx.x;
    int tx = tid & 15, ty = tid >> 4;
    int m0 = blockIdx.x * 64;
    int n0 = blockIdx.y * 64;
    int hOff = (n0 >> 8) * 512;
    float acc[4][4] = {};

    int arow = tid >> 2, ac4 = (tid & 3)*4;
    int brow = tid >> 4, bc4 = (tid & 15)*4;

    #pragma unroll 1
    for (int half_ = 0; half_ < 2; ++half_) {
        const float* Bm = half_ ? Wv2 : Ws2;
        for (int k0 = 0; k0 < 512; k0 += 16) {
            float4 av = make_float4(0.f,0.f,0.f,0.f);
            if (m0 + arow < BB) {
                av = half_
                   ? __ldg((const float4*)&g_z[(size_t)(m0+arow)*2048 + hOff + k0 + ac4])
                   : __ldg((const float4*)&g_ph1[(size_t)(m0+arow)*512 + k0 + ac4]);
            }
            As[ac4+0][arow] = av.x; As[ac4+1][arow] = av.y;
            As[ac4+2][arow] = av.z; As[ac4+3][arow] = av.w;
            float4 bv = __ldg((const float4*)&Bm[(size_t)(k0+brow)*1024 + n0 + bc4]);
            *(float4*)&Bs[brow][bc4] = bv;
            __syncthreads();
            #pragma unroll
            for (int kk = 0; kk < 16; ++kk) {
                float a[4], b[4];
                *(float4*)a = *(const float4*)&As[kk][ty*4];
                *(float4*)b = *(const float4*)&Bs[kk][tx*4];
                #pragma unroll
                for (int i = 0; i < 4; ++i)
                    #pragma unroll
                    for (int j = 0; j < 4; ++j)
                        acc[i][j] = fmaf(a[i], b[j], acc[i][j]);
            }
            __syncthreads();
        }
    }
    #pragma unroll
    for (int i = 0; i < 4; ++i) {
        int row = m0 + ty*4 + i;
        if (row < BB) {
            #pragma unroll
            for (int j = 0; j < 4; ++j) {
                int col = n0 + tx*4 + j;
                g_concat[(size_t)row*1280 + col] = acc[i][j] + __ldg(&bs2[col]);
            }
        }
    }
}

// ---------------- fingerprint GEMM partials: fpb @ Wfp, split-K=4 ----------------
__global__ void __launch_bounds__(256) gemm_fp64(
    const float* __restrict__ A, const float* __restrict__ Bm)
{
    __shared__ float As[16][68];
    __shared__ float Bs[16][68];
    int tid = threadIdx.x;
    int tx = tid & 15, ty = tid >> 4;
    int m0 = blockIdx.x * 64;
    int n0 = blockIdx.y * 64;
    int zs = blockIdx.z;
    int kb = zs * 512;
    float acc[4][4] = {};

    int arow = tid >> 2, ac4 = (tid & 3)*4;
    int brow = tid >> 4, bc4 = (tid & 15)*4;

    for (int k0 = kb; k0 < kb + 512; k0 += 16) {
        float4 av = make_float4(0.f,0.f,0.f,0.f);
        if (m0 + arow < BB)
            av = __ldg((const float4*)&A[(size_t)(m0+arow)*2048 + k0 + ac4]);
        As[ac4+0][arow] = av.x; As[ac4+1][arow] = av.y;
        As[ac4+2][arow] = av.z; As[ac4+3][arow] = av.w;
        float4 bv = __ldg((const float4*)&Bm[(size_t)(k0+brow)*256 + n0 + bc4]);
        *(float4*)&Bs[brow][bc4] = bv;
        __syncthreads();
        #pragma unroll
        for (int kk = 0; kk < 16; ++kk) {
            float a[4], b[4];
            *(float4*)a = *(const float4*)&As[kk][ty*4];
            *(float4*)b = *(const float4*)&Bs[kk][tx*4];
            #pragma unroll
            for (int i = 0; i < 4; ++i)
                #pragma unroll
                for (int j = 0; j < 4; ++j)
                    acc[i][j] = fmaf(a[i], b[j], acc[i][j]);
        }
        __syncthreads();
    }
    #pragma unroll
    for (int i = 0; i < 4; ++i) {
        int row = m0 + ty*4 + i;
        if (row < BB) {
            #pragma unroll
            for (int j = 0; j < 4; ++j) {
                int col = n0 + tx*4 + j;
                g_fppart[(size_t)zs*BB*256 + (size_t)row*256 + col] = acc[i][j];
            }
        }
    }
}

// ---------------- epilogue: edge term + bv2 term into concat ----------------
__global__ void eps_kernel(const float* __restrict__ We2, const float* __restrict__ bv2)
{
    int g = blockIdx.x;
    int c = blockIdx.y*256 + threadIdx.x;
    int h = c >> 8;
    float acc = g_cnt[g] * (1.f/NPG) * __ldg(&bv2[c]);
    #pragma unroll
    for (int t = 0; t < 4; ++t)
        acc = fmaf(g_r[g*16 + h*4 + t], __ldg(&We2[t*1024 + c]), acc);
    g_concat[(size_t)g*1280 + c] += acc;
}

// ---------------- concat -> fp16 (folds fp-partial reduce + bfp) ----------------
__global__ void convert_cc_kernel(const float* __restrict__ bfp)
{
    int i = blockIdx.x*blockDim.x + threadIdx.x;
    if (i >= BB*640) return;
    int row = i / 640;
    int c = (i % 640) * 2;
    float v0, v1;
    if (c < 1024) {
        v0 = g_concat[(size_t)row*1280 + c];
        v1 = g_concat[(size_t)row*1280 + c + 1];
    } else {
        int cc = c - 1024;
        v0 = __ldg(&bfp[cc]);   v1 = __ldg(&bfp[cc+1]);
        #pragma unroll
        for (int zp = 0; zp < 4; ++zp) {
            v0 += g_fppart[(size_t)zp*BB*256 + (size_t)row*256 + cc];
            v1 += g_fppart[(size_t)zp*BB*256 + (size_t)row*256 + cc + 1];
        }
    }
    ((__half2*)g_cch)[i] = __floats2half2_rn(v0, v1);
}

// ---------------- final reduce: d_out = bfin + sum of 4 partials ----------------
__global__ void reduce_fin_kernel(const float* __restrict__ bfin, float* __restrict__ out)
{
    int i = blockIdx.x*blockDim.x + threadIdx.x;
    if (i >= BB*256) return;
    int c4 = (i & 255) * 4;
    float4 acc = __ldg((const float4*)&bfin[c4]);
    #pragma unroll
    for (int zp = 0; zp < 4; ++zp) {
        float4 p = *(const float4*)&g_fpart[(size_t)zp*BB*1024 + (size_t)i*4];
        acc.x += p.x; acc.y += p.y; acc.z += p.z; acc.w += p.w;
    }
    ((float4*)out)[i] = acc;
}

// ---------------- launch ----------------
extern "C" void kernel_launch(void* const* d_in, const int* in_sizes, int n_in,
                              void* d_out, int out_size)
{
    const float* x    = (const float*)d_in[0];
    const int*   ei   = (const int*)  d_in[1];
    const float* ea   = (const float*)d_in[2];
    const float* fpb  = (const float*)d_in[4];
    const float *Wq1=(const float*)d_in[5],  *bq1=(const float*)d_in[6];
    const float *Wk1=(const float*)d_in[7],  *bk1=(const float*)d_in[8];
    const float *Wv1=(const float*)d_in[9],  *bv1=(const float*)d_in[10];
    const float *We1=(const float*)d_in[11];
    const float *Ws1=(const float*)d_in[12], *bs1=(const float*)d_in[13];
    const float *Wq2=(const float*)d_in[14], *bq2=(const float*)d_in[15];
    const float *Wk2=(const float*)d_in[16], *bk2=(const float*)d_in[17];
    const float *Wv2=(const float*)d_in[18], *bv2=(const float*)d_in[19];
    const float *We2=(const float*)d_in[20];
    const float *Ws2=(const float*)d_in[21], *bs2=(const float*)d_in[22];
    const float *Wfp=(const float*)d_in[23], *bfp=(const float*)d_in[24];
    const float *Wfin=(const float*)d_in[25],*bfin=(const float*)d_in[26];

    const int* srcArr = ei;
    const int* dstArr = ei + EE;

    float *q1,*s1,*ph1,*q2;
    __half *k1h,*v1h,*h1h,*k2h;
    cudaGetSymbolAddress((void**)&q1, g_q1);
    cudaGetSymbolAddress((void**)&s1, g_s1);
    cudaGetSymbolAddress((void**)&k1h, g_k1h);
    cudaGetSymbolAddress((void**)&v1h, g_v1h);
    cudaGetSymbolAddress((void**)&h1h, g_h1h);
    cudaGetSymbolAddress((void**)&ph1, g_ph1);
    cudaGetSymbolAddress((void**)&q2, g_q2);
    cudaGetSymbolAddress((void**)&k2h, g_k2h);

    const int SM1 = 96*512;
    const int SM2 = 16*1024 + 2*NPG*1024 + NPG*1024
                  + 256*4*4*2 + 256*4 + NPG*4*4 + NPG*4 + 64;
    cudaFuncSetAttribute(attn1_kernel, cudaFuncAttributeMaxDynamicSharedMemorySize, SM1);
    cudaFuncSetAttribute(attn2_kernel, cudaFuncAttributeMaxDynamicSharedMemorySize, SM2);

    // CSR build
    zero_deg_kernel<<<(NN+255)/256, 256>>>();
    hist_kernel<<<(EE+255)/256, 256>>>(dstArr);
    scan_kernel<<<1, 1024>>>();
    scatter_kernel<<<(EE+255)/256, 256>>>(dstArr);
    sort_kernel<<<(NN+255)/256, 256>>>();

    // weight converts (independent; issue early)
    wt2half_kernel<<<dim3(32, 16, 2), dim3(32, 32)>>>(Wq2, Wk2);
    wfin2half_kernel<<<dim3(32, 40), dim3(32, 32)>>>(Wfin);

    // fingerprint GEMM partials (independent of the graph path)
    gemm_fp64<<<dim3((BB+63)/64, 4, 4), 256>>>(fpb, Wfp);

    // layer 1
    proj1_kernel<<<(NN*32+255)/256, 256>>>(x, Wq1,bq1, Wk1,bk1, Wv1,bv1, Ws1,bs1);
    attn1_kernel<<<BB, 640, SM1>>>(q1, k1h, v1h, s1, ea, We1, srcArr, ph1, h1h);

    // layer-2 q,k projections on tensor cores (3-stage cp.async, occ=2)
    {
        dim3 grid((NN+127)/128, 1024/128, 2);
        gemm2_f16_kernel<<<grid, 256>>>(h1h, bq2, bk2, q2, NN);
    }

    // layer-2 attention weights -> z, r, cnt
    attn2_kernel<<<BB, 640, SM2>>>(q2, k2h, h1h, ea, We2, srcArr);

    // concat[:, :1024] = ph1@Ws2 + z@Wv2(per-head) + bs2, then edge/bias epilogue
    gemm_pool64<<<dim3((BB+63)/64, 1024/64), 256>>>(Ws2, Wv2, bs2);
    eps_kernel<<<dim3(BB, 4), 256>>>(We2, bv2);

    // fp16 convert (also reduces fingerprint partials into cols 1024:1280)
    convert_cc_kernel<<<(BB*640+255)/256, 256>>>(bfp);

    // final GEMM on tensor cores, split-K=4, then reduce
    gemmfin_f16_kernel<<<dim3((BB+127)/128, 1024/128, 4), 256>>>(BB);
    reduce_fin_kernel<<<(BB*256+255)/256, 256>>>(bfin, (float*)d_out);
}

// round 12
// speedup vs baseline: 3.4389x; 1.0335x over previous
#include <cuda_runtime.h>
#include <cuda_fp16.h>
#include <math.h>
#include <stdint.h>

#define NN 24000
#define EE 96000
#define BB 1200
#define NPG 20

// ---------------- device scratch ----------------
__device__ __half g_q1h[NN*512];
__device__ float  g_s1[NN*512];
__device__ __half g_k1h[NN*512];
__device__ __half g_v1h[NN*512];
__device__ __half g_h1h[NN*512];
__device__ float  g_ph1[BB*512];
__device__ __half g_q2h[NN*1024];
__device__ __half g_k2h[NN*1024];
__device__ float  g_z[BB*2048];
__device__ float  g_r[BB*16];
__device__ float  g_cnt[BB];
__device__ int    g_deg[NN];
__device__ int    g_offs[NN+1];
__device__ int    g_cursor[NN];
__device__ int    g_eidx[EE];
__device__ __half g_w2h[2*1024*512];
__device__ __half g_wfinh[1024*1280];
__device__ __half g_cch[BB*1280];
__device__ float  g_fppart[4*BB*256];
__device__ float  g_fpart[4*BB*1024];

__device__ __forceinline__ void cpa16(void* dst, const void* src, bool pred) {
    uint32_t d = (uint32_t)__cvta_generic_to_shared(dst);
    int sz = pred ? 16 : 0;
    asm volatile("cp.async.cg.shared.global [%0], [%1], 16, %2;\n"
                 :: "r"(d), "l"(src), "r"(sz));
}

// ---------------- CSR build ----------------
__global__ void zero_deg_kernel() {
    int i = blockIdx.x*blockDim.x + threadIdx.x;
    if (i < NN) g_deg[i] = 0;
}

__global__ void hist_kernel(const int* __restrict__ dst) {
    int e = blockIdx.x*blockDim.x + threadIdx.x;
    if (e < EE) atomicAdd(&g_deg[dst[e]], 1);
}

__global__ void scan_kernel() {
    __shared__ int wsum[32];
    __shared__ int carry;
    int tid = threadIdx.x;
    int lane = tid & 31, wid = tid >> 5;
    if (tid == 0) carry = 0;
    __syncthreads();
    for (int base = 0; base < NN; base += 1024) {
        int i = base + tid;
        int v = (i < NN) ? g_deg[i] : 0;
        int x = v;
        #pragma unroll
        for (int o = 1; o < 32; o <<= 1) {
            int y = __shfl_up_sync(0xffffffffu, x, o);
            if (lane >= o) x += y;
        }
        if (lane == 31) wsum[wid] = x;
        __syncthreads();
        if (wid == 0) {
            int s = wsum[lane];
            #pragma unroll
            for (int o = 1; o < 32; o <<= 1) {
                int y = __shfl_up_sync(0xffffffffu, s, o);
                if (lane >= o) s += y;
            }
            wsum[lane] = s;
        }
        __syncthreads();
        int pre = (wid > 0 ? wsum[wid-1] : 0) + carry;
        int incl = x + pre;
        if (i < NN) { g_offs[i] = incl - v; g_cursor[i] = incl - v; }
        __syncthreads();
        if (tid == 1023) carry = incl;
        __syncthreads();
    }
    if (tid == 0) g_offs[NN] = carry;
}

__global__ void scatter_kernel(const int* __restrict__ dst) {
    int e = blockIdx.x*blockDim.x + threadIdx.x;
    if (e < EE) {
        int p = atomicAdd(&g_cursor[dst[e]], 1);
        g_eidx[p] = e;
    }
}

__global__ void sort_kernel() {
    int n = blockIdx.x*blockDim.x + threadIdx.x;
    if (n >= NN) return;
    int a = g_offs[n], b = g_offs[n+1];
    for (int i = a+1; i < b; ++i) {
        int key = g_eidx[i];
        int j = i-1;
        while (j >= a && g_eidx[j] > key) { g_eidx[j+1] = g_eidx[j]; --j; }
        g_eidx[j+1] = key;
    }
}

// ---------------- layer-1 projections: q,k,v fp16; s fp32 ----------------
__global__ void proj1_kernel(const float* __restrict__ x,
    const float* __restrict__ Wq, const float* __restrict__ bq,
    const float* __restrict__ Wk, const float* __restrict__ bk,
    const float* __restrict__ Wv, const float* __restrict__ bv,
    const float* __restrict__ Ws, const float* __restrict__ bs)
{
    int warp = (blockIdx.x*blockDim.x + threadIdx.x) >> 5;
    int lane = threadIdx.x & 31;
    if (warp >= NN) return;
    float xr[9];
    #pragma unroll
    for (int t = 0; t < 9; ++t) xr[t] = __ldg(&x[warp*9 + t]);
    for (int j = lane; j < 512; j += 32) {
        float aq = __ldg(&bq[j]), ak = __ldg(&bk[j]);
        float av = __ldg(&bv[j]), as_ = __ldg(&bs[j]);
        #pragma unroll
        for (int t = 0; t < 9; ++t) {
            float xv = xr[t];
            aq  = fmaf(xv, __ldg(&Wq[t*512+j]), aq);
            ak  = fmaf(xv, __ldg(&Wk[t*512+j]), ak);
            av  = fmaf(xv, __ldg(&Wv[t*512+j]), av);
            as_ = fmaf(xv, __ldg(&Ws[t*512+j]), as_);
        }
        size_t o = (size_t)warp*512 + j;
        g_s1[o] = as_;
        g_q1h[o] = __float2half_rn(aq);
        g_k1h[o] = __float2half_rn(ak);
        g_v1h[o] = __float2half_rn(av);
    }
}

// ---------------- layer-1 per-graph attention (q fp16) ----------------
__global__ void __launch_bounds__(640, 1) attn1_kernel(
    const __half* __restrict__ qh, const __half* __restrict__ khg,
    const __half* __restrict__ vhg, const float* __restrict__ s,
    const float* __restrict__ ea, const float* __restrict__ We,
    const int* __restrict__ srcArr, float* __restrict__ outPooled,
    __half* __restrict__ h1h)
{
    constexpr int D = 512, H = 4;
    constexpr int VPT = D / 32;   // 16
    constexpr int NU = VPT / 8;   // 2
    constexpr int C = D / H;
    extern __shared__ char smraw[];
    float*  sWeT = (float*)smraw;
    __half* kh   = (__half*)(smraw + 16*D);
    __half* vh   = (__half*)(smraw + 16*D + 40*D);
    float*  poolbuf = (float*)kh;

    int tid = threadIdx.x;
    int wid = tid >> 5, lane = tid & 31;
    int graph = blockIdx.x;
    int gbase = graph * NPG;

    for (int i = tid; i < 4*D; i += 640) {
        int c = i >> 2, t = i & 3;
        sWeT[i] = __ldg(&We[t*D + c]);
    }
    {
        const uint4* ks = (const uint4*)(khg + (size_t)gbase*D);
        const uint4* vs = (const uint4*)(vhg + (size_t)gbase*D);
        uint4* kd = (uint4*)kh;
        uint4* vd = (uint4*)vh;
        for (int i = tid; i < NPG*D/8; i += 640) { kd[i] = __ldg(ks+i); vd[i] = __ldg(vs+i); }
    }
    __syncthreads();

    int node = gbase + wid;
    int cbase = lane * VPT;
    const float4* sWe4 = (const float4*)sWeT;

    float qrf[VPT], accf[VPT];
    {
        const uint4* q4 = (const uint4*)(qh + (size_t)node*D + cbase);
        #pragma unroll
        for (int i = 0; i < NU; ++i) {
            uint4 u = __ldg(q4 + i);
            const __half2* h2 = (const __half2*)&u;
            #pragma unroll
            for (int j = 0; j < 4; ++j) {
                float2 f = __half22float2(h2[j]);
                qrf[8*i+2*j] = f.x; qrf[8*i+2*j+1] = f.y;
            }
        }
    }
    #pragma unroll
    for (int i = 0; i < VPT; ++i) accf[i] = 0.f;

    float4 qe = make_float4(0.f,0.f,0.f,0.f);
    #pragma unroll
    for (int i = 0; i < VPT; ++i) {
        float4 w = sWe4[cbase + i];
        qe.x = fmaf(qrf[i], w.x, qe.x);
        qe.y = fmaf(qrf[i], w.y, qe.y);
        qe.z = fmaf(qrf[i], w.z, qe.z);
        qe.w = fmaf(qrf[i], w.w, qe.w);
    }
    #pragma unroll
    for (int o = 1; o < 8; o <<= 1) {
        qe.x += __shfl_xor_sync(0xffffffffu, qe.x, o);
        qe.y += __shfl_xor_sync(0xffffffffu, qe.y, o);
        qe.z += __shfl_xor_sync(0xffffffffu, qe.z, o);
        qe.w += __shfl_xor_sync(0xffffffffu, qe.w, o);
    }

    float m = -INFINITY, den = 0.f;
    float4 wa = make_float4(0.f,0.f,0.f,0.f);
    const float invs = rsqrtf((float)C);

    int e0 = g_offs[node], e1 = g_offs[node+1];
    for (int t = e0; t < e1; ++t) {
        int e  = __ldg(&g_eidx[t]);
        int ln = __ldg(&srcArr[e]) - gbase;
        float4 a4 = __ldg((const float4*)ea + e);

        const uint4* krow = (const uint4*)(kh + ln*D + cbase);
        float p = 0.f;
        #pragma unroll
        for (int i = 0; i < NU; ++i) {
            uint4 u = krow[i];
            const __half2* h2 = (const __half2*)&u;
            #pragma unroll
            for (int j = 0; j < 4; ++j) {
                float2 f = __half22float2(h2[j]);
                p = fmaf(qrf[8*i+2*j], f.x, p);
                p = fmaf(qrf[8*i+2*j+1], f.y, p);
            }
        }
        p += __shfl_xor_sync(0xffffffffu, p, 1);
        p += __shfl_xor_sync(0xffffffffu, p, 2);
        p += __shfl_xor_sync(0xffffffffu, p, 4);
        float alpha = (p + qe.x*a4.x + qe.y*a4.y + qe.z*a4.z + qe.w*a4.w) * invs;

        float nm = fmaxf(m, alpha);
        float sc = __expf(m - nm);
        float w  = __expf(alpha - nm);
        den = den*sc + w;
        m = nm;

        const uint4* vrow = (const uint4*)(vh + ln*D + cbase);
        #pragma unroll
        for (int i = 0; i < NU; ++i) {
            uint4 u = vrow[i];
            const __half2* h2 = (const __half2*)&u;
            #pragma unroll
            for (int j = 0; j < 4; ++j) {
                float2 f = __half22float2(h2[j]);
                accf[8*i+2*j]   = accf[8*i+2*j]*sc   + w*f.x;
                accf[8*i+2*j+1] = accf[8*i+2*j+1]*sc + w*f.y;
            }
        }
        wa.x = wa.x*sc + w*a4.x; wa.y = wa.y*sc + w*a4.y;
        wa.z = wa.z*sc + w*a4.z; wa.w = wa.w*sc + w*a4.w;
    }

    float r = 1.f / (den + 1e-16f);
    float outv[VPT];
    #pragma unroll
    for (int i = 0; i < VPT; ++i) {
        float4 w = sWe4[cbase + i];
        float msg = (accf[i] + wa.x*w.x + wa.y*w.y + wa.z*w.z + wa.w*w.w) * r;
        msg += __ldg(&s[(size_t)node*D + cbase + i]);
        msg = fmaxf(msg, 0.f);
        outv[i] = msg;
    }
    {
        __half2* h4 = (__half2*)(h1h + (size_t)node*D + cbase);
        #pragma unroll
        for (int i = 0; i < VPT/2; ++i)
            h4[i] = __floats2half2_rn(outv[2*i], outv[2*i+1]);
    }

    __syncthreads();
    #pragma unroll
    for (int i = 0; i < VPT; ++i) poolbuf[wid*D + cbase + i] = outv[i];
    __syncthreads();
    for (int c = tid; c < D; c += 640) {
        float sum = 0.f;
        #pragma unroll
        for (int i = 0; i < NPG; ++i) sum += poolbuf[i*D + c];
        outPooled[(size_t)graph*512 + c] = sum * (1.f/NPG);
    }
}

// ---------------- layer-2 attention: softmax weights only (q fp16) ----------------
__global__ void __launch_bounds__(640, 1) attn2_kernel(
    const __half* __restrict__ qh, const __half* __restrict__ khg,
    const __half* __restrict__ h1g,
    const float* __restrict__ ea, const float* __restrict__ We,
    const int* __restrict__ srcArr)
{
    constexpr int D = 1024, H = 4;
    constexpr int VPT = D / 32;   // 32
    constexpr int NU = VPT / 8;   // 4
    constexpr int C = D / H;
    constexpr int ECAP = 256;
    extern __shared__ char smraw[];
    float*  sWeT   = (float*)smraw;
    __half* kh     = (__half*)(smraw + 16*D);
    __half* h1s    = (__half*)(smraw + 16*D + 2*NPG*D);
    float*  alphaS = (float*)(smraw + 16*D + 2*NPG*D + NPG*1024);
    float*  wS     = alphaS + ECAP*H;
    int*    lnS    = (int*)(wS + ECAP*H);
    float*  cS     = (float*)(lnS + ECAP);
    int*    hasE   = (int*)(cS + NPG*H);

    int tid = threadIdx.x;
    int wid = tid >> 5, lane = tid & 31;
    int graph = blockIdx.x;
    int gbase = graph * NPG;
    int head = lane >> 3;

    for (int i = tid; i < 4*D; i += 640) {
        int c = i >> 2, t = i & 3;
        sWeT[i] = __ldg(&We[t*D + c]);
    }
    {
        const uint4* ks = (const uint4*)(khg + (size_t)gbase*D);
        uint4* kd = (uint4*)kh;
        for (int i = tid; i < NPG*D/8; i += 640) kd[i] = __ldg(ks+i);
        const uint4* hs = (const uint4*)(h1g + (size_t)gbase*512);
        uint4* hd = (uint4*)h1s;
        for (int i = tid; i < NPG*512/8; i += 640) hd[i] = __ldg(hs+i);
    }
    __syncthreads();

    int node = gbase + wid;
    int cbase = lane * VPT;
    const float4* sWe4 = (const float4*)sWeT;

    float qrf[VPT];
    {
        const uint4* q4 = (const uint4*)(qh + (size_t)node*D + cbase);
        #pragma unroll
        for (int i = 0; i < NU; ++i) {
            uint4 u = __ldg(q4 + i);
            const __half2* h2 = (const __half2*)&u;
            #pragma unroll
            for (int j = 0; j < 4; ++j) {
                float2 f = __half22float2(h2[j]);
                qrf[8*i+2*j] = f.x; qrf[8*i+2*j+1] = f.y;
            }
        }
    }

    float4 qe = make_float4(0.f,0.f,0.f,0.f);
    #pragma unroll
    for (int i = 0; i < VPT; ++i) {
        float4 w = sWe4[cbase + i];
        qe.x = fmaf(qrf[i], w.x, qe.x);
        qe.y = fmaf(qrf[i], w.y, qe.y);
        qe.z = fmaf(qrf[i], w.z, qe.z);
        qe.w = fmaf(qrf[i], w.w, qe.w);
    }
    #pragma unroll
    for (int o = 1; o < 8; o <<= 1) {
        qe.x += __shfl_xor_sync(0xffffffffu, qe.x, o);
        qe.y += __shfl_xor_sync(0xffffffffu, qe.y, o);
        qe.z += __shfl_xor_sync(0xffffffffu, qe.z, o);
        qe.w += __shfl_xor_sync(0xffffffffu, qe.w, o);
    }

    const float invs = rsqrtf((float)C);
    int eb = g_offs[gbase];
    int cntE = g_offs[gbase + NPG] - eb;
    int e0 = g_offs[node], e1 = g_offs[node+1];

    float m = -INFINITY, den = 0.f;
    for (int t = e0; t < e1; ++t) {
        int e  = __ldg(&g_eidx[t]);
        int ln = __ldg(&srcArr[e]) - gbase;
        float4 a4 = __ldg((const float4*)ea + e);

        const uint4* krow = (const uint4*)(kh + ln*D + cbase);
        float p = 0.f;
        #pragma unroll
        for (int i = 0; i < NU; ++i) {
            uint4 u = krow[i];
            const __half2* h2 = (const __half2*)&u;
            #pragma unroll
            for (int j = 0; j < 4; ++j) {
                float2 f = __half22float2(h2[j]);
                p = fmaf(qrf[8*i+2*j], f.x, p);
                p = fmaf(qrf[8*i+2*j+1], f.y, p);
            }
        }
        p += __shfl_xor_sync(0xffffffffu, p, 1);
        p += __shfl_xor_sync(0xffffffffu, p, 2);
        p += __shfl_xor_sync(0xffffffffu, p, 4);
        float alpha = (p + qe.x*a4.x + qe.y*a4.y + qe.z*a4.z + qe.w*a4.w) * invs;

        float nm = fmaxf(m, alpha);
        den = den*__expf(m - nm) + __expf(alpha - nm);
        m = nm;
        if ((lane & 7) == 0) alphaS[(t - eb)*H + head] = alpha;
        if (lane == 0) lnS[t - eb] = ln;
    }
    float rdn = (e1 > e0) ? 1.f/den : 0.f;
    if ((lane & 7) == 0) {
        for (int t = e0; t < e1; ++t) {
            float w = __expf(alphaS[(t - eb)*H + head] - m) * rdn;
            wS[(t - eb)*H + head] = w;
        }
    }
    if (lane == 0) hasE[wid] = (e1 > e0) ? 1 : 0;
    __syncthreads();

    if (tid < NPG*H) {
        int ln = tid >> 2, h = tid & 3;
        float c = 0.f;
        for (int i = 0; i < cntE; ++i)
            if (lnS[i] == ln) c += wS[i*H + h];
        cS[tid] = c * (1.f/NPG);
    } else if (tid < NPG*H + 16) {
        int idx = tid - NPG*H;
        int h = idx >> 2, t4 = idx & 3;
        float r = 0.f;
        for (int i = 0; i < cntE; ++i) {
            int e = __ldg(&g_eidx[eb + i]);
            r += wS[i*H + h] * __ldg(&ea[e*4 + t4]);
        }
        g_r[graph*16 + h*4 + t4] = r * (1.f/NPG);
    } else if (tid == NPG*H + 16) {
        int c = 0;
        #pragma unroll
        for (int i = 0; i < NPG; ++i) c += hasE[i];
        g_cnt[graph] = (float)c;
    }
    __syncthreads();

    for (int o = tid; o < H*512; o += 640) {
        int h = o >> 9, c = o & 511;
        float z = 0.f;
        #pragma unroll
        for (int ln = 0; ln < NPG; ++ln)
            z = fmaf(cS[ln*H + h], __half2float(h1s[ln*512 + c]), z);
        g_z[(size_t)graph*2048 + o] = z;
    }
}

// ---------------- weight transpose+fp16 converts ----------------
__global__ void wt2half_kernel(const float* __restrict__ W0, const float* __restrict__ W1) {
    __shared__ float tile[32][33];
    int z = blockIdx.z;
    const float* W = (z==0) ? W0 : W1;
    int n0 = blockIdx.x * 32, k0 = blockIdx.y * 32;
    int tx = threadIdx.x, ty = threadIdx.y;
    tile[ty][tx] = __ldg(&W[(size_t)(k0+ty)*1024 + n0 + tx]);
    __syncthreads();
    g_w2h[(size_t)z*1024*512 + (size_t)(n0+ty)*512 + k0 + tx] = __float2half_rn(tile[tx][ty]);
}

__global__ void wfin2half_kernel(const float* __restrict__ W) {
    __shared__ float tile[32][33];
    int n0 = blockIdx.x * 32, k0 = blockIdx.y * 32;
    int tx = threadIdx.x, ty = threadIdx.y;
    tile[ty][tx] = __ldg(&W[(size_t)(k0+ty)*1024 + n0 + tx]);
    __syncthreads();
    g_wfinh[(size_t)(n0+ty)*1280 + k0 + tx] = __float2half_rn(tile[tx][ty]);
}

// ---------------- f16 tensor-core GEMM: q2h/k2h both fp16 out ----------------
__global__ void __launch_bounds__(256, 2) gemm2_f16_kernel(
    const __half* __restrict__ Ah,
    const float* __restrict__ b0, const float* __restrict__ b1,
    int M)
{
    __shared__ __align__(16) uint32_t As[3][128][20];
    __shared__ __align__(16) uint32_t Bs[3][128][20];

    int z = blockIdx.z;
    const __half* Bz  = g_w2h + (size_t)z*1024*512;
    const float* bias = (z==0) ? b0 : b1;
    __half* Ch = (z==0) ? g_q2h : g_k2h;

    int tid  = threadIdx.x;
    int lane = tid & 31, wid = tid >> 5;
    int wm = wid >> 2, wn = wid & 3;
    int m0 = blockIdx.x * 128, n0 = blockIdx.y * 128;
    int g = lane >> 2, t = lane & 3;

    int lm[2], lq[2];
    #pragma unroll
    for (int i = 0; i < 2; ++i) {
        int idx = tid + i*256;
        lm[i] = idx >> 2;
        lq[i] = (idx & 3) * 8;
    }

    float acc[4][4][4];
    #pragma unroll
    for (int a = 0; a < 4; ++a)
        #pragma unroll
        for (int b = 0; b < 4; ++b)
            #pragma unroll
            for (int c = 0; c < 4; ++c) acc[a][b][c] = 0.f;

    const int T = 512 / 32;

    #pragma unroll
    for (int pt = 0; pt < 2; ++pt) {
        int ko = pt * 32;
        #pragma unroll
        for (int i = 0; i < 2; ++i) {
            cpa16(&As[pt][lm[i]][lq[i]>>1],
                  Ah + (size_t)(m0+lm[i])*512 + ko + lq[i], (m0+lm[i]) < M);
            cpa16(&Bs[pt][lm[i]][lq[i]>>1],
                  Bz + (size_t)(n0+lm[i])*512 + ko + lq[i], true);
        }
        asm volatile("cp.async.commit_group;\n");
    }

    for (int kt = 0; kt < T; ++kt) {
        int sl = kt % 3;
        asm volatile("cp.async.wait_group 1;\n");
        __syncthreads();

        if (kt + 2 < T) {
            int ns = (kt + 2) % 3;
            int ko = (kt + 2) * 32;
            #pragma unroll
            for (int i = 0; i < 2; ++i) {
                cpa16(&As[ns][lm[i]][lq[i]>>1],
                      Ah + (size_t)(m0+lm[i])*512 + ko + lq[i], (m0+lm[i]) < M);
                cpa16(&Bs[ns][lm[i]][lq[i]>>1],
                      Bz + (size_t)(n0+lm[i])*512 + ko + lq[i], true);
            }
        }
        asm volatile("cp.async.commit_group;\n");

        #pragma unroll
        for (int ks = 0; ks < 2; ++ks) {
            int kb = ks * 8;
            uint32_t af[4][4], bf[4][2];
            #pragma unroll
            for (int mt = 0; mt < 4; ++mt) {
                int mb = wm*64 + mt*16;
                af[mt][0] = As[sl][mb+g  ][kb+t  ];
                af[mt][1] = As[sl][mb+g+8][kb+t  ];
                af[mt][2] = As[sl][mb+g  ][kb+t+4];
                af[mt][3] = As[sl][mb+g+8][kb+t+4];
            }
            #pragma unroll
            for (int nt = 0; nt < 4; ++nt) {
                int nb = wn*32 + nt*8;
                bf[nt][0] = Bs[sl][nb+g][kb+t  ];
                bf[nt][1] = Bs[sl][nb+g][kb+t+4];
            }
            #pragma unroll
            for (int mt = 0; mt < 4; ++mt)
                #pragma unroll
                for (int nt = 0; nt < 4; ++nt) {
                    asm volatile(
                        "mma.sync.aligned.m16n8k16.row.col.f32.f16.f16.f32 "
                        "{%0,%1,%2,%3}, {%4,%5,%6,%7}, {%8,%9}, {%0,%1,%2,%3};"
                        : "+f"(acc[mt][nt][0]), "+f"(acc[mt][nt][1]),
                          "+f"(acc[mt][nt][2]), "+f"(acc[mt][nt][3])
                        : "r"(af[mt][0]), "r"(af[mt][1]), "r"(af[mt][2]), "r"(af[mt][3]),
                          "r"(bf[nt][0]), "r"(bf[nt][1]));
                }
        }
    }

    #pragma unroll
    for (int mt = 0; mt < 4; ++mt) {
        int r0 = m0 + wm*64 + mt*16 + g;
        #pragma unroll
        for (int nt = 0; nt < 4; ++nt) {
            int c = n0 + wn*32 + nt*8 + t*2;
            float bv0 = __ldg(&bias[c]), bv1 = __ldg(&bias[c+1]);
            if (r0 < M)
                *(__half2*)&Ch[(size_t)r0*1024 + c] =
                    __floats2half2_rn(acc[mt][nt][0] + bv0, acc[mt][nt][1] + bv1);
            if (r0 + 8 < M)
                *(__half2*)&Ch[(size_t)(r0+8)*1024 + c] =
                    __floats2half2_rn(acc[mt][nt][2] + bv0, acc[mt][nt][3] + bv1);
        }
    }
}

// ---------------- final-GEMM f16 tensor kernel, split-K partials ----------------
__global__ void __launch_bounds__(256) gemmfin_f16_kernel(int M)
{
    __shared__ uint32_t As[2][128][20];
    __shared__ uint32_t Bs[2][128][20];

    int zs = blockIdx.z;
    int kbase = zs * 320;
    float* P = g_fpart + (size_t)zs*BB*1024;

    int tid  = threadIdx.x;
    int lane = tid & 31, wid = tid >> 5;
    int wm = wid >> 2, wn = wid & 3;
    int m0 = blockIdx.x * 128, n0 = blockIdx.y * 128;
    int g = lane >> 2, t = lane & 3;

    int lm[2], lq[2];
    #pragma unroll
    for (int i = 0; i < 2; ++i) {
        int idx = tid + i*256;
        lm[i] = idx >> 2;
        lq[i] = (idx & 3) * 8;
    }

    float acc[4][4][4];
    #pragma unroll
    for (int a = 0; a < 4; ++a)
        #pragma unroll
        for (int b = 0; b < 4; ++b)
            #pragma unroll
            for (int c = 0; c < 4; ++c) acc[a][b][c] = 0.f;

    float4 pa[2], pb[2];
    const int T = 10;

    #pragma unroll
    for (int i = 0; i < 2; ++i) {
        pa[i] = (m0 + lm[i] < M)
              ? *(const float4*)(g_cch + (size_t)(m0+lm[i])*1280 + kbase + lq[i])
              : make_float4(0.f,0.f,0.f,0.f);
        pb[i] = *(const float4*)(g_wfinh + (size_t)(n0+lm[i])*1280 + kbase + lq[i]);
    }
    #pragma unroll
    for (int i = 0; i < 2; ++i) {
        *(float4*)&As[0][lm[i]][lq[i]>>1] = pa[i];
        *(float4*)&Bs[0][lm[i]][lq[i]>>1] = pb[i];
    }
    __syncthreads();

    for (int kt = 0; kt < T; ++kt) {
        int b = kt & 1;
        if (kt + 1 < T) {
            int ko = kbase + (kt+1) * 32;
            #pragma unroll
            for (int i = 0; i < 2; ++i) {
                pa[i] = (m0 + lm[i] < M)
                      ? *(const float4*)(g_cch + (size_t)(m0+lm[i])*1280 + ko + lq[i])
                      : make_float4(0.f,0.f,0.f,0.f);
                pb[i] = *(const float4*)(g_wfinh + (size_t)(n0+lm[i])*1280 + ko + lq[i]);
            }
        }

        #pragma unroll
        for (int ks = 0; ks < 2; ++ks) {
            int kb = ks * 8;
            uint32_t af[4][4], bf[4][2];
            #pragma unroll
            for (int mt = 0; mt < 4; ++mt) {
                int mb = wm*64 + mt*16;
                af[mt][0] = As[b][mb+g  ][kb+t  ];
                af[mt][1] = As[b][mb+g+8][kb+t  ];
                af[mt][2] = As[b][mb+g  ][kb+t+4];
                af[mt][3] = As[b][mb+g+8][kb+t+4];
            }
            #pragma unroll
            for (int nt = 0; nt < 4; ++nt) {
                int nb = wn*32 + nt*8;
                bf[nt][0] = Bs[b][nb+g][kb+t  ];
                bf[nt][1] = Bs[b][nb+g][kb+t+4];
            }
            #pragma unroll
            for (int mt = 0; mt < 4; ++mt)
                #pragma unroll
                for (int nt = 0; nt < 4; ++nt) {
                    asm volatile(
                        "mma.sync.aligned.m16n8k16.row.col.f32.f16.f16.f32 "
                        "{%0,%1,%2,%3}, {%4,%5,%6,%7}, {%8,%9}, {%0,%1,%2,%3};"
                        : "+f"(acc[mt][nt][0]), "+f"(acc[mt][nt][1]),
                          "+f"(acc[mt][nt][2]), "+f"(acc[mt][nt][3])
                        : "r"(af[mt][0]), "r"(af[mt][1]), "r"(af[mt][2]), "r"(af[mt][3]),
                          "r"(bf[nt][0]), "r"(bf[nt][1]));
                }
        }

        if (kt + 1 < T) {
            int nb_ = b ^ 1;
            #pragma unroll
            for (int i = 0; i < 2; ++i) {
                *(float4*)&As[nb_][lm[i]][lq[i]>>1] = pa[i];
                *(float4*)&Bs[nb_][lm[i]][lq[i]>>1] = pb[i];
            }
            __syncthreads();
        }
    }

    #pragma unroll
    for (int mt = 0; mt < 4; ++mt) {
        int r0 = m0 + wm*64 + mt*16 + g;
        #pragma unroll
        for (int nt = 0; nt < 4; ++nt) {
            int c = n0 + wn*32 + nt*8 + t*2;
            if (r0 < M)
                *(float2*)&P[(size_t)r0*1024 + c] = make_float2(acc[mt][nt][0], acc[mt][nt][1]);
            if (r0 + 8 < M)
                *(float2*)&P[(size_t)(r0+8)*1024 + c] = make_float2(acc[mt][nt][2], acc[mt][nt][3]);
        }
    }
}

// ---------------- fp32 64x64 GEMM: pooled skip + z@Wv2 + edge/bias, write cch fp16 ------
__global__ void __launch_bounds__(256) gemm_pool64(
    const float* __restrict__ Ws2, const float* __restrict__ Wv2,
    const float* __restrict__ bs2,
    const float* __restrict__ We2, const float* __restrict__ bv2)
{
    __shared__ float As[16][68];
    __shared__ float Bs[16][68];
    int tid = threadIdx.x;
    int tx = tid & 15, ty = tid >> 4;
    int m0 = blockIdx.x * 64;
    int n0 = blockIdx.y * 64;
    int h = n0 >> 8;            // head uniform per block (64 | 256)
    int hOff = h * 512;
    float acc[4][4] = {};

    int arow = tid >> 2, ac4 = (tid & 3)*4;
    int brow = tid >> 4, bc4 = (tid & 15)*4;

    #pragma unroll 1
    for (int half_ = 0; half_ < 2; ++half_) {
        const float* Bm = half_ ? Wv2 : Ws2;
        for (int k0 = 0; k0 < 512; k0 += 16) {
            float4 av = make_float4(0.f,0.f,0.f,0.f);
            if (m0 + arow < BB) {
                av = half_
                   ? __ldg((const float4*)&g_z[(size_t)(m0+arow)*2048 + hOff + k0 + ac4])
                   : __ldg((const float4*)&g_ph1[(size_t)(m0+arow)*512 + k0 + ac4]);
            }
            As[ac4+0][arow] = av.x; As[ac4+1][arow] = av.y;
            As[ac4+2][arow] = av.z; As[ac4+3][arow] = av.w;
            float4 bv = __ldg((const float4*)&Bm[(size_t)(k0+brow)*1024 + n0 + bc4]);
            *(float4*)&Bs[brow][bc4] = bv;
            __syncthreads();
            #pragma unroll
            for (int kk = 0; kk < 16; ++kk) {
                float a[4], b[4];
                *(float4*)a = *(const float4*)&As[kk][ty*4];
                *(float4*)b = *(const float4*)&Bs[kk][tx*4];
                #pragma unroll
                for (int i = 0; i < 4; ++i)
                    #pragma unroll
                    for (int j = 0; j < 4; ++j)
                        acc[i][j] = fmaf(a[i], b[j], acc[i][j]);
            }
            __syncthreads();
        }
    }
    #pragma unroll
    for (int i = 0; i < 4; ++i) {
        int row = m0 + ty*4 + i;
        if (row < BB) {
            float cfac = g_cnt[row] * (1.f/NPG);
            float r0 = g_r[row*16 + h*4 + 0], r1 = g_r[row*16 + h*4 + 1];
            float r2 = g_r[row*16 + h*4 + 2], r3 = g_r[row*16 + h*4 + 3];
            __half hbuf[4];
            #pragma unroll
            for (int j = 0; j < 4; ++j) {
                int col = n0 + tx*4 + j;
                float v = acc[i][j] + __ldg(&bs2[col]) + cfac*__ldg(&bv2[col]);
                v = fmaf(r0, __ldg(&We2[0*1024 + col]), v);
                v = fmaf(r1, __ldg(&We2[1*1024 + col]), v);
                v = fmaf(r2, __ldg(&We2[2*1024 + col]), v);
                v = fmaf(r3, __ldg(&We2[3*1024 + col]), v);
                hbuf[j] = __float2half_rn(v);
            }
            *(uint2*)&g_cch[(size_t)row*1280 + n0 + tx*4] = *(uint2*)hbuf;
        }
    }
}

// ---------------- fingerprint GEMM partials: fpb @ Wfp, split-K=4 ----------------
__global__ void __launch_bounds__(256) gemm_fp64(
    const float* __restrict__ A, const float* __restrict__ Bm)
{
    __shared__ float As[16][68];
    __shared__ float Bs[16][68];
    int tid = threadIdx.x;
    int tx = tid & 15, ty = tid >> 4;
    int m0 = blockIdx.x * 64;
    int n0 = blockIdx.y * 64;
    int zs = blockIdx.z;
    int kb = zs * 512;
    float acc[4][4] = {};

    int arow = tid >> 2, ac4 = (tid & 3)*4;
    int brow = tid >> 4, bc4 = (tid & 15)*4;

    for (int k0 = kb; k0 < kb + 512; k0 += 16) {
        float4 av = make_float4(0.f,0.f,0.f,0.f);
        if (m0 + arow < BB)
            av = __ldg((const float4*)&A[(size_t)(m0+arow)*2048 + k0 + ac4]);
        As[ac4+0][arow] = av.x; As[ac4+1][arow] = av.y;
        As[ac4+2][arow] = av.z; As[ac4+3][arow] = av.w;
        float4 bv = __ldg((const float4*)&Bm[(size_t)(k0+brow)*256 + n0 + bc4]);
        *(float4*)&Bs[brow][bc4] = bv;
        __syncthreads();
        #pragma unroll
        for (int kk = 0; kk < 16; ++kk) {
            float a[4], b[4];
            *(float4*)a = *(const float4*)&As[kk][ty*4];
            *(float4*)b = *(const float4*)&Bs[kk][tx*4];
            #pragma unroll
            for (int i = 0; i < 4; ++i)
                #pragma unroll
                for (int j = 0; j < 4; ++j)
                    acc[i][j] = fmaf(a[i], b[j], acc[i][j]);
        }
        __syncthreads();
    }
    #pragma unroll
    for (int i = 0; i < 4; ++i) {
        int row = m0 + ty*4 + i;
        if (row < BB) {
            #pragma unroll
            for (int j = 0; j < 4; ++j) {
                int col = n0 + tx*4 + j;
                g_fppart[(size_t)zs*BB*256 + (size_t)row*256 + col] = acc[i][j];
            }
        }
    }
}

// ---------------- fingerprint cols -> cch fp16 (partial reduce + bfp) ----------------
__global__ void fpcc_kernel(const float* __restrict__ bfp)
{
    int i = blockIdx.x*blockDim.x + threadIdx.x;   // over BB*128 half2s
    if (i >= BB*128) return;
    int row = i >> 7;
    int cc = (i & 127) * 2;
    float v0 = __ldg(&bfp[cc]), v1 = __ldg(&bfp[cc+1]);
    #pragma unroll
    for (int zp = 0; zp < 4; ++zp) {
        v0 += g_fppart[(size_t)zp*BB*256 + (size_t)row*256 + cc];
        v1 += g_fppart[(size_t)zp*BB*256 + (size_t)row*256 + cc + 1];
    }
    *(__half2*)&g_cch[(size_t)row*1280 + 1024 + cc] = __floats2half2_rn(v0, v1);
}

// ---------------- final reduce: d_out = bfin + sum of 4 partials ----------------
__global__ void reduce_fin_kernel(const float* __restrict__ bfin, float* __restrict__ out)
{
    int i = blockIdx.x*blockDim.x + threadIdx.x;
    if (i >= BB*256) return;
    int c4 = (i & 255) * 4;
    float4 acc = __ldg((const float4*)&bfin[c4]);
    #pragma unroll
    for (int zp = 0; zp < 4; ++zp) {
        float4 p = *(const float4*)&g_fpart[(size_t)zp*BB*1024 + (size_t)i*4];
        acc.x += p.x; acc.y += p.y; acc.z += p.z; acc.w += p.w;
    }
    ((float4*)out)[i] = acc;
}

// ---------------- launch ----------------
extern "C" void kernel_launch(void* const* d_in, const int* in_sizes, int n_in,
                              void* d_out, int out_size)
{
    const float* x    = (const float*)d_in[0];
    const int*   ei   = (const int*)  d_in[1];
    const float* ea   = (const float*)d_in[2];
    const float* fpb  = (const float*)d_in[4];
    const float *Wq1=(const float*)d_in[5],  *bq1=(const float*)d_in[6];
    const float *Wk1=(const float*)d_in[7],  *bk1=(const float*)d_in[8];
    const float *Wv1=(const float*)d_in[9],  *bv1=(const float*)d_in[10];
    const float *We1=(const float*)d_in[11];
    const float *Ws1=(const float*)d_in[12], *bs1=(const float*)d_in[13];
    const float *Wq2=(const float*)d_in[14], *bq2=(const float*)d_in[15];
    const float *Wk2=(const float*)d_in[16], *bk2=(const float*)d_in[17];
    const float *Wv2=(const float*)d_in[18], *bv2=(const float*)d_in[19];
    const float *We2=(const float*)d_in[20];
    const float *Ws2=(const float*)d_in[21], *bs2=(const float*)d_in[22];
    const float *Wfp=(const float*)d_in[23], *bfp=(const float*)d_in[24];
    const float *Wfin=(const float*)d_in[25],*bfin=(const float*)d_in[26];

    const int* srcArr = ei;
    const int* dstArr = ei + EE;

    float *s1,*ph1;
    __half *q1h,*k1h,*v1h,*h1h,*q2h,*k2h;
    cudaGetSymbolAddress((void**)&q1h, g_q1h);
    cudaGetSymbolAddress((void**)&s1, g_s1);
    cudaGetSymbolAddress((void**)&k1h, g_k1h);
    cudaGetSymbolAddress((void**)&v1h, g_v1h);
    cudaGetSymbolAddress((void**)&h1h, g_h1h);
    cudaGetSymbolAddress((void**)&ph1, g_ph1);
    cudaGetSymbolAddress((void**)&q2h, g_q2h);
    cudaGetSymbolAddress((void**)&k2h, g_k2h);

    const int SM1 = 96*512;
    const int SM2 = 16*1024 + 2*NPG*1024 + NPG*1024
                  + 256*4*4*2 + 256*4 + NPG*4*4 + NPG*4 + 64;
    cudaFuncSetAttribute(attn1_kernel, cudaFuncAttributeMaxDynamicSharedMemorySize, SM1);
    cudaFuncSetAttribute(attn2_kernel, cudaFuncAttributeMaxDynamicSharedMemorySize, SM2);

    // CSR build
    zero_deg_kernel<<<(NN+255)/256, 256>>>();
    hist_kernel<<<(EE+255)/256, 256>>>(dstArr);
    scan_kernel<<<1, 1024>>>();
    scatter_kernel<<<(EE+255)/256, 256>>>(dstArr);
    sort_kernel<<<(NN+255)/256, 256>>>();

    // weight converts + fingerprint partials (independent)
    wt2half_kernel<<<dim3(32, 16, 2), dim3(32, 32)>>>(Wq2, Wk2);
    wfin2half_kernel<<<dim3(32, 40), dim3(32, 32)>>>(Wfin);
    gemm_fp64<<<dim3((BB+63)/64, 4, 4), 256>>>(fpb, Wfp);
    fpcc_kernel<<<(BB*128+255)/256, 256>>>(bfp);

    // layer 1
    proj1_kernel<<<(NN*32+255)/256, 256>>>(x, Wq1,bq1, Wk1,bk1, Wv1,bv1, Ws1,bs1);
    attn1_kernel<<<BB, 640, SM1>>>(q1h, k1h, v1h, s1, ea, We1, srcArr, ph1, h1h);

    // layer-2 q,k projections (both fp16 out)
    {
        dim3 grid((NN+127)/128, 1024/128, 2);
        gemm2_f16_kernel<<<grid, 256>>>(h1h, bq2, bk2, NN);
    }

    // layer-2 attention weights -> z, r, cnt
    attn2_kernel<<<BB, 640, SM2>>>(q2h, k2h, h1h, ea, We2, srcArr);

    // cch[:, :1024] = ph1@Ws2 + z@Wv2 + bs2 + edge/bias terms (fp16 direct)
    gemm_pool64<<<dim3((BB+63)/64, 1024/64), 256>>>(Ws2, Wv2, bs2, We2, bv2);

    // final GEMM on tensor cores, split-K=4, then reduce
    gemmfin_f16_kernel<<<dim3((BB+127)/128, 1024/128, 4), 256>>>(BB);
    reduce_fin_kernel<<<(BB*256+255)/256, 256>>>(bfin, (float*)d_out);
}

// round 13
// speedup vs baseline: 3.5545x; 1.0336x over previous
#include <cuda_runtime.h>
#include <cuda_fp16.h>
#include <math.h>
#include <stdint.h>

#define NN 24000
#define EE 96000
#define BB 1200
#define NPG 20

// ---------------- device scratch ----------------
__device__ __half g_q1h[NN*512];
__device__ __half g_s1h[NN*512];
__device__ __half g_k1h[NN*512];
__device__ __half g_v1h[NN*512];
__device__ __half g_h1h[NN*512];
__device__ float  g_ph1[BB*512];
__device__ __half g_q2h[NN*1024];
__device__ __half g_k2h[NN*1024];
__device__ float  g_z[BB*2048];
__device__ float  g_r[BB*16];
__device__ float  g_cnt[BB];
__device__ int    g_deg[NN];
__device__ int    g_offs[NN+1];
__device__ int    g_cursor[NN];
__device__ int    g_eidx[EE];
__device__ __half g_w2h[2*1024*512];
__device__ __half g_wfinh[1024*1280];
__device__ __half g_cch[BB*1280];
__device__ float  g_fppart[4*BB*256];
__device__ float  g_fpart[4*BB*1024];

// ---------------- side stream + events (created once at program init) ----------------
static cudaStream_t g_sB;
static cudaEvent_t  g_evA0, g_evCSR, g_evB1, g_evB2;
namespace {
struct StreamInit {
    StreamInit() {
        cudaStreamCreateWithFlags(&g_sB, cudaStreamNonBlocking);
        cudaEventCreateWithFlags(&g_evA0,  cudaEventDisableTiming);
        cudaEventCreateWithFlags(&g_evCSR, cudaEventDisableTiming);
        cudaEventCreateWithFlags(&g_evB1,  cudaEventDisableTiming);
        cudaEventCreateWithFlags(&g_evB2,  cudaEventDisableTiming);
    }
};
static StreamInit g_streamInit;
}

__device__ __forceinline__ void cpa16(void* dst, const void* src, bool pred) {
    uint32_t d = (uint32_t)__cvta_generic_to_shared(dst);
    int sz = pred ? 16 : 0;
    asm volatile("cp.async.cg.shared.global [%0], [%1], 16, %2;\n"
                 :: "r"(d), "l"(src), "r"(sz));
}

// ---------------- CSR build ----------------
__global__ void zero_deg_kernel() {
    int i = blockIdx.x*blockDim.x + threadIdx.x;
    if (i < NN) g_deg[i] = 0;
}

__global__ void hist_kernel(const int* __restrict__ dst) {
    int e = blockIdx.x*blockDim.x + threadIdx.x;
    if (e < EE) atomicAdd(&g_deg[dst[e]], 1);
}

__global__ void scan_kernel() {
    __shared__ int wsum[32];
    __shared__ int carry;
    int tid = threadIdx.x;
    int lane = tid & 31, wid = tid >> 5;
    if (tid == 0) carry = 0;
    __syncthreads();
    for (int base = 0; base < NN; base += 1024) {
        int i = base + tid;
        int v = (i < NN) ? g_deg[i] : 0;
        int x = v;
        #pragma unroll
        for (int o = 1; o < 32; o <<= 1) {
            int y = __shfl_up_sync(0xffffffffu, x, o);
            if (lane >= o) x += y;
        }
        if (lane == 31) wsum[wid] = x;
        __syncthreads();
        if (wid == 0) {
            int s = wsum[lane];
            #pragma unroll
            for (int o = 1; o < 32; o <<= 1) {
                int y = __shfl_up_sync(0xffffffffu, s, o);
                if (lane >= o) s += y;
            }
            wsum[lane] = s;
        }
        __syncthreads();
        int pre = (wid > 0 ? wsum[wid-1] : 0) + carry;
        int incl = x + pre;
        if (i < NN) { g_offs[i] = incl - v; g_cursor[i] = incl - v; }
        __syncthreads();
        if (tid == 1023) carry = incl;
        __syncthreads();
    }
    if (tid == 0) g_offs[NN] = carry;
}

__global__ void scatter_kernel(const int* __restrict__ dst) {
    int e = blockIdx.x*blockDim.x + threadIdx.x;
    if (e < EE) {
        int p = atomicAdd(&g_cursor[dst[e]], 1);
        g_eidx[p] = e;
    }
}

__global__ void sort_kernel() {
    int n = blockIdx.x*blockDim.x + threadIdx.x;
    if (n >= NN) return;
    int a = g_offs[n], b = g_offs[n+1];
    for (int i = a+1; i < b; ++i) {
        int key = g_eidx[i];
        int j = i-1;
        while (j >= a && g_eidx[j] > key) { g_eidx[j+1] = g_eidx[j]; --j; }
        g_eidx[j+1] = key;
    }
}

// ---------------- layer-1 projections: q,k,v,s all fp16 ----------------
__global__ void proj1_kernel(const float* __restrict__ x,
    const float* __restrict__ Wq, const float* __restrict__ bq,
    const float* __restrict__ Wk, const float* __restrict__ bk,
    const float* __restrict__ Wv, const float* __restrict__ bv,
    const float* __restrict__ Ws, const float* __restrict__ bs)
{
    int warp = (blockIdx.x*blockDim.x + threadIdx.x) >> 5;
    int lane = threadIdx.x & 31;
    if (warp >= NN) return;
    float xr[9];
    #pragma unroll
    for (int t = 0; t < 9; ++t) xr[t] = __ldg(&x[warp*9 + t]);
    for (int j = lane; j < 512; j += 32) {
        float aq = __ldg(&bq[j]), ak = __ldg(&bk[j]);
        float av = __ldg(&bv[j]), as_ = __ldg(&bs[j]);
        #pragma unroll
        for (int t = 0; t < 9; ++t) {
            float xv = xr[t];
            aq  = fmaf(xv, __ldg(&Wq[t*512+j]), aq);
            ak  = fmaf(xv, __ldg(&Wk[t*512+j]), ak);
            av  = fmaf(xv, __ldg(&Wv[t*512+j]), av);
            as_ = fmaf(xv, __ldg(&Ws[t*512+j]), as_);
        }
        size_t o = (size_t)warp*512 + j;
        g_q1h[o] = __float2half_rn(aq);
        g_k1h[o] = __float2half_rn(ak);
        g_v1h[o] = __float2half_rn(av);
        g_s1h[o] = __float2half_rn(as_);
    }
}

// ---------------- layer-1 per-graph attention (q,s fp16) ----------------
__global__ void __launch_bounds__(640, 1) attn1_kernel(
    const __half* __restrict__ qh, const __half* __restrict__ khg,
    const __half* __restrict__ vhg, const __half* __restrict__ sh,
    const float* __restrict__ ea, const float* __restrict__ We,
    const int* __restrict__ srcArr, float* __restrict__ outPooled,
    __half* __restrict__ h1h)
{
    constexpr int D = 512, H = 4;
    constexpr int VPT = D / 32;   // 16
    constexpr int NU = VPT / 8;   // 2
    constexpr int C = D / H;
    extern __shared__ char smraw[];
    float*  sWeT = (float*)smraw;
    __half* kh   = (__half*)(smraw + 16*D);
    __half* vh   = (__half*)(smraw + 16*D + 40*D);
    float*  poolbuf = (float*)kh;

    int tid = threadIdx.x;
    int wid = tid >> 5, lane = tid & 31;
    int graph = blockIdx.x;
    int gbase = graph * NPG;

    for (int i = tid; i < 4*D; i += 640) {
        int c = i >> 2, t = i & 3;
        sWeT[i] = __ldg(&We[t*D + c]);
    }
    {
        const uint4* ks = (const uint4*)(khg + (size_t)gbase*D);
        const uint4* vs = (const uint4*)(vhg + (size_t)gbase*D);
        uint4* kd = (uint4*)kh;
        uint4* vd = (uint4*)vh;
        for (int i = tid; i < NPG*D/8; i += 640) { kd[i] = __ldg(ks+i); vd[i] = __ldg(vs+i); }
    }
    __syncthreads();

    int node = gbase + wid;
    int cbase = lane * VPT;
    const float4* sWe4 = (const float4*)sWeT;

    float qrf[VPT], accf[VPT];
    {
        const uint4* q4 = (const uint4*)(qh + (size_t)node*D + cbase);
        #pragma unroll
        for (int i = 0; i < NU; ++i) {
            uint4 u = __ldg(q4 + i);
            const __half2* h2 = (const __half2*)&u;
            #pragma unroll
            for (int j = 0; j < 4; ++j) {
                float2 f = __half22float2(h2[j]);
                qrf[8*i+2*j] = f.x; qrf[8*i+2*j+1] = f.y;
            }
        }
    }
    #pragma unroll
    for (int i = 0; i < VPT; ++i) accf[i] = 0.f;

    float4 qe = make_float4(0.f,0.f,0.f,0.f);
    #pragma unroll
    for (int i = 0; i < VPT; ++i) {
        float4 w = sWe4[cbase + i];
        qe.x = fmaf(qrf[i], w.x, qe.x);
        qe.y = fmaf(qrf[i], w.y, qe.y);
        qe.z = fmaf(qrf[i], w.z, qe.z);
        qe.w = fmaf(qrf[i], w.w, qe.w);
    }
    #pragma unroll
    for (int o = 1; o < 8; o <<= 1) {
        qe.x += __shfl_xor_sync(0xffffffffu, qe.x, o);
        qe.y += __shfl_xor_sync(0xffffffffu, qe.y, o);
        qe.z += __shfl_xor_sync(0xffffffffu, qe.z, o);
        qe.w += __shfl_xor_sync(0xffffffffu, qe.w, o);
    }

    float m = -INFINITY, den = 0.f;
    float4 wa = make_float4(0.f,0.f,0.f,0.f);
    const float invs = rsqrtf((float)C);

    int e0 = g_offs[node], e1 = g_offs[node+1];
    for (int t = e0; t < e1; ++t) {
        int e  = __ldg(&g_eidx[t]);
        int ln = __ldg(&srcArr[e]) - gbase;
        float4 a4 = __ldg((const float4*)ea + e);

        const uint4* krow = (const uint4*)(kh + ln*D + cbase);
        float p = 0.f;
        #pragma unroll
        for (int i = 0; i < NU; ++i) {
            uint4 u = krow[i];
            const __half2* h2 = (const __half2*)&u;
            #pragma unroll
            for (int j = 0; j < 4; ++j) {
                float2 f = __half22float2(h2[j]);
                p = fmaf(qrf[8*i+2*j], f.x, p);
                p = fmaf(qrf[8*i+2*j+1], f.y, p);
            }
        }
        p += __shfl_xor_sync(0xffffffffu, p, 1);
        p += __shfl_xor_sync(0xffffffffu, p, 2);
        p += __shfl_xor_sync(0xffffffffu, p, 4);
        float alpha = (p + qe.x*a4.x + qe.y*a4.y + qe.z*a4.z + qe.w*a4.w) * invs;

        float nm = fmaxf(m, alpha);
        float sc = __expf(m - nm);
        float w  = __expf(alpha - nm);
        den = den*sc + w;
        m = nm;

        const uint4* vrow = (const uint4*)(vh + ln*D + cbase);
        #pragma unroll
        for (int i = 0; i < NU; ++i) {
            uint4 u = vrow[i];
            const __half2* h2 = (const __half2*)&u;
            #pragma unroll
            for (int j = 0; j < 4; ++j) {
                float2 f = __half22float2(h2[j]);
                accf[8*i+2*j]   = accf[8*i+2*j]*sc   + w*f.x;
                accf[8*i+2*j+1] = accf[8*i+2*j+1]*sc + w*f.y;
            }
        }
        wa.x = wa.x*sc + w*a4.x; wa.y = wa.y*sc + w*a4.y;
        wa.z = wa.z*sc + w*a4.z; wa.w = wa.w*sc + w*a4.w;
    }

    float r = 1.f / (den + 1e-16f);
    float outv[VPT];
    {
        const __half2* s2p = (const __half2*)(sh + (size_t)node*D + cbase);
        #pragma unroll
        for (int i = 0; i < VPT; ++i) {
            float4 w = sWe4[cbase + i];
            float msg = (accf[i] + wa.x*w.x + wa.y*w.y + wa.z*w.z + wa.w*w.w) * r;
            outv[i] = msg;
        }
        #pragma unroll
        for (int i = 0; i < VPT/2; ++i) {
            float2 sv = __half22float2(__ldg(s2p + i));
            outv[2*i]   = fmaxf(outv[2*i]   + sv.x, 0.f);
            outv[2*i+1] = fmaxf(outv[2*i+1] + sv.y, 0.f);
        }
    }
    {
        __half2* h4 = (__half2*)(h1h + (size_t)node*D + cbase);
        #pragma unroll
        for (int i = 0; i < VPT/2; ++i)
            h4[i] = __floats2half2_rn(outv[2*i], outv[2*i+1]);
    }

    __syncthreads();
    #pragma unroll
    for (int i = 0; i < VPT; ++i) poolbuf[wid*D + cbase + i] = outv[i];
    __syncthreads();
    for (int c = tid; c < D; c += 640) {
        float sum = 0.f;
        #pragma unroll
        for (int i = 0; i < NPG; ++i) sum += poolbuf[i*D + c];
        outPooled[(size_t)graph*512 + c] = sum * (1.f/NPG);
    }
}

// ---------------- layer-2 attention: softmax weights only (q fp16) ----------------
__global__ void __launch_bounds__(640, 1) attn2_kernel(
    const __half* __restrict__ qh, const __half* __restrict__ khg,
    const __half* __restrict__ h1g,
    const float* __restrict__ ea, const float* __restrict__ We,
    const int* __restrict__ srcArr)
{
    constexpr int D = 1024, H = 4;
    constexpr int VPT = D / 32;   // 32
    constexpr int NU = VPT / 8;   // 4
    constexpr int C = D / H;
    constexpr int ECAP = 256;
    extern __shared__ char smraw[];
    float*  sWeT   = (float*)smraw;
    __half* kh     = (__half*)(smraw + 16*D);
    __half* h1s    = (__half*)(smraw + 16*D + 2*NPG*D);
    float*  alphaS = (float*)(smraw + 16*D + 2*NPG*D + NPG*1024);
    float*  wS     = alphaS + ECAP*H;
    int*    lnS    = (int*)(wS + ECAP*H);
    float*  cS     = (float*)(lnS + ECAP);
    int*    hasE   = (int*)(cS + NPG*H);

    int tid = threadIdx.x;
    int wid = tid >> 5, lane = tid & 31;
    int graph = blockIdx.x;
    int gbase = graph * NPG;
    int head = lane >> 3;

    for (int i = tid; i < 4*D; i += 640) {
        int c = i >> 2, t = i & 3;
        sWeT[i] = __ldg(&We[t*D + c]);
    }
    {
        const uint4* ks = (const uint4*)(khg + (size_t)gbase*D);
        uint4* kd = (uint4*)kh;
        for (int i = tid; i < NPG*D/8; i += 640) kd[i] = __ldg(ks+i);
        const uint4* hs = (const uint4*)(h1g + (size_t)gbase*512);
        uint4* hd = (uint4*)h1s;
        for (int i = tid; i < NPG*512/8; i += 640) hd[i] = __ldg(hs+i);
    }
    __syncthreads();

    int node = gbase + wid;
    int cbase = lane * VPT;
    const float4* sWe4 = (const float4*)sWeT;

    float qrf[VPT];
    {
        const uint4* q4 = (const uint4*)(qh + (size_t)node*D + cbase);
        #pragma unroll
        for (int i = 0; i < NU; ++i) {
            uint4 u = __ldg(q4 + i);
            const __half2* h2 = (const __half2*)&u;
            #pragma unroll
            for (int j = 0; j < 4; ++j) {
                float2 f = __half22float2(h2[j]);
                qrf[8*i+2*j] = f.x; qrf[8*i+2*j+1] = f.y;
            }
        }
    }

    float4 qe = make_float4(0.f,0.f,0.f,0.f);
    #pragma unroll
    for (int i = 0; i < VPT; ++i) {
        float4 w = sWe4[cbase + i];
        qe.x = fmaf(qrf[i], w.x, qe.x);
        qe.y = fmaf(qrf[i], w.y, qe.y);
        qe.z = fmaf(qrf[i], w.z, qe.z);
        qe.w = fmaf(qrf[i], w.w, qe.w);
    }
    #pragma unroll
    for (int o = 1; o < 8; o <<= 1) {
        qe.x += __shfl_xor_sync(0xffffffffu, qe.x, o);
        qe.y += __shfl_xor_sync(0xffffffffu, qe.y, o);
        qe.z += __shfl_xor_sync(0xffffffffu, qe.z, o);
        qe.w += __shfl_xor_sync(0xffffffffu, qe.w, o);
    }

    const float invs = rsqrtf((float)C);
    int eb = g_offs[gbase];
    int cntE = g_offs[gbase + NPG] - eb;
    int e0 = g_offs[node], e1 = g_offs[node+1];

    float m = -INFINITY, den = 0.f;
    for (int t = e0; t < e1; ++t) {
        int e  = __ldg(&g_eidx[t]);
        int ln = __ldg(&srcArr[e]) - gbase;
        float4 a4 = __ldg((const float4*)ea + e);

        const uint4* krow = (const uint4*)(kh + ln*D + cbase);
        float p = 0.f;
        #pragma unroll
        for (int i = 0; i < NU; ++i) {
            uint4 u = krow[i];
            const __half2* h2 = (const __half2*)&u;
            #pragma unroll
            for (int j = 0; j < 4; ++j) {
                float2 f = __half22float2(h2[j]);
                p = fmaf(qrf[8*i+2*j], f.x, p);
                p = fmaf(qrf[8*i+2*j+1], f.y, p);
            }
        }
        p += __shfl_xor_sync(0xffffffffu, p, 1);
        p += __shfl_xor_sync(0xffffffffu, p, 2);
        p += __shfl_xor_sync(0xffffffffu, p, 4);
        float alpha = (p + qe.x*a4.x + qe.y*a4.y + qe.z*a4.z + qe.w*a4.w) * invs;

        float nm = fmaxf(m, alpha);
        den = den*__expf(m - nm) + __expf(alpha - nm);
        m = nm;
        if ((lane & 7) == 0) alphaS[(t - eb)*H + head] = alpha;
        if (lane == 0) lnS[t - eb] = ln;
    }
    float rdn = (e1 > e0) ? 1.f/den : 0.f;
    if ((lane & 7) == 0) {
        for (int t = e0; t < e1; ++t) {
            float w = __expf(alphaS[(t - eb)*H + head] - m) * rdn;
            wS[(t - eb)*H + head] = w;
        }
    }
    if (lane == 0) hasE[wid] = (e1 > e0) ? 1 : 0;
    __syncthreads();

    if (tid < NPG*H) {
        int ln = tid >> 2, h = tid & 3;
        float c = 0.f;
        for (int i = 0; i < cntE; ++i)
            if (lnS[i] == ln) c += wS[i*H + h];
        cS[tid] = c * (1.f/NPG);
    } else if (tid < NPG*H + 16) {
        int idx = tid - NPG*H;
        int h = idx >> 2, t4 = idx & 3;
        float r = 0.f;
        for (int i = 0; i < cntE; ++i) {
            int e = __ldg(&g_eidx[eb + i]);
            r += wS[i*H + h] * __ldg(&ea[e*4 + t4]);
        }
        g_r[graph*16 + h*4 + t4] = r * (1.f/NPG);
    } else if (tid == NPG*H + 16) {
        int c = 0;
        #pragma unroll
        for (int i = 0; i < NPG; ++i) c += hasE[i];
        g_cnt[graph] = (float)c;
    }
    __syncthreads();

    for (int o = tid; o < H*512; o += 640) {
        int h = o >> 9, c = o & 511;
        float z = 0.f;
        #pragma unroll
        for (int ln = 0; ln < NPG; ++ln)
            z = fmaf(cS[ln*H + h], __half2float(h1s[ln*512 + c]), z);
        g_z[(size_t)graph*2048 + o] = z;
    }
}

// ---------------- weight transpose+fp16 converts ----------------
__global__ void wt2half_kernel(const float* __restrict__ W0, const float* __restrict__ W1) {
    __shared__ float tile[32][33];
    int z = blockIdx.z;
    const float* W = (z==0) ? W0 : W1;
    int n0 = blockIdx.x * 32, k0 = blockIdx.y * 32;
    int tx = threadIdx.x, ty = threadIdx.y;
    tile[ty][tx] = __ldg(&W[(size_t)(k0+ty)*1024 + n0 + tx]);
    __syncthreads();
    g_w2h[(size_t)z*1024*512 + (size_t)(n0+ty)*512 + k0 + tx] = __float2half_rn(tile[tx][ty]);
}

__global__ void wfin2half_kernel(const float* __restrict__ W) {
    __shared__ float tile[32][33];
    int n0 = blockIdx.x * 32, k0 = blockIdx.y * 32;
    int tx = threadIdx.x, ty = threadIdx.y;
    tile[ty][tx] = __ldg(&W[(size_t)(k0+ty)*1024 + n0 + tx]);
    __syncthreads();
    g_wfinh[(size_t)(n0+ty)*1280 + k0 + tx] = __float2half_rn(tile[tx][ty]);
}

// ---------------- f16 tensor-core GEMM: q2h/k2h both fp16 out ----------------
__global__ void __launch_bounds__(256, 2) gemm2_f16_kernel(
    const __half* __restrict__ Ah,
    const float* __restrict__ b0, const float* __restrict__ b1,
    int M)
{
    __shared__ __align__(16) uint32_t As[3][128][20];
    __shared__ __align__(16) uint32_t Bs[3][128][20];

    int z = blockIdx.z;
    const __half* Bz  = g_w2h + (size_t)z*1024*512;
    const float* bias = (z==0) ? b0 : b1;
    __half* Ch = (z==0) ? g_q2h : g_k2h;

    int tid  = threadIdx.x;
    int lane = tid & 31, wid = tid >> 5;
    int wm = wid >> 2, wn = wid & 3;
    int m0 = blockIdx.x * 128, n0 = blockIdx.y * 128;
    int g = lane >> 2, t = lane & 3;

    int lm[2], lq[2];
    #pragma unroll
    for (int i = 0; i < 2; ++i) {
        int idx = tid + i*256;
        lm[i] = idx >> 2;
        lq[i] = (idx & 3) * 8;
    }

    float acc[4][4][4];
    #pragma unroll
    for (int a = 0; a < 4; ++a)
        #pragma unroll
        for (int b = 0; b < 4; ++b)
            #pragma unroll
            for (int c = 0; c < 4; ++c) acc[a][b][c] = 0.f;

    const int T = 512 / 32;

    #pragma unroll
    for (int pt = 0; pt < 2; ++pt) {
        int ko = pt * 32;
        #pragma unroll
        for (int i = 0; i < 2; ++i) {
            cpa16(&As[pt][lm[i]][lq[i]>>1],
                  Ah + (size_t)(m0+lm[i])*512 + ko + lq[i], (m0+lm[i]) < M);
            cpa16(&Bs[pt][lm[i]][lq[i]>>1],
                  Bz + (size_t)(n0+lm[i])*512 + ko + lq[i], true);
        }
        asm volatile("cp.async.commit_group;\n");
    }

    for (int kt = 0; kt < T; ++kt) {
        int sl = kt % 3;
        asm volatile("cp.async.wait_group 1;\n");
        __syncthreads();

        if (kt + 2 < T) {
            int ns = (kt + 2) % 3;
            int ko = (kt + 2) * 32;
            #pragma unroll
            for (int i = 0; i < 2; ++i) {
                cpa16(&As[ns][lm[i]][lq[i]>>1],
                      Ah + (size_t)(m0+lm[i])*512 + ko + lq[i], (m0+lm[i]) < M);
                cpa16(&Bs[ns][lm[i]][lq[i]>>1],
                      Bz + (size_t)(n0+lm[i])*512 + ko + lq[i], true);
            }
        }
        asm volatile("cp.async.commit_group;\n");

        #pragma unroll
        for (int ks = 0; ks < 2; ++ks) {
            int kb = ks * 8;
            uint32_t af[4][4], bf[4][2];
            #pragma unroll
            for (int mt = 0; mt < 4; ++mt) {
                int mb = wm*64 + mt*16;
                af[mt][0] = As[sl][mb+g  ][kb+t  ];
                af[mt][1] = As[sl][mb+g+8][kb+t  ];
                af[mt][2] = As[sl][mb+g  ][kb+t+4];
                af[mt][3] = As[sl][mb+g+8][kb+t+4];
            }
            #pragma unroll
            for (int nt = 0; nt < 4; ++nt) {
                int nb = wn*32 + nt*8;
                bf[nt][0] = Bs[sl][nb+g][kb+t  ];
                bf[nt][1] = Bs[sl][nb+g][kb+t+4];
            }
            #pragma unroll
            for (int mt = 0; mt < 4; ++mt)
                #pragma unroll
                for (int nt = 0; nt < 4; ++nt) {
                    asm volatile(
                        "mma.sync.aligned.m16n8k16.row.col.f32.f16.f16.f32 "
                        "{%0,%1,%2,%3}, {%4,%5,%6,%7}, {%8,%9}, {%0,%1,%2,%3};"
                        : "+f"(acc[mt][nt][0]), "+f"(acc[mt][nt][1]),
                          "+f"(acc[mt][nt][2]), "+f"(acc[mt][nt][3])
                        : "r"(af[mt][0]), "r"(af[mt][1]), "r"(af[mt][2]), "r"(af[mt][3]),
                          "r"(bf[nt][0]), "r"(bf[nt][1]));
                }
        }
    }

    #pragma unroll
    for (int mt = 0; mt < 4; ++mt) {
        int r0 = m0 + wm*64 + mt*16 + g;
        #pragma unroll
        for (int nt = 0; nt < 4; ++nt) {
            int c = n0 + wn*32 + nt*8 + t*2;
            float bv0 = __ldg(&bias[c]), bv1 = __ldg(&bias[c+1]);
            if (r0 < M)
                *(__half2*)&Ch[(size_t)r0*1024 + c] =
                    __floats2half2_rn(acc[mt][nt][0] + bv0, acc[mt][nt][1] + bv1);
            if (r0 + 8 < M)
                *(__half2*)&Ch[(size_t)(r0+8)*1024 + c] =
                    __floats2half2_rn(acc[mt][nt][2] + bv0, acc[mt][nt][3] + bv1);
        }
    }
}

// ---------------- final-GEMM f16 tensor kernel, split-K partials ----------------
__global__ void __launch_bounds__(256) gemmfin_f16_kernel(int M)
{
    __shared__ uint32_t As[2][128][20];
    __shared__ uint32_t Bs[2][128][20];

    int zs = blockIdx.z;
    int kbase = zs * 320;
    float* P = g_fpart + (size_t)zs*BB*1024;

    int tid  = threadIdx.x;
    int lane = tid & 31, wid = tid >> 5;
    int wm = wid >> 2, wn = wid & 3;
    int m0 = blockIdx.x * 128, n0 = blockIdx.y * 128;
    int g = lane >> 2, t = lane & 3;

    int lm[2], lq[2];
    #pragma unroll
    for (int i = 0; i < 2; ++i) {
        int idx = tid + i*256;
        lm[i] = idx >> 2;
        lq[i] = (idx & 3) * 8;
    }

    float acc[4][4][4];
    #pragma unroll
    for (int a = 0; a < 4; ++a)
        #pragma unroll
        for (int b = 0; b < 4; ++b)
            #pragma unroll
            for (int c = 0; c < 4; ++c) acc[a][b][c] = 0.f;

    float4 pa[2], pb[2];
    const int T = 10;

    #pragma unroll
    for (int i = 0; i < 2; ++i) {
        pa[i] = (m0 + lm[i] < M)
              ? *(const float4*)(g_cch + (size_t)(m0+lm[i])*1280 + kbase + lq[i])
              : make_float4(0.f,0.f,0.f,0.f);
        pb[i] = *(const float4*)(g_wfinh + (size_t)(n0+lm[i])*1280 + kbase + lq[i]);
    }
    #pragma unroll
    for (int i = 0; i < 2; ++i) {
        *(float4*)&As[0][lm[i]][lq[i]>>1] = pa[i];
        *(float4*)&Bs[0][lm[i]][lq[i]>>1] = pb[i];
    }
    __syncthreads();

    for (int kt = 0; kt < T; ++kt) {
        int b = kt & 1;
        if (kt + 1 < T) {
            int ko = kbase + (kt+1) * 32;
            #pragma unroll
            for (int i = 0; i < 2; ++i) {
                pa[i] = (m0 + lm[i] < M)
                      ? *(const float4*)(g_cch + (size_t)(m0+lm[i])*1280 + ko + lq[i])
                      : make_float4(0.f,0.f,0.f,0.f);
                pb[i] = *(const float4*)(g_wfinh + (size_t)(n0+lm[i])*1280 + ko + lq[i]);
            }
        }

        #pragma unroll
        for (int ks = 0; ks < 2; ++ks) {
            int kb = ks * 8;
            uint32_t af[4][4], bf[4][2];
            #pragma unroll
            for (int mt = 0; mt < 4; ++mt) {
                int mb = wm*64 + mt*16;
                af[mt][0] = As[b][mb+g  ][kb+t  ];
                af[mt][1] = As[b][mb+g+8][kb+t  ];
                af[mt][2] = As[b][mb+g  ][kb+t+4];
                af[mt][3] = As[b][mb+g+8][kb+t+4];
            }
            #pragma unroll
            for (int nt = 0; nt < 4; ++nt) {
                int nb = wn*32 + nt*8;
                bf[nt][0] = Bs[b][nb+g][kb+t  ];
                bf[nt][1] = Bs[b][nb+g][kb+t+4];
            }
            #pragma unroll
            for (int mt = 0; mt < 4; ++mt)
                #pragma unroll
                for (int nt = 0; nt < 4; ++nt) {
                    asm volatile(
                        "mma.sync.aligned.m16n8k16.row.col.f32.f16.f16.f32 "
                        "{%0,%1,%2,%3}, {%4,%5,%6,%7}, {%8,%9}, {%0,%1,%2,%3};"
                        : "+f"(acc[mt][nt][0]), "+f"(acc[mt][nt][1]),
                          "+f"(acc[mt][nt][2]), "+f"(acc[mt][nt][3])
                        : "r"(af[mt][0]), "r"(af[mt][1]), "r"(af[mt][2]), "r"(af[mt][3]),
                          "r"(bf[nt][0]), "r"(bf[nt][1]));
                }
        }

        if (kt + 1 < T) {
            int nb_ = b ^ 1;
            #pragma unroll
            for (int i = 0; i < 2; ++i) {
                *(float4*)&As[nb_][lm[i]][lq[i]>>1] = pa[i];
                *(float4*)&Bs[nb_][lm[i]][lq[i]>>1] = pb[i];
            }
            __syncthreads();
        }
    }

    #pragma unroll
    for (int mt = 0; mt < 4; ++mt) {
        int r0 = m0 + wm*64 + mt*16 + g;
        #pragma unroll
        for (int nt = 0; nt < 4; ++nt) {
            int c = n0 + wn*32 + nt*8 + t*2;
            if (r0 < M)
                *(float2*)&P[(size_t)r0*1024 + c] = make_float2(acc[mt][nt][0], acc[mt][nt][1]);
            if (r0 + 8 < M)
                *(float2*)&P[(size_t)(r0+8)*1024 + c] = make_float2(acc[mt][nt][2], acc[mt][nt][3]);
        }
    }
}

// ---------------- fp32 64x64 GEMM: pooled skip + z@Wv2 + edge/bias -> cch fp16 ------
__global__ void __launch_bounds__(256) gemm_pool64(
    const float* __restrict__ Ws2, const float* __restrict__ Wv2,
    const float* __restrict__ bs2,
    const float* __restrict__ We2, const float* __restrict__ bv2)
{
    __shared__ float As[16][68];
    __shared__ float Bs[16][68];
    int tid = threadIdx.x;
    int tx = tid & 15, ty = tid >> 4;
    int m0 = blockIdx.x * 64;
    int n0 = blockIdx.y * 64;
    int h = n0 >> 8;
    int hOff = h * 512;
    float acc[4][4] = {};

    int arow = tid >> 2, ac4 = (tid & 3)*4;
    int brow = tid >> 4, bc4 = (tid & 15)*4;

    #pragma unroll 1
    for (int half_ = 0; half_ < 2; ++half_) {
        const float* Bm = half_ ? Wv2 : Ws2;
        for (int k0 = 0; k0 < 512; k0 += 16) {
            float4 av = make_float4(0.f,0.f,0.f,0.f);
            if (m0 + arow < BB) {
                av = half_
                   ? __ldg((const float4*)&g_z[(size_t)(m0+arow)*2048 + hOff + k0 + ac4])
                   : __ldg((const float4*)&g_ph1[(size_t)(m0+arow)*512 + k0 + ac4]);
            }
            As[ac4+0][arow] = av.x; As[ac4+1][arow] = av.y;
            As[ac4+2][arow] = av.z; As[ac4+3][arow] = av.w;
            float4 bv = __ldg((const float4*)&Bm[(size_t)(k0+brow)*1024 + n0 + bc4]);
            *(float4*)&Bs[brow][bc4] = bv;
            __syncthreads();
            #pragma unroll
            for (int kk = 0; kk < 16; ++kk) {
                float a[4], b[4];
                *(float4*)a = *(const float4*)&As[kk][ty*4];
                *(float4*)b = *(const float4*)&Bs[kk][tx*4];
                #pragma unroll
                for (int i = 0; i < 4; ++i)
                    #pragma unroll
                    for (int j = 0; j < 4; ++j)
                        acc[i][j] = fmaf(a[i], b[j], acc[i][j]);
            }
            __syncthreads();
        }
    }
    #pragma unroll
    for (int i = 0; i < 4; ++i) {
        int row = m0 + ty*4 + i;
        if (row < BB) {
            float cfac = g_cnt[row] * (1.f/NPG);
            float r0 = g_r[row*16 + h*4 + 0], r1 = g_r[row*16 + h*4 + 1];
            float r2 = g_r[row*16 + h*4 + 2], r3 = g_r[row*16 + h*4 + 3];
            __half hbuf[4];
            #pragma unroll
            for (int j = 0; j < 4; ++j) {
                int col = n0 + tx*4 + j;
                float v = acc[i][j] + __ldg(&bs2[col]) + cfac*__ldg(&bv2[col]);
                v = fmaf(r0, __ldg(&We2[0*1024 + col]), v);
                v = fmaf(r1, __ldg(&We2[1*1024 + col]), v);
                v = fmaf(r2, __ldg(&We2[2*1024 + col]), v);
                v = fmaf(r3, __ldg(&We2[3*1024 + col]), v);
                hbuf[j] = __float2half_rn(v);
            }
            *(uint2*)&g_cch[(size_t)row*1280 + n0 + tx*4] = *(uint2*)hbuf;
        }
    }
}

// ---------------- fingerprint GEMM partials: fpb @ Wfp, split-K=4 ----------------
__global__ void __launch_bounds__(256) gemm_fp64(
    const float* __restrict__ A, const float* __restrict__ Bm)
{
    __shared__ float As[16][68];
    __shared__ float Bs[16][68];
    int tid = threadIdx.x;
    int tx = tid & 15, ty = tid >> 4;
    int m0 = blockIdx.x * 64;
    int n0 = blockIdx.y * 64;
    int zs = blockIdx.z;
    int kb = zs * 512;
    float acc[4][4] = {};

    int arow = tid >> 2, ac4 = (tid & 3)*4;
    int brow = tid >> 4, bc4 = (tid & 15)*4;

    for (int k0 = kb; k0 < kb + 512; k0 += 16) {
        float4 av = make_float4(0.f,0.f,0.f,0.f);
        if (m0 + arow < BB)
            av = __ldg((const float4*)&A[(size_t)(m0+arow)*2048 + k0 + ac4]);
        As[ac4+0][arow] = av.x; As[ac4+1][arow] = av.y;
        As[ac4+2][arow] = av.z; As[ac4+3][arow] = av.w;
        float4 bv = __ldg((const float4*)&Bm[(size_t)(k0+brow)*256 + n0 + bc4]);
        *(float4*)&Bs[brow][bc4] = bv;
        __syncthreads();
        #pragma unroll
        for (int kk = 0; kk < 16; ++kk) {
            float a[4], b[4];
            *(float4*)a = *(const float4*)&As[kk][ty*4];
            *(float4*)b = *(const float4*)&Bs[kk][tx*4];
            #pragma unroll
            for (int i = 0; i < 4; ++i)
                #pragma unroll
                for (int j = 0; j < 4; ++j)
                    acc[i][j] = fmaf(a[i], b[j], acc[i][j]);
        }
        __syncthreads();
    }
    #pragma unroll
    for (int i = 0; i < 4; ++i) {
        int row = m0 + ty*4 + i;
        if (row < BB) {
            #pragma unroll
            for (int j = 0; j < 4; ++j) {
                int col = n0 + tx*4 + j;
                g_fppart[(size_t)zs*BB*256 + (size_t)row*256 + col] = acc[i][j];
            }
        }
    }
}

// ---------------- fingerprint cols -> cch fp16 (partial reduce + bfp) ----------------
__global__ void fpcc_kernel(const float* __restrict__ bfp)
{
    int i = blockIdx.x*blockDim.x + threadIdx.x;
    if (i >= BB*128) return;
    int row = i >> 7;
    int cc = (i & 127) * 2;
    float v0 = __ldg(&bfp[cc]), v1 = __ldg(&bfp[cc+1]);
    #pragma unroll
    for (int zp = 0; zp < 4; ++zp) {
        v0 += g_fppart[(size_t)zp*BB*256 + (size_t)row*256 + cc];
        v1 += g_fppart[(size_t)zp*BB*256 + (size_t)row*256 + cc + 1];
    }
    *(__half2*)&g_cch[(size_t)row*1280 + 1024 + cc] = __floats2half2_rn(v0, v1);
}

// ---------------- final reduce: d_out = bfin + sum of 4 partials ----------------
__global__ void reduce_fin_kernel(const float* __restrict__ bfin, float* __restrict__ out)
{
    int i = blockIdx.x*blockDim.x + threadIdx.x;
    if (i >= BB*256) return;
    int c4 = (i & 255) * 4;
    float4 acc = __ldg((const float4*)&bfin[c4]);
    #pragma unroll
    for (int zp = 0; zp < 4; ++zp) {
        float4 p = *(const float4*)&g_fpart[(size_t)zp*BB*1024 + (size_t)i*4];
        acc.x += p.x; acc.y += p.y; acc.z += p.z; acc.w += p.w;
    }
    ((float4*)out)[i] = acc;
}

// ---------------- launch ----------------
extern "C" void kernel_launch(void* const* d_in, const int* in_sizes, int n_in,
                              void* d_out, int out_size)
{
    const float* x    = (const float*)d_in[0];
    const int*   ei   = (const int*)  d_in[1];
    const float* ea   = (const float*)d_in[2];
    const float* fpb  = (const float*)d_in[4];
    const float *Wq1=(const float*)d_in[5],  *bq1=(const float*)d_in[6];
    const float *Wk1=(const float*)d_in[7],  *bk1=(const float*)d_in[8];
    const float *Wv1=(const float*)d_in[9],  *bv1=(const float*)d_in[10];
    const float *We1=(const float*)d_in[11];
    const float *Ws1=(const float*)d_in[12], *bs1=(const float*)d_in[13];
    const float *Wq2=(const float*)d_in[14], *bq2=(const float*)d_in[15];
    const float *Wk2=(const float*)d_in[16], *bk2=(const float*)d_in[17];
    const float *Wv2=(const float*)d_in[18], *bv2=(const float*)d_in[19];
    const float *We2=(const float*)d_in[20];
    const float *Ws2=(const float*)d_in[21], *bs2=(const float*)d_in[22];
    const float *Wfp=(const float*)d_in[23], *bfp=(const float*)d_in[24];
    const float *Wfin=(const float*)d_in[25],*bfin=(const float*)d_in[26];

    const int* srcArr = ei;
    const int* dstArr = ei + EE;

    float *ph1;
    __half *q1h,*s1h,*k1h,*v1h,*h1h,*q2h,*k2h;
    cudaGetSymbolAddress((void**)&q1h, g_q1h);
    cudaGetSymbolAddress((void**)&s1h, g_s1h);
    cudaGetSymbolAddress((void**)&k1h, g_k1h);
    cudaGetSymbolAddress((void**)&v1h, g_v1h);
    cudaGetSymbolAddress((void**)&h1h, g_h1h);
    cudaGetSymbolAddress((void**)&ph1, g_ph1);
    cudaGetSymbolAddress((void**)&q2h, g_q2h);
    cudaGetSymbolAddress((void**)&k2h, g_k2h);

    const int SM1 = 96*512;
    const int SM2 = 16*1024 + 2*NPG*1024 + NPG*1024
                  + 256*4*4*2 + 256*4 + NPG*4*4 + NPG*4 + 64;
    cudaFuncSetAttribute(attn1_kernel, cudaFuncAttributeMaxDynamicSharedMemorySize, SM1);
    cudaFuncSetAttribute(attn2_kernel, cudaFuncAttributeMaxDynamicSharedMemorySize, SM2);

    // ---- fork side stream ----
    cudaEventRecord(g_evA0, 0);
    cudaStreamWaitEvent(g_sB, g_evA0, 0);

    // side stream: CSR build -> weight converts -> fingerprint path
    zero_deg_kernel<<<(NN+255)/256, 256, 0, g_sB>>>();
    hist_kernel<<<(EE+255)/256, 256, 0, g_sB>>>(dstArr);
    scan_kernel<<<1, 1024, 0, g_sB>>>();
    scatter_kernel<<<(EE+255)/256, 256, 0, g_sB>>>(dstArr);
    sort_kernel<<<(NN+255)/256, 256, 0, g_sB>>>();
    cudaEventRecord(g_evCSR, g_sB);
    wt2half_kernel<<<dim3(32, 16, 2), dim3(32, 32), 0, g_sB>>>(Wq2, Wk2);
    cudaEventRecord(g_evB1, g_sB);
    wfin2half_kernel<<<dim3(32, 40), dim3(32, 32), 0, g_sB>>>(Wfin);
    gemm_fp64<<<dim3((BB+63)/64, 4, 4), 256, 0, g_sB>>>(fpb, Wfp);
    fpcc_kernel<<<(BB*128+255)/256, 256, 0, g_sB>>>(bfp);
    cudaEventRecord(g_evB2, g_sB);

    // main stream: layer 1
    proj1_kernel<<<(NN*32+255)/256, 256>>>(x, Wq1,bq1, Wk1,bk1, Wv1,bv1, Ws1,bs1);
    cudaStreamWaitEvent(0, g_evCSR, 0);
    attn1_kernel<<<BB, 640, SM1>>>(q1h, k1h, v1h, s1h, ea, We1, srcArr, ph1, h1h);

    // layer-2 q,k projections (needs wt2half)
    cudaStreamWaitEvent(0, g_evB1, 0);
    {
        dim3 grid((NN+127)/128, 1024/128, 2);
        gemm2_f16_kernel<<<grid, 256>>>(h1h, bq2, bk2, NN);
    }

    // layer-2 attention weights -> z, r, cnt
    attn2_kernel<<<BB, 640, SM2>>>(q2h, k2h, h1h, ea, We2, srcArr);

    // cch[:, :1024] = ph1@Ws2 + z@Wv2 + bs2 + edge/bias terms (fp16 direct)
    gemm_pool64<<<dim3((BB+63)/64, 1024/64), 256>>>(Ws2, Wv2, bs2, We2, bv2);

    // final GEMM (needs wfinh + fpcc)
    cudaStreamWaitEvent(0, g_evB2, 0);
    gemmfin_f16_kernel<<<dim3((BB+127)/128, 1024/128, 4), 256>>>(BB);
    reduce_fin_kernel<<<(BB*256+255)/256, 256>>>(bfin, (float*)d_out);
}